// round 1
// baseline (speedup 1.0000x reference)
#include <cuda_runtime.h>
#include <math.h>

#define N_HEADS   32
#define KV_HEADS  8
#define HEAD_DIM  128
#define D_MODEL   4096
#define BATCH     2
#define SEQ       2048
#define M_TOTAL   (BATCH * SEQ)                          /* 4096 */
#define QKV_N     ((KV_HEADS * 2 + N_HEADS) * HEAD_DIM)  /* 6144 */

// ---------------- scratch (static device globals; no allocation) ----------
__device__ float g_q[(size_t)BATCH * N_HEADS * SEQ * HEAD_DIM];   // 64 MB
__device__ float g_k[(size_t)BATCH * KV_HEADS * SEQ * HEAD_DIM];  // 16 MB
__device__ float g_v[(size_t)BATCH * KV_HEADS * SEQ * HEAD_DIM];  // 16 MB
__device__ float g_attn[(size_t)M_TOTAL * D_MODEL];               // 64 MB
__device__ float g_cos[SEQ * 64];
__device__ float g_sin[SEQ * 64];

// ---------------- RoPE table (fp64 for exact trig) ------------------------
__global__ void rope_table_kernel() {
    int i = blockIdx.x * blockDim.x + threadIdx.x;
    if (i >= SEQ * 64) return;
    int l = i >> 6, d = i & 63;
    double inv = pow(500000.0, -((double)d) / 64.0);
    double ang = (double)l * inv;
    g_cos[i] = (float)cos(ang);
    g_sin[i] = (float)sin(ang);
}

// ---------------- QKV GEMM: C = clip(X @ Wqkv^T), fused RoPE + scatter ----
// X: [4096, 4096] row-major, W: [6144, 4096] row-major.
// BM=BN=128, BK=16, 256 threads, 8x8 per thread (4+4 split at +64).
// BN == HEAD_DIM, so blockIdx.y == linear head index; the 4+4 column split
// lands exactly on RoPE pairs (d, d+64).
__global__ __launch_bounds__(256) void qkv_gemm_kernel(
        const float* __restrict__ X, const float* __restrict__ W) {
    __shared__ float As[16][128];
    __shared__ float Bs[16][128];
    const int K = D_MODEL;
    int tid = threadIdx.x;
    int bm = blockIdx.x, bn = blockIdx.y;
    int ty = tid >> 4, tx = tid & 15;
    int rowL = tid >> 2;          // 0..63
    int colL = (tid & 3) * 4;     // 0,4,8,12
    const float* Ap = X + (size_t)(bm * 128 + rowL) * K + colL;
    const float* Bp = W + (size_t)(bn * 128 + rowL) * K + colL;

    float acc[8][8];
#pragma unroll
    for (int i = 0; i < 8; i++)
#pragma unroll
        for (int j = 0; j < 8; j++) acc[i][j] = 0.f;

    for (int k0 = 0; k0 < K; k0 += 16) {
        float4 a0 = *(const float4*)(Ap + k0);
        float4 a1 = *(const float4*)(Ap + (size_t)64 * K + k0);
        float4 b0 = *(const float4*)(Bp + k0);
        float4 b1 = *(const float4*)(Bp + (size_t)64 * K + k0);
        As[colL + 0][rowL] = a0.x; As[colL + 1][rowL] = a0.y;
        As[colL + 2][rowL] = a0.z; As[colL + 3][rowL] = a0.w;
        As[colL + 0][rowL + 64] = a1.x; As[colL + 1][rowL + 64] = a1.y;
        As[colL + 2][rowL + 64] = a1.z; As[colL + 3][rowL + 64] = a1.w;
        Bs[colL + 0][rowL] = b0.x; Bs[colL + 1][rowL] = b0.y;
        Bs[colL + 2][rowL] = b0.z; Bs[colL + 3][rowL] = b0.w;
        Bs[colL + 0][rowL + 64] = b1.x; Bs[colL + 1][rowL + 64] = b1.y;
        Bs[colL + 2][rowL + 64] = b1.z; Bs[colL + 3][rowL + 64] = b1.w;
        __syncthreads();
#pragma unroll
        for (int k = 0; k < 16; k++) {
            float4 av0 = *(const float4*)&As[k][ty * 4];
            float4 av1 = *(const float4*)&As[k][64 + ty * 4];
            float4 bv0 = *(const float4*)&Bs[k][tx * 4];
            float4 bv1 = *(const float4*)&Bs[k][64 + tx * 4];
            float a[8] = {av0.x, av0.y, av0.z, av0.w, av1.x, av1.y, av1.z, av1.w};
            float b[8] = {bv0.x, bv0.y, bv0.z, bv0.w, bv1.x, bv1.y, bv1.z, bv1.w};
#pragma unroll
            for (int i = 0; i < 8; i++)
#pragma unroll
                for (int j = 0; j < 8; j++)
                    acc[i][j] = fmaf(a[i], b[j], acc[i][j]);
        }
        __syncthreads();
    }

    // epilogue: clip, RoPE (q,k), scatter to [b, head, l, d]
    int head = bn;
    float* dst;
    int do_rope, nheads;
    if (head < N_HEADS)                  { dst = g_q; do_rope = 1; nheads = N_HEADS; }
    else if (head < N_HEADS + KV_HEADS)  { dst = g_k; do_rope = 1; nheads = KV_HEADS; head -= N_HEADS; }
    else                                 { dst = g_v; do_rope = 0; nheads = KV_HEADS; head -= N_HEADS + KV_HEADS; }

#pragma unroll
    for (int i = 0; i < 8; i++) {
        int r = (i < 4) ? (ty * 4 + i) : (64 + ty * 4 + (i - 4));
        int m = bm * 128 + r;
        int b = m >> 11, l = m & 2047;
        float vals[8];
#pragma unroll
        for (int j = 0; j < 8; j++)
            vals[j] = fminf(fmaxf(acc[i][j], -8.0f), 8.0f);
        if (do_rope) {
#pragma unroll
            for (int j = 0; j < 4; j++) {
                int d = tx * 4 + j;                       // 0..63
                float c = g_cos[l * 64 + d];
                float s = g_sin[l * 64 + d];
                float x1 = vals[j], x2 = vals[j + 4];
                vals[j]     = x1 * c - x2 * s;
                vals[j + 4] = x2 * c + x1 * s;
            }
        }
        float* outp = dst + (((size_t)(b * nheads + head)) * SEQ + l) * HEAD_DIM;
#pragma unroll
        for (int j = 0; j < 8; j++) {
            int d = (j < 4) ? (tx * 4 + j) : (64 + tx * 4 + (j - 4));
            outp[d] = vals[j];
        }
    }
}

// ---------------- Flash attention (fp32 SIMT), causal, GQA ----------------
#define QS_STRIDE 132
#define PS_STRIDE 68
__global__ __launch_bounds__(256) void attn_kernel() {
    extern __shared__ float sm[];
    float* Qs  = sm;                       // 64 x 132
    float* KVs = sm + 64 * QS_STRIDE;      // 64 x 132 (K then reused for V)
    float* Ps  = KVs + 64 * QS_STRIDE;     // 64 x 68

    int qt = blockIdx.x;                   // 0..31 (q tile of 64 rows)
    int bh = blockIdx.y;                   // 0..63
    int b = bh >> 5, h = bh & 31, kh = h >> 2;
    int tid = threadIdx.x;
    int ty = tid >> 4, tx = tid & 15;
    const float scale = 0.08838834764831845f;  // 1/sqrt(128)

    const float* Qg = g_q + ((size_t)(b * N_HEADS + h) * SEQ + qt * 64) * HEAD_DIM;
    const float* Kg = g_k + ((size_t)(b * KV_HEADS + kh) * SEQ) * HEAD_DIM;
    const float* Vg = g_v + ((size_t)(b * KV_HEADS + kh) * SEQ) * HEAD_DIM;

    // load Q tile (pre-scaled)
    for (int i = tid; i < 64 * 32; i += 256) {
        int r = i >> 5, c = (i & 31) * 4;
        float4 v = *(const float4*)(Qg + (size_t)r * HEAD_DIM + c);
        float4 w = make_float4(v.x * scale, v.y * scale, v.z * scale, v.w * scale);
        *(float4*)&Qs[r * QS_STRIDE + c] = w;
    }

    float m_i[4], l_i[4], accO[4][8];
#pragma unroll
    for (int i = 0; i < 4; i++) {
        m_i[i] = -1e30f; l_i[i] = 0.f;
#pragma unroll
        for (int c = 0; c < 8; c++) accO[i][c] = 0.f;
    }

    int nkt = qt + 1;
    for (int kt = 0; kt < nkt; kt++) {
        __syncthreads();   // prior PV done with Ps/KVs
        // load K tile
        for (int i = tid; i < 64 * 32; i += 256) {
            int r = i >> 5, c = (i & 31) * 4;
            *(float4*)&KVs[r * QS_STRIDE + c] =
                *(const float4*)(Kg + (size_t)(kt * 64 + r) * HEAD_DIM + c);
        }
        __syncthreads();

        // S = Qs @ Ks^T (4x4 per thread)
        float s[4][4];
#pragma unroll
        for (int i = 0; i < 4; i++)
#pragma unroll
            for (int j = 0; j < 4; j++) s[i][j] = 0.f;
#pragma unroll 4
        for (int d = 0; d < 128; d += 4) {
            float4 qv[4], kv[4];
#pragma unroll
            for (int i = 0; i < 4; i++)
                qv[i] = *(const float4*)&Qs[(ty * 4 + i) * QS_STRIDE + d];
#pragma unroll
            for (int j = 0; j < 4; j++)
                kv[j] = *(const float4*)&KVs[(tx * 4 + j) * QS_STRIDE + d];
#pragma unroll
            for (int i = 0; i < 4; i++)
#pragma unroll
                for (int j = 0; j < 4; j++) {
                    s[i][j] = fmaf(qv[i].x, kv[j].x, s[i][j]);
                    s[i][j] = fmaf(qv[i].y, kv[j].y, s[i][j]);
                    s[i][j] = fmaf(qv[i].z, kv[j].z, s[i][j]);
                    s[i][j] = fmaf(qv[i].w, kv[j].w, s[i][j]);
                }
        }

        // causal mask (only diagonal tile)
        if (kt == qt) {
#pragma unroll
            for (int i = 0; i < 4; i++)
#pragma unroll
                for (int j = 0; j < 4; j++)
                    if (tx * 4 + j > ty * 4 + i) s[i][j] = -1e30f;
        }

        // online softmax row stats (reduce across 16 tx lanes via shfl)
        float p[4][4], corr[4];
#pragma unroll
        for (int i = 0; i < 4; i++) {
            float rm = fmaxf(fmaxf(s[i][0], s[i][1]), fmaxf(s[i][2], s[i][3]));
#pragma unroll
            for (int o = 1; o < 16; o <<= 1)
                rm = fmaxf(rm, __shfl_xor_sync(0xffffffffu, rm, o));
            float mn = fmaxf(m_i[i], rm);
            corr[i] = __expf(m_i[i] - mn);
            m_i[i] = mn;
            float rs = 0.f;
#pragma unroll
            for (int j = 0; j < 4; j++) {
                p[i][j] = __expf(s[i][j] - mn);
                rs += p[i][j];
            }
#pragma unroll
            for (int o = 1; o < 16; o <<= 1)
                rs += __shfl_xor_sync(0xffffffffu, rs, o);
            l_i[i] = l_i[i] * corr[i] + rs;
        }
        __syncthreads();   // done reading K from KVs

        // load V into KVs; stash P into Ps
        for (int i = tid; i < 64 * 32; i += 256) {
            int r = i >> 5, c = (i & 31) * 4;
            *(float4*)&KVs[r * QS_STRIDE + c] =
                *(const float4*)(Vg + (size_t)(kt * 64 + r) * HEAD_DIM + c);
        }
#pragma unroll
        for (int i = 0; i < 4; i++)
#pragma unroll
            for (int j = 0; j < 4; j++)
                Ps[(ty * 4 + i) * PS_STRIDE + tx * 4 + j] = p[i][j];
        __syncthreads();

        // rescale accumulator, then O += P @ V (4 rows x 8 cols per thread)
#pragma unroll
        for (int i = 0; i < 4; i++)
#pragma unroll
            for (int c = 0; c < 8; c++) accO[i][c] *= corr[i];
#pragma unroll 4
        for (int kk = 0; kk < 64; kk++) {
            float pv[4];
#pragma unroll
            for (int i = 0; i < 4; i++)
                pv[i] = Ps[(ty * 4 + i) * PS_STRIDE + kk];
            float4 v0 = *(const float4*)&KVs[kk * QS_STRIDE + tx * 8];
            float4 v1 = *(const float4*)&KVs[kk * QS_STRIDE + tx * 8 + 4];
#pragma unroll
            for (int i = 0; i < 4; i++) {
                accO[i][0] = fmaf(pv[i], v0.x, accO[i][0]);
                accO[i][1] = fmaf(pv[i], v0.y, accO[i][1]);
                accO[i][2] = fmaf(pv[i], v0.z, accO[i][2]);
                accO[i][3] = fmaf(pv[i], v0.w, accO[i][3]);
                accO[i][4] = fmaf(pv[i], v1.x, accO[i][4]);
                accO[i][5] = fmaf(pv[i], v1.y, accO[i][5]);
                accO[i][6] = fmaf(pv[i], v1.z, accO[i][6]);
                accO[i][7] = fmaf(pv[i], v1.w, accO[i][7]);
            }
        }
    }

    // write O / l  -> g_attn laid out [b, l, h*128+d] for the out-proj GEMM
#pragma unroll
    for (int i = 0; i < 4; i++) {
        int l = qt * 64 + ty * 4 + i;
        float inv = 1.0f / l_i[i];
        float* dst = g_attn + ((size_t)b * SEQ + l) * D_MODEL + h * HEAD_DIM + tx * 8;
        float4 o0 = make_float4(accO[i][0] * inv, accO[i][1] * inv,
                                accO[i][2] * inv, accO[i][3] * inv);
        float4 o1 = make_float4(accO[i][4] * inv, accO[i][5] * inv,
                                accO[i][6] * inv, accO[i][7] * inv);
        *(float4*)dst = o0;
        *(float4*)(dst + 4) = o1;
    }
}

// ---------------- Out projection: out = attn @ Wout^T ---------------------
__global__ __launch_bounds__(256) void out_gemm_kernel(
        const float* __restrict__ W, float* __restrict__ out) {
    __shared__ float As[16][128];
    __shared__ float Bs[16][128];
    const float* X = g_attn;
    const int K = D_MODEL;
    int tid = threadIdx.x;
    int bm = blockIdx.x, bn = blockIdx.y;
    int ty = tid >> 4, tx = tid & 15;
    int rowL = tid >> 2;
    int colL = (tid & 3) * 4;
    const float* Ap = X + (size_t)(bm * 128 + rowL) * K + colL;
    const float* Bp = W + (size_t)(bn * 128 + rowL) * K + colL;

    float acc[8][8];
#pragma unroll
    for (int i = 0; i < 8; i++)
#pragma unroll
        for (int j = 0; j < 8; j++) acc[i][j] = 0.f;

    for (int k0 = 0; k0 < K; k0 += 16) {
        float4 a0 = *(const float4*)(Ap + k0);
        float4 a1 = *(const float4*)(Ap + (size_t)64 * K + k0);
        float4 b0 = *(const float4*)(Bp + k0);
        float4 b1 = *(const float4*)(Bp + (size_t)64 * K + k0);
        As[colL + 0][rowL] = a0.x; As[colL + 1][rowL] = a0.y;
        As[colL + 2][rowL] = a0.z; As[colL + 3][rowL] = a0.w;
        As[colL + 0][rowL + 64] = a1.x; As[colL + 1][rowL + 64] = a1.y;
        As[colL + 2][rowL + 64] = a1.z; As[colL + 3][rowL + 64] = a1.w;
        Bs[colL + 0][rowL] = b0.x; Bs[colL + 1][rowL] = b0.y;
        Bs[colL + 2][rowL] = b0.z; Bs[colL + 3][rowL] = b0.w;
        Bs[colL + 0][rowL + 64] = b1.x; Bs[colL + 1][rowL + 64] = b1.y;
        Bs[colL + 2][rowL + 64] = b1.z; Bs[colL + 3][rowL + 64] = b1.w;
        __syncthreads();
#pragma unroll
        for (int k = 0; k < 16; k++) {
            float4 av0 = *(const float4*)&As[k][ty * 4];
            float4 av1 = *(const float4*)&As[k][64 + ty * 4];
            float4 bv0 = *(const float4*)&Bs[k][tx * 4];
            float4 bv1 = *(const float4*)&Bs[k][64 + tx * 4];
            float a[8] = {av0.x, av0.y, av0.z, av0.w, av1.x, av1.y, av1.z, av1.w};
            float b[8] = {bv0.x, bv0.y, bv0.z, bv0.w, bv1.x, bv1.y, bv1.z, bv1.w};
#pragma unroll
            for (int i = 0; i < 8; i++)
#pragma unroll
                for (int j = 0; j < 8; j++)
                    acc[i][j] = fmaf(a[i], b[j], acc[i][j]);
        }
        __syncthreads();
    }

#pragma unroll
    for (int i = 0; i < 8; i++) {
        int r = (i < 4) ? (ty * 4 + i) : (64 + ty * 4 + (i - 4));
        size_t m = (size_t)(bm * 128 + r);
        float* dst = out + m * D_MODEL + bn * 128;
        float4 v0 = make_float4(acc[i][0], acc[i][1], acc[i][2], acc[i][3]);
        float4 v1 = make_float4(acc[i][4], acc[i][5], acc[i][6], acc[i][7]);
        *(float4*)(dst + tx * 4) = v0;
        *(float4*)(dst + 64 + tx * 4) = v1;
    }
}

// ---------------- launch ---------------------------------------------------
extern "C" void kernel_launch(void* const* d_in, const int* in_sizes, int n_in,
                              void* d_out, int out_size) {
    const float* x    = (const float*)d_in[0];
    const float* Wqkv = (const float*)d_in[1];
    const float* Wout = (const float*)d_in[2];
    float* out = (float*)d_out;

    rope_table_kernel<<<(SEQ * 64 + 255) / 256, 256>>>();

    qkv_gemm_kernel<<<dim3(M_TOTAL / 128, QKV_N / 128), 256>>>(x, Wqkv);

    const int smem = (64 * QS_STRIDE * 2 + 64 * PS_STRIDE) * (int)sizeof(float);
    cudaFuncSetAttribute(attn_kernel, cudaFuncAttributeMaxDynamicSharedMemorySize, smem);
    attn_kernel<<<dim3(SEQ / 64, BATCH * N_HEADS), 256, smem>>>();

    out_gemm_kernel<<<dim3(M_TOTAL / 128, D_MODEL / 128), 256>>>(Wout, out);
}

// round 3
// speedup vs baseline: 1.5675x; 1.5675x over previous
#include <cuda_runtime.h>
#include <cuda_bf16.h>
#include <math.h>
#include <stdint.h>

#define N_HEADS   32
#define KV_HEADS  8
#define HEAD_DIM  128
#define D_MODEL   4096
#define BATCH     2
#define SEQ       2048
#define M_TOTAL   (BATCH * SEQ)                          /* 4096 */
#define QKV_N     ((KV_HEADS * 2 + N_HEADS) * HEAD_DIM)  /* 6144 */
#define KDIM      4096

// ---------------- scratch (static device globals; no allocation) ----------
__device__ float g_q[(size_t)BATCH * N_HEADS * SEQ * HEAD_DIM];   // 64 MB
__device__ float g_k[(size_t)BATCH * KV_HEADS * SEQ * HEAD_DIM];  // 16 MB
__device__ float g_v[(size_t)BATCH * KV_HEADS * SEQ * HEAD_DIM];  // 16 MB
__device__ float g_cos[SEQ * 64];
__device__ float g_sin[SEQ * 64];

__device__ __align__(256) __nv_bfloat16 g_xh[(size_t)M_TOTAL * D_MODEL];
__device__ __align__(256) __nv_bfloat16 g_xl[(size_t)M_TOTAL * D_MODEL];
__device__ __align__(256) __nv_bfloat16 g_wqkvh[(size_t)QKV_N * D_MODEL];
__device__ __align__(256) __nv_bfloat16 g_wqkvl[(size_t)QKV_N * D_MODEL];
__device__ __align__(256) __nv_bfloat16 g_wouth[(size_t)D_MODEL * D_MODEL];
__device__ __align__(256) __nv_bfloat16 g_woutl[(size_t)D_MODEL * D_MODEL];
__device__ __align__(256) __nv_bfloat16 g_attnh[(size_t)M_TOTAL * D_MODEL];
__device__ __align__(256) __nv_bfloat16 g_attnl[(size_t)M_TOTAL * D_MODEL];

// ====================== warp MMA helpers (compute_103-safe) ===============
__device__ __forceinline__ uint32_t smem_u32(const void* p) {
    uint32_t a;
    asm("{ .reg .u64 t; cvta.to.shared.u64 t, %1; cvt.u32.u64 %0, t; }"
        : "=r"(a) : "l"(p));
    return a;
}

__device__ __forceinline__ void ldm_x4(uint32_t& r0, uint32_t& r1,
                                       uint32_t& r2, uint32_t& r3, uint32_t addr) {
    asm volatile("ldmatrix.sync.aligned.m8n8.x4.shared.b16 {%0,%1,%2,%3}, [%4];"
                 : "=r"(r0), "=r"(r1), "=r"(r2), "=r"(r3) : "r"(addr));
}

__device__ __forceinline__ void mma_bf16(float* c, const uint32_t* a,
                                         const uint32_t* b) {
    asm volatile(
        "mma.sync.aligned.m16n8k16.row.col.f32.bf16.bf16.f32 "
        "{%0,%1,%2,%3}, {%4,%5,%6,%7}, {%8,%9}, {%0,%1,%2,%3};"
        : "+f"(c[0]), "+f"(c[1]), "+f"(c[2]), "+f"(c[3])
        : "r"(a[0]), "r"(a[1]), "r"(a[2]), "r"(a[3]), "r"(b[0]), "r"(b[1]));
}

// ---------------- RoPE table (fp64 for exact trig) ------------------------
__global__ void rope_table_kernel() {
    int i = blockIdx.x * blockDim.x + threadIdx.x;
    if (i >= SEQ * 64) return;
    int l = i >> 6, d = i & 63;
    double inv = pow(500000.0, -((double)d) / 64.0);
    double ang = (double)l * inv;
    g_cos[i] = (float)cos(ang);
    g_sin[i] = (float)sin(ang);
}

// ---------------- fp32 -> bf16 hi/lo split ---------------------------------
__global__ __launch_bounds__(256) void split_kernel(
        const float* __restrict__ in, __nv_bfloat16* __restrict__ hi,
        __nv_bfloat16* __restrict__ lo, int n4) {
    int i = blockIdx.x * blockDim.x + threadIdx.x;
    if (i >= n4) return;
    float4 v = ((const float4*)in)[i];
    __nv_bfloat16 h[4], l[4];
    float vv[4] = {v.x, v.y, v.z, v.w};
#pragma unroll
    for (int j = 0; j < 4; j++) {
        h[j] = __float2bfloat16(vv[j]);
        l[j] = __float2bfloat16(vv[j] - __bfloat162float(h[j]));
    }
    ((uint2*)hi)[i] = *(uint2*)h;
    ((uint2*)lo)[i] = *(uint2*)l;
}

// ---------------- split-bf16 GEMM via mma.sync -----------------------------
// C[128x128] per CTA = A @ B^T, A=[M,4096], B=[N,4096], both K-major hi/lo.
// D = Ah Bh + Al Bh + Ah Bl (fp32 accum in regs).
// MODE 0: QKV epilogue (clip + RoPE + scatter to g_q/g_k/g_v; bn = head id)
// MODE 1: plain fp32 store to outp.
//
// smem: 2 stages x 4 variants x [128 rows x 40 bf16] (80B row stride).
#define ROWB   40          /* bf16 elems per smem row (80 bytes) */
#define VBYTES (128 * ROWB * 2)            /* 10240 per variant */
#define STAGEB (4 * VBYTES)                /* 40960 per stage   */
#define GEMM_SMEM_BYTES (2 * STAGEB + 1024)

template<int MODE>
__global__ __launch_bounds__(256) void mma_gemm(
        const __nv_bfloat16* __restrict__ Ah, const __nv_bfloat16* __restrict__ Al,
        const __nv_bfloat16* __restrict__ Bh, const __nv_bfloat16* __restrict__ Bl,
        float* __restrict__ outp) {
    extern __shared__ char smraw[];
    char* smp = (char*)(((uintptr_t)smraw + 1023) & ~(uintptr_t)1023);
    const uint32_t sbase = smem_u32(smp);

    const int tid = threadIdx.x;
    const int lane = tid & 31;
    const int wid = tid >> 5;
    const int warp_m = wid & 1;        // 2 warps along M (64 rows each)
    const int warp_n = wid >> 1;       // 4 warps along N (32 cols each)
    const int bm = blockIdx.x, bn = blockIdx.y;

    // per-thread load geometry: 2 rows x 1 group of 8 elems, per variant
    const int lr = tid >> 2;           // 0..63
    const int jj = tid & 3;            // 16B group within 32-elem row
    const size_t aoff = (size_t)(bm * 128) * KDIM;
    const size_t boff = (size_t)(bn * 128) * KDIM;

    float acc[4][4][4];
#pragma unroll
    for (int i = 0; i < 4; i++)
#pragma unroll
        for (int j = 0; j < 4; j++)
#pragma unroll
            for (int c = 0; c < 4; c++) acc[i][j][c] = 0.f;

    uint4 rg[8];
    const __nv_bfloat16* srcs[4] = {Ah, Al, Bh, Bl};
    const size_t roff[4] = {aoff, aoff, boff, boff};

    auto load_regs = [&](int ic) {
#pragma unroll
        for (int v = 0; v < 4; v++) {
#pragma unroll
            for (int i = 0; i < 2; i++) {
                int r = lr + i * 64;
                rg[v * 2 + i] = *(const uint4*)(srcs[v] + roff[v] +
                                (size_t)r * KDIM + ic * 32 + jj * 8);
            }
        }
    };
    auto store_regs = [&](int st) {
        char* base = smp + st * STAGEB;
#pragma unroll
        for (int v = 0; v < 4; v++) {
#pragma unroll
            for (int i = 0; i < 2; i++) {
                int r = lr + i * 64;
                *(uint4*)(base + v * VBYTES + (r * ROWB + jj * 8) * 2) = rg[v * 2 + i];
            }
        }
    };

    // smem fragment addresses (byte offsets within a variant buffer)
    const uint32_t a_lane_off =
        (uint32_t)((lane & 15) * (ROWB * 2) + ((lane >> 4) << 3) * 2);
    const uint32_t b_lane_off =
        (uint32_t)((((lane & 16) >> 1) + (lane & 7)) * (ROWB * 2) + (lane & 8) * 2);
    const int m0 = warp_m * 64;
    const int n0 = warp_n * 32;

    auto compute = [&](int st, int passA, int passB) {
        // passA selects Ah(0)/Al(1); passB selects Bh(0)/Bl(1)
        uint32_t sA = sbase + st * STAGEB + passA * VBYTES;
        uint32_t sB = sbase + st * STAGEB + (2 + passB) * VBYTES;
#pragma unroll
        for (int ks = 0; ks < 2; ks++) {
            const uint32_t k0b = ks * 16 * 2;
            uint32_t a[4][4], b[4][2];
#pragma unroll
            for (int mi = 0; mi < 4; mi++)
                ldm_x4(a[mi][0], a[mi][1], a[mi][2], a[mi][3],
                       sA + (uint32_t)((m0 + mi * 16) * (ROWB * 2)) + a_lane_off + k0b);
#pragma unroll
            for (int p = 0; p < 2; p++) {
                uint32_t r0, r1, r2, r3;
                ldm_x4(r0, r1, r2, r3,
                       sB + (uint32_t)((n0 + p * 16) * (ROWB * 2)) + b_lane_off + k0b);
                b[p * 2][0] = r0; b[p * 2][1] = r1;
                b[p * 2 + 1][0] = r2; b[p * 2 + 1][1] = r3;
            }
#pragma unroll
            for (int mi = 0; mi < 4; mi++)
#pragma unroll
                for (int ni = 0; ni < 4; ni++)
                    mma_bf16(acc[mi][ni], a[mi], b[ni]);
        }
    };

    // prologue
    load_regs(0);
    store_regs(0);
    __syncthreads();

    for (int ic = 0; ic < 128; ic++) {
        const int st = ic & 1;
        if (ic + 1 < 128) load_regs(ic + 1);
        compute(st, 0, 0);   // Ah * Bh
        compute(st, 1, 0);   // Al * Bh
        compute(st, 0, 1);   // Ah * Bl
        __syncthreads();
        if (ic + 1 < 128) store_regs(st ^ 1);
        __syncthreads();
    }

    // ---- epilogue: regs -> smem stage -> (clip/RoPE) -> global ----
    float* ep = (float*)smp;                 // [128][136]
    const int g = lane >> 2, tg = lane & 3;
#pragma unroll
    for (int mi = 0; mi < 4; mi++) {
#pragma unroll
        for (int ni = 0; ni < 4; ni++) {
            int row = m0 + mi * 16 + g;
            int col = n0 + ni * 8 + tg * 2;
            ep[row * 136 + col]       = acc[mi][ni][0];
            ep[row * 136 + col + 1]   = acc[mi][ni][1];
            ep[(row + 8) * 136 + col]     = acc[mi][ni][2];
            ep[(row + 8) * 136 + col + 1] = acc[mi][ni][3];
        }
    }
    __syncthreads();

    for (int t = tid; t < 128 * 16; t += 256) {
        int row = t >> 4, j = t & 15;        // j: first-half float4 group
        float4 v1 = *(const float4*)&ep[row * 136 + j * 4];
        float4 v2 = *(const float4*)&ep[row * 136 + 64 + j * 4];
        if (MODE == 0) {
            float* p1 = &v1.x; float* p2 = &v2.x;
#pragma unroll
            for (int e = 0; e < 4; e++) {
                p1[e] = fminf(fmaxf(p1[e], -8.0f), 8.0f);
                p2[e] = fminf(fmaxf(p2[e], -8.0f), 8.0f);
            }
            int m = bm * 128 + row;
            int b = m >> 11, l = m & (SEQ - 1);
            if (bn < N_HEADS + KV_HEADS) {   // RoPE for q and k heads
#pragma unroll
                for (int e = 0; e < 4; e++) {
                    int d = j * 4 + e;
                    float c = g_cos[l * 64 + d];
                    float s = g_sin[l * 64 + d];
                    float x1 = p1[e], x2 = p2[e];
                    p1[e] = x1 * c - x2 * s;
                    p2[e] = x2 * c + x1 * s;
                }
            }
            float* dst;
            if (bn < N_HEADS)
                dst = g_q + ((size_t)(b * N_HEADS + bn) * SEQ + l) * HEAD_DIM;
            else if (bn < N_HEADS + KV_HEADS)
                dst = g_k + ((size_t)(b * KV_HEADS + (bn - N_HEADS)) * SEQ + l) * HEAD_DIM;
            else
                dst = g_v + ((size_t)(b * KV_HEADS + (bn - N_HEADS - KV_HEADS)) * SEQ + l) * HEAD_DIM;
            *(float4*)(dst + j * 4) = v1;
            *(float4*)(dst + 64 + j * 4) = v2;
        } else {
            float* dst = outp + (size_t)(bm * 128 + row) * D_MODEL + bn * 128;
            *(float4*)(dst + j * 4) = v1;
            *(float4*)(dst + 64 + j * 4) = v2;
        }
    }
}

// ---------------- Flash attention (fp32 SIMT), causal, GQA ----------------
#define QS_STRIDE 132
#define PS_STRIDE 68
__global__ __launch_bounds__(256) void attn_kernel() {
    extern __shared__ float sm[];
    float* Qs  = sm;                       // 64 x 132
    float* KVs = sm + 64 * QS_STRIDE;      // 64 x 132 (K then reused for V)
    float* Ps  = KVs + 64 * QS_STRIDE;     // 64 x 68

    int qt = blockIdx.x;
    int bh = blockIdx.y;
    int b = bh >> 5, h = bh & 31, kh = h >> 2;
    int tid = threadIdx.x;
    int ty = tid >> 4, tx = tid & 15;
    const float scale = 0.08838834764831845f;

    const float* Qg = g_q + ((size_t)(b * N_HEADS + h) * SEQ + qt * 64) * HEAD_DIM;
    const float* Kg = g_k + ((size_t)(b * KV_HEADS + kh) * SEQ) * HEAD_DIM;
    const float* Vg = g_v + ((size_t)(b * KV_HEADS + kh) * SEQ) * HEAD_DIM;

    for (int i = tid; i < 64 * 32; i += 256) {
        int r = i >> 5, c = (i & 31) * 4;
        float4 v = *(const float4*)(Qg + (size_t)r * HEAD_DIM + c);
        float4 w = make_float4(v.x * scale, v.y * scale, v.z * scale, v.w * scale);
        *(float4*)&Qs[r * QS_STRIDE + c] = w;
    }

    float m_i[4], l_i[4], accO[4][8];
#pragma unroll
    for (int i = 0; i < 4; i++) {
        m_i[i] = -1e30f; l_i[i] = 0.f;
#pragma unroll
        for (int c = 0; c < 8; c++) accO[i][c] = 0.f;
    }

    int nkt = qt + 1;
    for (int kt = 0; kt < nkt; kt++) {
        __syncthreads();
        for (int i = tid; i < 64 * 32; i += 256) {
            int r = i >> 5, c = (i & 31) * 4;
            *(float4*)&KVs[r * QS_STRIDE + c] =
                *(const float4*)(Kg + (size_t)(kt * 64 + r) * HEAD_DIM + c);
        }
        __syncthreads();

        float s[4][4];
#pragma unroll
        for (int i = 0; i < 4; i++)
#pragma unroll
            for (int j = 0; j < 4; j++) s[i][j] = 0.f;
#pragma unroll 4
        for (int d = 0; d < 128; d += 4) {
            float4 qv[4], kv[4];
#pragma unroll
            for (int i = 0; i < 4; i++)
                qv[i] = *(const float4*)&Qs[(ty * 4 + i) * QS_STRIDE + d];
#pragma unroll
            for (int j = 0; j < 4; j++)
                kv[j] = *(const float4*)&KVs[(tx * 4 + j) * QS_STRIDE + d];
#pragma unroll
            for (int i = 0; i < 4; i++)
#pragma unroll
                for (int j = 0; j < 4; j++) {
                    s[i][j] = fmaf(qv[i].x, kv[j].x, s[i][j]);
                    s[i][j] = fmaf(qv[i].y, kv[j].y, s[i][j]);
                    s[i][j] = fmaf(qv[i].z, kv[j].z, s[i][j]);
                    s[i][j] = fmaf(qv[i].w, kv[j].w, s[i][j]);
                }
        }

        if (kt == qt) {
#pragma unroll
            for (int i = 0; i < 4; i++)
#pragma unroll
                for (int j = 0; j < 4; j++)
                    if (tx * 4 + j > ty * 4 + i) s[i][j] = -1e30f;
        }

        float p[4][4], corr[4];
#pragma unroll
        for (int i = 0; i < 4; i++) {
            float rm = fmaxf(fmaxf(s[i][0], s[i][1]), fmaxf(s[i][2], s[i][3]));
#pragma unroll
            for (int o = 1; o < 16; o <<= 1)
                rm = fmaxf(rm, __shfl_xor_sync(0xffffffffu, rm, o));
            float mn = fmaxf(m_i[i], rm);
            corr[i] = __expf(m_i[i] - mn);
            m_i[i] = mn;
            float rs = 0.f;
#pragma unroll
            for (int j = 0; j < 4; j++) {
                p[i][j] = __expf(s[i][j] - mn);
                rs += p[i][j];
            }
#pragma unroll
            for (int o = 1; o < 16; o <<= 1)
                rs += __shfl_xor_sync(0xffffffffu, rs, o);
            l_i[i] = l_i[i] * corr[i] + rs;
        }
        __syncthreads();

        for (int i = tid; i < 64 * 32; i += 256) {
            int r = i >> 5, c = (i & 31) * 4;
            *(float4*)&KVs[r * QS_STRIDE + c] =
                *(const float4*)(Vg + (size_t)(kt * 64 + r) * HEAD_DIM + c);
        }
#pragma unroll
        for (int i = 0; i < 4; i++)
#pragma unroll
            for (int j = 0; j < 4; j++)
                Ps[(ty * 4 + i) * PS_STRIDE + tx * 4 + j] = p[i][j];
        __syncthreads();

#pragma unroll
        for (int i = 0; i < 4; i++)
#pragma unroll
            for (int c = 0; c < 8; c++) accO[i][c] *= corr[i];
#pragma unroll 4
        for (int kk = 0; kk < 64; kk++) {
            float pv[4];
#pragma unroll
            for (int i = 0; i < 4; i++)
                pv[i] = Ps[(ty * 4 + i) * PS_STRIDE + kk];
            float4 v0 = *(const float4*)&KVs[kk * QS_STRIDE + tx * 8];
            float4 v1 = *(const float4*)&KVs[kk * QS_STRIDE + tx * 8 + 4];
#pragma unroll
            for (int i = 0; i < 4; i++) {
                accO[i][0] = fmaf(pv[i], v0.x, accO[i][0]);
                accO[i][1] = fmaf(pv[i], v0.y, accO[i][1]);
                accO[i][2] = fmaf(pv[i], v0.z, accO[i][2]);
                accO[i][3] = fmaf(pv[i], v0.w, accO[i][3]);
                accO[i][4] = fmaf(pv[i], v1.x, accO[i][4]);
                accO[i][5] = fmaf(pv[i], v1.y, accO[i][5]);
                accO[i][6] = fmaf(pv[i], v1.z, accO[i][6]);
                accO[i][7] = fmaf(pv[i], v1.w, accO[i][7]);
            }
        }
    }

    // epilogue: write O rows as bf16 hi/lo split for the tensor-core out-proj
#pragma unroll
    for (int i = 0; i < 4; i++) {
        int l = qt * 64 + ty * 4 + i;
        float inv = 1.0f / l_i[i];
        size_t off = ((size_t)b * SEQ + l) * D_MODEL + h * HEAD_DIM + tx * 8;
        __nv_bfloat16 hb[8], lb[8];
#pragma unroll
        for (int c = 0; c < 8; c++) {
            float v = accO[i][c] * inv;
            __nv_bfloat16 hh = __float2bfloat16(v);
            hb[c] = hh;
            lb[c] = __float2bfloat16(v - __bfloat162float(hh));
        }
        *(uint4*)(g_attnh + off) = *(uint4*)hb;
        *(uint4*)(g_attnl + off) = *(uint4*)lb;
    }
}

// ---------------- launch ---------------------------------------------------
extern "C" void kernel_launch(void* const* d_in, const int* in_sizes, int n_in,
                              void* d_out, int out_size) {
    const float* x    = (const float*)d_in[0];
    const float* Wqkv = (const float*)d_in[1];
    const float* Wout = (const float*)d_in[2];
    float* out = (float*)d_out;

    __nv_bfloat16 *xh, *xl, *wqh, *wql, *woh, *wol, *ah, *al;
    cudaGetSymbolAddress((void**)&xh,  g_xh);
    cudaGetSymbolAddress((void**)&xl,  g_xl);
    cudaGetSymbolAddress((void**)&wqh, g_wqkvh);
    cudaGetSymbolAddress((void**)&wql, g_wqkvl);
    cudaGetSymbolAddress((void**)&woh, g_wouth);
    cudaGetSymbolAddress((void**)&wol, g_woutl);
    cudaGetSymbolAddress((void**)&ah,  g_attnh);
    cudaGetSymbolAddress((void**)&al,  g_attnl);

    rope_table_kernel<<<(SEQ * 64 + 255) / 256, 256>>>();

    {   // fp32 -> bf16 hi/lo splits
        int n4x = M_TOTAL * D_MODEL / 4;
        split_kernel<<<(n4x + 255) / 256, 256>>>(x, xh, xl, n4x);
        int n4q = QKV_N * D_MODEL / 4;
        split_kernel<<<(n4q + 255) / 256, 256>>>(Wqkv, wqh, wql, n4q);
        int n4o = D_MODEL * D_MODEL / 4;
        split_kernel<<<(n4o + 255) / 256, 256>>>(Wout, woh, wol, n4o);
    }

    cudaFuncSetAttribute(mma_gemm<0>, cudaFuncAttributeMaxDynamicSharedMemorySize,
                         GEMM_SMEM_BYTES);
    cudaFuncSetAttribute(mma_gemm<1>, cudaFuncAttributeMaxDynamicSharedMemorySize,
                         GEMM_SMEM_BYTES);

    // QKV projection: [4096 x 6144], fused clip+RoPE+scatter
    mma_gemm<0><<<dim3(M_TOTAL / 128, QKV_N / 128), 256, GEMM_SMEM_BYTES>>>(
        xh, xl, wqh, wql, nullptr);

    // attention (fp32 SIMT)
    const int attn_smem = (64 * QS_STRIDE * 2 + 64 * PS_STRIDE) * (int)sizeof(float);
    cudaFuncSetAttribute(attn_kernel, cudaFuncAttributeMaxDynamicSharedMemorySize,
                         attn_smem);
    attn_kernel<<<dim3(SEQ / 64, BATCH * N_HEADS), 256, attn_smem>>>();

    // out projection: [4096 x 4096]
    mma_gemm<1><<<dim3(M_TOTAL / 128, D_MODEL / 128), 256, GEMM_SMEM_BYTES>>>(
        ah, al, woh, wol, out);
}

// round 4
// speedup vs baseline: 2.6381x; 1.6830x over previous
#include <cuda_runtime.h>
#include <cuda_bf16.h>
#include <math.h>
#include <stdint.h>

#define N_HEADS   32
#define KV_HEADS  8
#define HEAD_DIM  128
#define D_MODEL   4096
#define BATCH     2
#define SEQ       2048
#define M_TOTAL   (BATCH * SEQ)                          /* 4096 */
#define QKV_N     ((KV_HEADS * 2 + N_HEADS) * HEAD_DIM)  /* 6144 */
#define KDIM      4096

// ---------------- scratch (static device globals; no allocation) ----------
__device__ float g_cos[SEQ * 64];
__device__ float g_sin[SEQ * 64];

__device__ __align__(256) __nv_bfloat16 g_xh[(size_t)M_TOTAL * D_MODEL];
__device__ __align__(256) __nv_bfloat16 g_xl[(size_t)M_TOTAL * D_MODEL];
__device__ __align__(256) __nv_bfloat16 g_wqkvh[(size_t)QKV_N * D_MODEL];
__device__ __align__(256) __nv_bfloat16 g_wqkvl[(size_t)QKV_N * D_MODEL];
__device__ __align__(256) __nv_bfloat16 g_wouth[(size_t)D_MODEL * D_MODEL];
__device__ __align__(256) __nv_bfloat16 g_woutl[(size_t)D_MODEL * D_MODEL];
__device__ __align__(256) __nv_bfloat16 g_attnh[(size_t)M_TOTAL * D_MODEL];
__device__ __align__(256) __nv_bfloat16 g_attnl[(size_t)M_TOTAL * D_MODEL];

// q/k/v as bf16 hi/lo splits (q pre-scaled by 1/sqrt(HEAD_DIM))
__device__ __align__(256) __nv_bfloat16 g_qh[(size_t)BATCH * N_HEADS * SEQ * HEAD_DIM];
__device__ __align__(256) __nv_bfloat16 g_ql[(size_t)BATCH * N_HEADS * SEQ * HEAD_DIM];
__device__ __align__(256) __nv_bfloat16 g_kh[(size_t)BATCH * KV_HEADS * SEQ * HEAD_DIM];
__device__ __align__(256) __nv_bfloat16 g_kl[(size_t)BATCH * KV_HEADS * SEQ * HEAD_DIM];
__device__ __align__(256) __nv_bfloat16 g_vh[(size_t)BATCH * KV_HEADS * SEQ * HEAD_DIM];
__device__ __align__(256) __nv_bfloat16 g_vl[(size_t)BATCH * KV_HEADS * SEQ * HEAD_DIM];

// ====================== helpers (compute_103-safe) =========================
__device__ __forceinline__ uint32_t smem_u32(const void* p) {
    uint32_t a;
    asm("{ .reg .u64 t; cvta.to.shared.u64 t, %1; cvt.u32.u64 %0, t; }"
        : "=r"(a) : "l"(p));
    return a;
}

__device__ __forceinline__ void ldm_x4(uint32_t& r0, uint32_t& r1,
                                       uint32_t& r2, uint32_t& r3, uint32_t addr) {
    asm volatile("ldmatrix.sync.aligned.m8n8.x4.shared.b16 {%0,%1,%2,%3}, [%4];"
                 : "=r"(r0), "=r"(r1), "=r"(r2), "=r"(r3) : "r"(addr));
}
__device__ __forceinline__ void ldm_x4_t(uint32_t& r0, uint32_t& r1,
                                         uint32_t& r2, uint32_t& r3, uint32_t addr) {
    asm volatile("ldmatrix.sync.aligned.m8n8.x4.trans.shared.b16 {%0,%1,%2,%3}, [%4];"
                 : "=r"(r0), "=r"(r1), "=r"(r2), "=r"(r3) : "r"(addr));
}

__device__ __forceinline__ void mma_bf16(float* c, const uint32_t* a,
                                         const uint32_t* b) {
    asm volatile(
        "mma.sync.aligned.m16n8k16.row.col.f32.bf16.bf16.f32 "
        "{%0,%1,%2,%3}, {%4,%5,%6,%7}, {%8,%9}, {%0,%1,%2,%3};"
        : "+f"(c[0]), "+f"(c[1]), "+f"(c[2]), "+f"(c[3])
        : "r"(a[0]), "r"(a[1]), "r"(a[2]), "r"(a[3]), "r"(b[0]), "r"(b[1]));
}

#define CP_ASYNC16(dst, src) \
    asm volatile("cp.async.cg.shared.global [%0], [%1], 16;" \
                 :: "r"(dst), "l"(src) : "memory")
#define CP_COMMIT() asm volatile("cp.async.commit_group;" ::: "memory")
#define CP_WAIT1()  asm volatile("cp.async.wait_group 1;" ::: "memory")
#define CP_WAIT0()  asm volatile("cp.async.wait_group 0;" ::: "memory")

// fast exp for x <= 0, relative error ~2.4e-6 (FMA pipe, no MUFU)
__device__ __forceinline__ float fast_exp(float x) {
    x = fmaxf(x, -80.0f);
    float y = x * 1.4426950408889634f;
    float z = y + 12582912.0f;                 // round-to-nearest int in mantissa
    int   ni = __float_as_int(z) - 0x4B400000; // two's-complement n
    float f = y - (z - 12582912.0f);           // f in [-0.5, 0.5]
    float p = 1.3333558146e-3f;
    p = fmaf(p, f, 9.6181291077e-3f);
    p = fmaf(p, f, 5.5504108664e-2f);
    p = fmaf(p, f, 2.4022650696e-1f);
    p = fmaf(p, f, 6.9314718056e-1f);
    p = fmaf(p, f, 1.0f);
    return p * __int_as_float((ni + 127) << 23);
}

// split x,y into packed bf16 hi pair and lo (residual) pair
__device__ __forceinline__ void split_pack2(float x, float y,
                                            uint32_t& hi, uint32_t& lo) {
    __nv_bfloat162 hh = __floats2bfloat162_rn(x, y);
    float2 hf = __bfloat1622float2(hh);
    __nv_bfloat162 ll = __floats2bfloat162_rn(x - hf.x, y - hf.y);
    hi = *(uint32_t*)&hh;
    lo = *(uint32_t*)&ll;
}

// ---------------- RoPE table (fp64 for exact trig) ------------------------
__global__ void rope_table_kernel() {
    int i = blockIdx.x * blockDim.x + threadIdx.x;
    if (i >= SEQ * 64) return;
    int l = i >> 6, d = i & 63;
    double inv = pow(500000.0, -((double)d) / 64.0);
    double ang = (double)l * inv;
    g_cos[i] = (float)cos(ang);
    g_sin[i] = (float)sin(ang);
}

// ---------------- fp32 -> bf16 hi/lo split ---------------------------------
__global__ __launch_bounds__(256) void split_kernel(
        const float* __restrict__ in, __nv_bfloat16* __restrict__ hi,
        __nv_bfloat16* __restrict__ lo, int n4) {
    int i = blockIdx.x * blockDim.x + threadIdx.x;
    if (i >= n4) return;
    float4 v = ((const float4*)in)[i];
    __nv_bfloat16 h[4], l[4];
    float vv[4] = {v.x, v.y, v.z, v.w};
#pragma unroll
    for (int j = 0; j < 4; j++) {
        h[j] = __float2bfloat16(vv[j]);
        l[j] = __float2bfloat16(vv[j] - __bfloat162float(h[j]));
    }
    ((uint2*)hi)[i] = *(uint2*)h;
    ((uint2*)lo)[i] = *(uint2*)l;
}

// ---------------- split-bf16 GEMM via mma.sync -----------------------------
#define ROWB   40
#define VBYTES (128 * ROWB * 2)
#define STAGEB (4 * VBYTES)
#define GEMM_SMEM_BYTES (2 * STAGEB + 1024)

template<int MODE>
__global__ __launch_bounds__(256) void mma_gemm(
        const __nv_bfloat16* __restrict__ Ah, const __nv_bfloat16* __restrict__ Al,
        const __nv_bfloat16* __restrict__ Bh, const __nv_bfloat16* __restrict__ Bl,
        float* __restrict__ outp) {
    extern __shared__ char smraw[];
    char* smp = (char*)(((uintptr_t)smraw + 1023) & ~(uintptr_t)1023);
    const uint32_t sbase = smem_u32(smp);

    const int tid = threadIdx.x;
    const int lane = tid & 31;
    const int wid = tid >> 5;
    const int warp_m = wid & 1;
    const int warp_n = wid >> 1;
    const int bm = blockIdx.x, bn = blockIdx.y;

    const int lr = tid >> 2;
    const int jj = tid & 3;
    const size_t aoff = (size_t)(bm * 128) * KDIM;
    const size_t boff = (size_t)(bn * 128) * KDIM;

    float acc[4][4][4];
#pragma unroll
    for (int i = 0; i < 4; i++)
#pragma unroll
        for (int j = 0; j < 4; j++)
#pragma unroll
            for (int c = 0; c < 4; c++) acc[i][j][c] = 0.f;

    uint4 rg[8];
    const __nv_bfloat16* srcs[4] = {Ah, Al, Bh, Bl};
    const size_t roff[4] = {aoff, aoff, boff, boff};

    auto load_regs = [&](int ic) {
#pragma unroll
        for (int v = 0; v < 4; v++)
#pragma unroll
            for (int i = 0; i < 2; i++) {
                int r = lr + i * 64;
                rg[v * 2 + i] = *(const uint4*)(srcs[v] + roff[v] +
                                (size_t)r * KDIM + ic * 32 + jj * 8);
            }
    };
    auto store_regs = [&](int st) {
        char* base = smp + st * STAGEB;
#pragma unroll
        for (int v = 0; v < 4; v++)
#pragma unroll
            for (int i = 0; i < 2; i++) {
                int r = lr + i * 64;
                *(uint4*)(base + v * VBYTES + (r * ROWB + jj * 8) * 2) = rg[v * 2 + i];
            }
    };

    const uint32_t a_lane_off =
        (uint32_t)((lane & 15) * (ROWB * 2) + ((lane >> 4) << 3) * 2);
    const uint32_t b_lane_off =
        (uint32_t)((((lane & 16) >> 1) + (lane & 7)) * (ROWB * 2) + (lane & 8) * 2);
    const int m0 = warp_m * 64;
    const int n0 = warp_n * 32;

    auto compute = [&](int st, int passA, int passB) {
        uint32_t sA = sbase + st * STAGEB + passA * VBYTES;
        uint32_t sB = sbase + st * STAGEB + (2 + passB) * VBYTES;
#pragma unroll
        for (int ks = 0; ks < 2; ks++) {
            const uint32_t k0b = ks * 16 * 2;
            uint32_t a[4][4], b[4][2];
#pragma unroll
            for (int mi = 0; mi < 4; mi++)
                ldm_x4(a[mi][0], a[mi][1], a[mi][2], a[mi][3],
                       sA + (uint32_t)((m0 + mi * 16) * (ROWB * 2)) + a_lane_off + k0b);
#pragma unroll
            for (int p = 0; p < 2; p++) {
                uint32_t r0, r1, r2, r3;
                ldm_x4(r0, r1, r2, r3,
                       sB + (uint32_t)((n0 + p * 16) * (ROWB * 2)) + b_lane_off + k0b);
                b[p * 2][0] = r0; b[p * 2][1] = r1;
                b[p * 2 + 1][0] = r2; b[p * 2 + 1][1] = r3;
            }
#pragma unroll
            for (int mi = 0; mi < 4; mi++)
#pragma unroll
                for (int ni = 0; ni < 4; ni++)
                    mma_bf16(acc[mi][ni], a[mi], b[ni]);
        }
    };

    load_regs(0);
    store_regs(0);
    __syncthreads();

    for (int ic = 0; ic < 128; ic++) {
        const int st = ic & 1;
        if (ic + 1 < 128) load_regs(ic + 1);
        compute(st, 0, 0);
        compute(st, 1, 0);
        compute(st, 0, 1);
        __syncthreads();
        if (ic + 1 < 128) store_regs(st ^ 1);
        __syncthreads();
    }

    // ---- epilogue ----
    float* ep = (float*)smp;                 // [128][136]
    const int g = lane >> 2, tg = lane & 3;
#pragma unroll
    for (int mi = 0; mi < 4; mi++)
#pragma unroll
        for (int ni = 0; ni < 4; ni++) {
            int row = m0 + mi * 16 + g;
            int col = n0 + ni * 8 + tg * 2;
            ep[row * 136 + col]       = acc[mi][ni][0];
            ep[row * 136 + col + 1]   = acc[mi][ni][1];
            ep[(row + 8) * 136 + col]     = acc[mi][ni][2];
            ep[(row + 8) * 136 + col + 1] = acc[mi][ni][3];
        }
    __syncthreads();

    for (int t = tid; t < 128 * 16; t += 256) {
        int row = t >> 4, j = t & 15;
        float4 v1 = *(const float4*)&ep[row * 136 + j * 4];
        float4 v2 = *(const float4*)&ep[row * 136 + 64 + j * 4];
        if (MODE == 0) {
            float* p1 = &v1.x; float* p2 = &v2.x;
#pragma unroll
            for (int e = 0; e < 4; e++) {
                p1[e] = fminf(fmaxf(p1[e], -8.0f), 8.0f);
                p2[e] = fminf(fmaxf(p2[e], -8.0f), 8.0f);
            }
            int m = bm * 128 + row;
            int bb = m >> 11, l = m & (SEQ - 1);
            if (bn < N_HEADS + KV_HEADS) {   // RoPE for q and k heads
#pragma unroll
                for (int e = 0; e < 4; e++) {
                    int d = j * 4 + e;
                    float c = g_cos[l * 64 + d];
                    float s = g_sin[l * 64 + d];
                    float x1 = p1[e], x2 = p2[e];
                    p1[e] = x1 * c - x2 * s;
                    p2[e] = x2 * c + x1 * s;
                }
            }
            float sc = 1.0f;
            __nv_bfloat16 *dhi, *dlo;
            size_t off;
            if (bn < N_HEADS) {
                sc = 0.08838834764831845f;   // fold 1/sqrt(128) into q
                off = ((size_t)(bb * N_HEADS + bn) * SEQ + l) * HEAD_DIM;
                dhi = g_qh; dlo = g_ql;
            } else if (bn < N_HEADS + KV_HEADS) {
                off = ((size_t)(bb * KV_HEADS + (bn - N_HEADS)) * SEQ + l) * HEAD_DIM;
                dhi = g_kh; dlo = g_kl;
            } else {
                off = ((size_t)(bb * KV_HEADS + (bn - N_HEADS - KV_HEADS)) * SEQ + l) * HEAD_DIM;
                dhi = g_vh; dlo = g_vl;
            }
            __nv_bfloat16 hb[8], lb[8];
            float vv[8] = {p1[0]*sc, p1[1]*sc, p1[2]*sc, p1[3]*sc,
                           p2[0]*sc, p2[1]*sc, p2[2]*sc, p2[3]*sc};
#pragma unroll
            for (int e = 0; e < 8; e++) {
                hb[e] = __float2bfloat16(vv[e]);
                lb[e] = __float2bfloat16(vv[e] - __bfloat162float(hb[e]));
            }
            *(uint2*)(dhi + off + j * 4)      = *(uint2*)hb;
            *(uint2*)(dlo + off + j * 4)      = *(uint2*)lb;
            *(uint2*)(dhi + off + 64 + j * 4) = *(uint2*)(hb + 4);
            *(uint2*)(dlo + off + 64 + j * 4) = *(uint2*)(lb + 4);
        } else {
            float* dst = outp + (size_t)(bm * 128 + row) * D_MODEL + bn * 128;
            *(float4*)(dst + j * 4) = v1;
            *(float4*)(dst + 64 + j * 4) = v2;
        }
    }
}

// ---------------- tensor-core flash attention ------------------------------
// 128 q-rows per CTA, 64-key tiles. 8 warps, warp w owns rows w*16..w*16+15.
// S = QhKh + QlKh + QhKl; P split hi/lo; O += PhVh + PlVh + PhVl.
#define AT_STRIDE 136                      /* bf16 elems per smem row */
#define AT_ROWB   (AT_STRIDE * 2)          /* 272 bytes */
#define AT_KV_VB  (64  * AT_ROWB)          /* 17408 */
#define AT_Q_VB   (128 * AT_ROWB)          /* 34816 */
#define AT_SMEM   (2 * AT_Q_VB + 8 * AT_KV_VB)   /* 208896 */

__global__ void __launch_bounds__(256, 1) attn_mma_kernel() {
    extern __shared__ char smp[];
    const uint32_t sb  = smem_u32(smp);
    const uint32_t qhB = sb, qlB = sb + AT_Q_VB;
    const uint32_t kvB = sb + 2 * AT_Q_VB;

    const int tid = threadIdx.x, lane = tid & 31, w = tid >> 5;
    const int g = lane >> 2, tg = lane & 3;
    const int qt = 15 - (int)blockIdx.x;     // big tiles first
    const int bh = blockIdx.y;
    const int b = bh >> 5, h = bh & 31, kh = h >> 2;

    const __nv_bfloat16* Qhp = g_qh + ((size_t)(b * N_HEADS + h) * SEQ + qt * 128) * HEAD_DIM;
    const __nv_bfloat16* Qlp = g_ql + ((size_t)(b * N_HEADS + h) * SEQ + qt * 128) * HEAD_DIM;
    const __nv_bfloat16* Khp = g_kh + (size_t)(b * KV_HEADS + kh) * SEQ * HEAD_DIM;
    const __nv_bfloat16* Klp = g_kl + (size_t)(b * KV_HEADS + kh) * SEQ * HEAD_DIM;
    const __nv_bfloat16* Vhp = g_vh + (size_t)(b * KV_HEADS + kh) * SEQ * HEAD_DIM;
    const __nv_bfloat16* Vlp = g_vl + (size_t)(b * KV_HEADS + kh) * SEQ * HEAD_DIM;

    const int nkt = 2 * qt + 2;

    auto issue = [&](int kt, int st) {
        uint32_t base = kvB + (uint32_t)st * (4 * AT_KV_VB);
        const __nv_bfloat16* srcs[4] = {Khp, Klp, Vhp, Vlp};
#pragma unroll
        for (int v = 0; v < 4; v++) {
            const __nv_bfloat16* src = srcs[v] + (size_t)kt * 64 * HEAD_DIM;
#pragma unroll
            for (int t = 0; t < 4; t++) {
                int c = tid + t * 256;
                int row = c >> 4, cc = c & 15;
                CP_ASYNC16(base + (uint32_t)v * AT_KV_VB + row * AT_ROWB + cc * 16,
                           src + (size_t)row * HEAD_DIM + cc * 8);
            }
        }
    };

    issue(0, 0);
    CP_COMMIT();

    // stage Q hi/lo into smem
    for (int i = tid; i < 128 * 16; i += 256) {
        int row = i >> 4, c = i & 15;
        *(uint4*)(smp + row * AT_ROWB + c * 16) =
            *(const uint4*)(Qhp + (size_t)row * HEAD_DIM + c * 8);
        *(uint4*)(smp + AT_Q_VB + row * AT_ROWB + c * 16) =
            *(const uint4*)(Qlp + (size_t)row * HEAD_DIM + c * 8);
    }
    __syncthreads();

    float o[16][4];
#pragma unroll
    for (int j = 0; j < 16; j++)
#pragma unroll
        for (int c = 0; c < 4; c++) o[j][c] = 0.f;
    float mi0 = -1e30f, mi1 = -1e30f, li0 = 0.f, li1 = 0.f;

    const uint32_t a_off = (uint32_t)((lane & 15) * AT_ROWB + ((lane >> 4) << 4));
    const uint32_t b_off = (uint32_t)((((lane & 16) >> 1) + (lane & 7)) * AT_ROWB + (lane & 8) * 2);
    const uint32_t v_off = (uint32_t)((lane & 15) * AT_ROWB + ((lane >> 4) << 4));
    const uint32_t qrowb = (uint32_t)(w * 16) * AT_ROWB;

    for (int kt = 0; kt < nkt; kt++) {
        const uint32_t kb_ = kvB + (uint32_t)(kt & 1) * (4 * AT_KV_VB);
        if (kt + 1 < nkt) { issue(kt + 1, (kt + 1) & 1); CP_COMMIT(); CP_WAIT1(); }
        else              { CP_WAIT0(); }
        __syncthreads();

        // ---- S = Q K^T (3 split passes), fp32 accum ----
        float s[8][4];
#pragma unroll
        for (int j = 0; j < 8; j++)
#pragma unroll
            for (int c = 0; c < 4; c++) s[j][c] = 0.f;

#pragma unroll
        for (int kc = 0; kc < 8; kc++) {
            uint32_t aq[4], al4[4], kf[8][2];
            ldm_x4(aq[0], aq[1], aq[2], aq[3],  qhB + qrowb + kc * 32 + a_off);
            ldm_x4(al4[0], al4[1], al4[2], al4[3], qlB + qrowb + kc * 32 + a_off);
#pragma unroll
            for (int g8 = 0; g8 < 4; g8++)
                ldm_x4(kf[g8*2][0], kf[g8*2][1], kf[g8*2+1][0], kf[g8*2+1][1],
                       kb_ + (uint32_t)(g8 * 16) * AT_ROWB + kc * 32 + b_off);
#pragma unroll
            for (int j = 0; j < 8; j++) { mma_bf16(s[j], aq, kf[j]); mma_bf16(s[j], al4, kf[j]); }
#pragma unroll
            for (int g8 = 0; g8 < 4; g8++)
                ldm_x4(kf[g8*2][0], kf[g8*2][1], kf[g8*2+1][0], kf[g8*2+1][1],
                       kb_ + AT_KV_VB + (uint32_t)(g8 * 16) * AT_ROWB + kc * 32 + b_off);
#pragma unroll
            for (int j = 0; j < 8; j++) mma_bf16(s[j], aq, kf[j]);
        }

        // ---- causal mask (partial tiles only) ----
        if (kt * 64 + 63 > qt * 128 + w * 16) {
            int qr = qt * 128 + w * 16 + g;
#pragma unroll
            for (int j = 0; j < 8; j++) {
                int key = kt * 64 + j * 8 + tg * 2;
                if (key     > qr)     s[j][0] = -1e30f;
                if (key + 1 > qr)     s[j][1] = -1e30f;
                if (key     > qr + 8) s[j][2] = -1e30f;
                if (key + 1 > qr + 8) s[j][3] = -1e30f;
            }
        }

        // ---- online softmax ----
        float rm0 = s[0][0], rm1 = s[0][2];
#pragma unroll
        for (int j = 0; j < 8; j++) {
            rm0 = fmaxf(rm0, fmaxf(s[j][0], s[j][1]));
            rm1 = fmaxf(rm1, fmaxf(s[j][2], s[j][3]));
        }
        rm0 = fmaxf(rm0, __shfl_xor_sync(0xffffffffu, rm0, 1));
        rm0 = fmaxf(rm0, __shfl_xor_sync(0xffffffffu, rm0, 2));
        rm1 = fmaxf(rm1, __shfl_xor_sync(0xffffffffu, rm1, 1));
        rm1 = fmaxf(rm1, __shfl_xor_sync(0xffffffffu, rm1, 2));
        float mn0 = fmaxf(mi0, rm0), mn1 = fmaxf(mi1, rm1);
        float c0 = fast_exp(mi0 - mn0), c1 = fast_exp(mi1 - mn1);
        mi0 = mn0; mi1 = mn1;
        float sum0 = 0.f, sum1 = 0.f;
#pragma unroll
        for (int j = 0; j < 8; j++) {
            s[j][0] = fast_exp(s[j][0] - mn0); sum0 += s[j][0];
            s[j][1] = fast_exp(s[j][1] - mn0); sum0 += s[j][1];
            s[j][2] = fast_exp(s[j][2] - mn1); sum1 += s[j][2];
            s[j][3] = fast_exp(s[j][3] - mn1); sum1 += s[j][3];
        }
        sum0 += __shfl_xor_sync(0xffffffffu, sum0, 1);
        sum0 += __shfl_xor_sync(0xffffffffu, sum0, 2);
        sum1 += __shfl_xor_sync(0xffffffffu, sum1, 1);
        sum1 += __shfl_xor_sync(0xffffffffu, sum1, 2);
        li0 = li0 * c0 + sum0; li1 = li1 * c1 + sum1;
#pragma unroll
        for (int j = 0; j < 16; j++) {
            o[j][0] *= c0; o[j][1] *= c0; o[j][2] *= c1; o[j][3] *= c1;
        }

        // ---- pack P into hi/lo A-fragments (C layout == A layout) ----
        uint32_t ph[4][4], pl[4][4];
#pragma unroll
        for (int kc = 0; kc < 4; kc++) {
            split_pack2(s[2*kc][0],   s[2*kc][1],   ph[kc][0], pl[kc][0]);
            split_pack2(s[2*kc][2],   s[2*kc][3],   ph[kc][1], pl[kc][1]);
            split_pack2(s[2*kc+1][0], s[2*kc+1][1], ph[kc][2], pl[kc][2]);
            split_pack2(s[2*kc+1][2], s[2*kc+1][3], ph[kc][3], pl[kc][3]);
        }

        // ---- O += P @ V (V^T via ldmatrix.trans) ----
#pragma unroll
        for (int g8 = 0; g8 < 8; g8++) {
#pragma unroll
            for (int kc = 0; kc < 4; kc++) {
                uint32_t r0, r1, r2, r3;
                ldm_x4_t(r0, r1, r2, r3,
                         kb_ + 2 * AT_KV_VB + (uint32_t)(kc * 16) * AT_ROWB + g8 * 32 + v_off);
                uint32_t b0[2] = {r0, r1}, b1[2] = {r2, r3};
                mma_bf16(o[2*g8],   ph[kc], b0);
                mma_bf16(o[2*g8+1], ph[kc], b1);
                mma_bf16(o[2*g8],   pl[kc], b0);
                mma_bf16(o[2*g8+1], pl[kc], b1);
            }
#pragma unroll
            for (int kc = 0; kc < 4; kc++) {
                uint32_t r0, r1, r2, r3;
                ldm_x4_t(r0, r1, r2, r3,
                         kb_ + 3 * AT_KV_VB + (uint32_t)(kc * 16) * AT_ROWB + g8 * 32 + v_off);
                uint32_t b0[2] = {r0, r1}, b1[2] = {r2, r3};
                mma_bf16(o[2*g8],   ph[kc], b0);
                mma_bf16(o[2*g8+1], ph[kc], b1);
            }
        }
        __syncthreads();
    }

    // ---- epilogue: O/l -> bf16 hi/lo to g_attn{h,l} ----
    float inv0 = 1.0f / li0, inv1 = 1.0f / li1;
    int row0 = qt * 128 + w * 16 + g;
    size_t base  = ((size_t)b * SEQ + row0) * D_MODEL + h * HEAD_DIM;
    size_t base8 = base + (size_t)8 * D_MODEL;
#pragma unroll
    for (int j = 0; j < 16; j++) {
        int col = j * 8 + tg * 2;
        uint32_t hi, lo;
        split_pack2(o[j][0] * inv0, o[j][1] * inv0, hi, lo);
        *(uint32_t*)(g_attnh + base + col) = hi;
        *(uint32_t*)(g_attnl + base + col) = lo;
        split_pack2(o[j][2] * inv1, o[j][3] * inv1, hi, lo);
        *(uint32_t*)(g_attnh + base8 + col) = hi;
        *(uint32_t*)(g_attnl + base8 + col) = lo;
    }
}

// ---------------- launch ---------------------------------------------------
extern "C" void kernel_launch(void* const* d_in, const int* in_sizes, int n_in,
                              void* d_out, int out_size) {
    const float* x    = (const float*)d_in[0];
    const float* Wqkv = (const float*)d_in[1];
    const float* Wout = (const float*)d_in[2];
    float* out = (float*)d_out;

    __nv_bfloat16 *xh, *xl, *wqh, *wql, *woh, *wol, *ah, *al;
    cudaGetSymbolAddress((void**)&xh,  g_xh);
    cudaGetSymbolAddress((void**)&xl,  g_xl);
    cudaGetSymbolAddress((void**)&wqh, g_wqkvh);
    cudaGetSymbolAddress((void**)&wql, g_wqkvl);
    cudaGetSymbolAddress((void**)&woh, g_wouth);
    cudaGetSymbolAddress((void**)&wol, g_woutl);
    cudaGetSymbolAddress((void**)&ah,  g_attnh);
    cudaGetSymbolAddress((void**)&al,  g_attnl);

    rope_table_kernel<<<(SEQ * 64 + 255) / 256, 256>>>();

    {   // fp32 -> bf16 hi/lo splits
        int n4x = M_TOTAL * D_MODEL / 4;
        split_kernel<<<(n4x + 255) / 256, 256>>>(x, xh, xl, n4x);
        int n4q = QKV_N * D_MODEL / 4;
        split_kernel<<<(n4q + 255) / 256, 256>>>(Wqkv, wqh, wql, n4q);
        int n4o = D_MODEL * D_MODEL / 4;
        split_kernel<<<(n4o + 255) / 256, 256>>>(Wout, woh, wol, n4o);
    }

    cudaFuncSetAttribute(mma_gemm<0>, cudaFuncAttributeMaxDynamicSharedMemorySize,
                         GEMM_SMEM_BYTES);
    cudaFuncSetAttribute(mma_gemm<1>, cudaFuncAttributeMaxDynamicSharedMemorySize,
                         GEMM_SMEM_BYTES);
    cudaFuncSetAttribute(attn_mma_kernel, cudaFuncAttributeMaxDynamicSharedMemorySize,
                         AT_SMEM);

    // QKV projection: fused clip+RoPE+scale+split-scatter
    mma_gemm<0><<<dim3(M_TOTAL / 128, QKV_N / 128), 256, GEMM_SMEM_BYTES>>>(
        xh, xl, wqh, wql, nullptr);

    // tensor-core flash attention
    attn_mma_kernel<<<dim3(SEQ / 128, BATCH * N_HEADS), 256, AT_SMEM>>>();

    // out projection
    mma_gemm<1><<<dim3(M_TOTAL / 128, D_MODEL / 128), 256, GEMM_SMEM_BYTES>>>(
        ah, al, woh, wol, out);
}

// round 5
// speedup vs baseline: 2.8031x; 1.0625x over previous
#include <cuda_runtime.h>
#include <cuda_bf16.h>
#include <math.h>
#include <stdint.h>

#define N_HEADS   32
#define KV_HEADS  8
#define HEAD_DIM  128
#define D_MODEL   4096
#define BATCH     2
#define SEQ       2048
#define M_TOTAL   (BATCH * SEQ)                          /* 4096 */
#define QKV_N     ((KV_HEADS * 2 + N_HEADS) * HEAD_DIM)  /* 6144 */
#define KDIM      4096

// ---------------- scratch (static device globals; no allocation) ----------
__device__ float g_cos[SEQ * 64];
__device__ float g_sin[SEQ * 64];

__device__ __align__(256) __nv_bfloat16 g_xh[(size_t)M_TOTAL * D_MODEL];
__device__ __align__(256) __nv_bfloat16 g_xl[(size_t)M_TOTAL * D_MODEL];
__device__ __align__(256) __nv_bfloat16 g_wqkvh[(size_t)QKV_N * D_MODEL];
__device__ __align__(256) __nv_bfloat16 g_wqkvl[(size_t)QKV_N * D_MODEL];
__device__ __align__(256) __nv_bfloat16 g_wouth[(size_t)D_MODEL * D_MODEL];
__device__ __align__(256) __nv_bfloat16 g_woutl[(size_t)D_MODEL * D_MODEL];
__device__ __align__(256) __nv_bfloat16 g_attnh[(size_t)M_TOTAL * D_MODEL];
__device__ __align__(256) __nv_bfloat16 g_attnl[(size_t)M_TOTAL * D_MODEL];

// q/k/v as bf16 hi/lo splits (q pre-scaled by 1/sqrt(HEAD_DIM))
__device__ __align__(256) __nv_bfloat16 g_qh[(size_t)BATCH * N_HEADS * SEQ * HEAD_DIM];
__device__ __align__(256) __nv_bfloat16 g_ql[(size_t)BATCH * N_HEADS * SEQ * HEAD_DIM];
__device__ __align__(256) __nv_bfloat16 g_kh[(size_t)BATCH * KV_HEADS * SEQ * HEAD_DIM];
__device__ __align__(256) __nv_bfloat16 g_kl[(size_t)BATCH * KV_HEADS * SEQ * HEAD_DIM];
__device__ __align__(256) __nv_bfloat16 g_vh[(size_t)BATCH * KV_HEADS * SEQ * HEAD_DIM];
__device__ __align__(256) __nv_bfloat16 g_vl[(size_t)BATCH * KV_HEADS * SEQ * HEAD_DIM];

// ====================== helpers (compute_103-safe) =========================
__device__ __forceinline__ uint32_t smem_u32(const void* p) {
    uint32_t a;
    asm("{ .reg .u64 t; cvta.to.shared.u64 t, %1; cvt.u32.u64 %0, t; }"
        : "=r"(a) : "l"(p));
    return a;
}

__device__ __forceinline__ void ldm_x4(uint32_t& r0, uint32_t& r1,
                                       uint32_t& r2, uint32_t& r3, uint32_t addr) {
    asm volatile("ldmatrix.sync.aligned.m8n8.x4.shared.b16 {%0,%1,%2,%3}, [%4];"
                 : "=r"(r0), "=r"(r1), "=r"(r2), "=r"(r3) : "r"(addr));
}
__device__ __forceinline__ void ldm_x4_t(uint32_t& r0, uint32_t& r1,
                                         uint32_t& r2, uint32_t& r3, uint32_t addr) {
    asm volatile("ldmatrix.sync.aligned.m8n8.x4.trans.shared.b16 {%0,%1,%2,%3}, [%4];"
                 : "=r"(r0), "=r"(r1), "=r"(r2), "=r"(r3) : "r"(addr));
}

__device__ __forceinline__ void mma_bf16(float* c, const uint32_t* a,
                                         const uint32_t* b) {
    asm volatile(
        "mma.sync.aligned.m16n8k16.row.col.f32.bf16.bf16.f32 "
        "{%0,%1,%2,%3}, {%4,%5,%6,%7}, {%8,%9}, {%0,%1,%2,%3};"
        : "+f"(c[0]), "+f"(c[1]), "+f"(c[2]), "+f"(c[3])
        : "r"(a[0]), "r"(a[1]), "r"(a[2]), "r"(a[3]), "r"(b[0]), "r"(b[1]));
}

#define CP_ASYNC16(dst, src) \
    asm volatile("cp.async.cg.shared.global [%0], [%1], 16;" \
                 :: "r"(dst), "l"(src) : "memory")
#define CP_COMMIT() asm volatile("cp.async.commit_group;" ::: "memory")
#define CP_WAIT2()  asm volatile("cp.async.wait_group 2;" ::: "memory")
#define CP_WAIT1()  asm volatile("cp.async.wait_group 1;" ::: "memory")
#define CP_WAIT0()  asm volatile("cp.async.wait_group 0;" ::: "memory")

// fast exp for x <= 0, relative error ~2.4e-6 (FMA pipe, no MUFU)
__device__ __forceinline__ float fast_exp(float x) {
    x = fmaxf(x, -80.0f);
    float y = x * 1.4426950408889634f;
    float z = y + 12582912.0f;
    int   ni = __float_as_int(z) - 0x4B400000;
    float f = y - (z - 12582912.0f);
    float p = 1.3333558146e-3f;
    p = fmaf(p, f, 9.6181291077e-3f);
    p = fmaf(p, f, 5.5504108664e-2f);
    p = fmaf(p, f, 2.4022650696e-1f);
    p = fmaf(p, f, 6.9314718056e-1f);
    p = fmaf(p, f, 1.0f);
    return p * __int_as_float((ni + 127) << 23);
}

__device__ __forceinline__ void split_pack2(float x, float y,
                                            uint32_t& hi, uint32_t& lo) {
    __nv_bfloat162 hh = __floats2bfloat162_rn(x, y);
    float2 hf = __bfloat1622float2(hh);
    __nv_bfloat162 ll = __floats2bfloat162_rn(x - hf.x, y - hf.y);
    hi = *(uint32_t*)&hh;
    lo = *(uint32_t*)&ll;
}

// ---------------- RoPE table (fp64 for exact trig) ------------------------
__global__ void rope_table_kernel() {
    int i = blockIdx.x * blockDim.x + threadIdx.x;
    if (i >= SEQ * 64) return;
    int l = i >> 6, d = i & 63;
    double inv = pow(500000.0, -((double)d) / 64.0);
    double ang = (double)l * inv;
    g_cos[i] = (float)cos(ang);
    g_sin[i] = (float)sin(ang);
}

// ---------------- fp32 -> bf16 hi/lo split ---------------------------------
__global__ __launch_bounds__(256) void split_kernel(
        const float* __restrict__ in, __nv_bfloat16* __restrict__ hi,
        __nv_bfloat16* __restrict__ lo, int n4) {
    int i = blockIdx.x * blockDim.x + threadIdx.x;
    if (i >= n4) return;
    float4 v = ((const float4*)in)[i];
    __nv_bfloat16 h[4], l[4];
    float vv[4] = {v.x, v.y, v.z, v.w};
#pragma unroll
    for (int j = 0; j < 4; j++) {
        h[j] = __float2bfloat16(vv[j]);
        l[j] = __float2bfloat16(vv[j] - __bfloat162float(h[j]));
    }
    ((uint2*)hi)[i] = *(uint2*)h;
    ((uint2*)lo)[i] = *(uint2*)l;
}

// ---------------- split-bf16 GEMM via mma.sync + cp.async pipeline --------
// C[128x128] per CTA = A @ B^T; K-chunk 32; 4 smem stages, 3 in flight.
#define ROWB   40                              /* bf16 elems per smem row */
#define VBYTES (128 * ROWB * 2)                /* 10240 per variant */
#define STAGEB (4 * VBYTES)                    /* 40960 per stage   */
#define NSTAGE 4
#define GEMM_SMEM_BYTES (NSTAGE * STAGEB + 1024)

template<int MODE>
__global__ __launch_bounds__(256) void mma_gemm(
        const __nv_bfloat16* __restrict__ Ah, const __nv_bfloat16* __restrict__ Al,
        const __nv_bfloat16* __restrict__ Bh, const __nv_bfloat16* __restrict__ Bl,
        float* __restrict__ outp) {
    extern __shared__ char smraw[];
    char* smp = (char*)(((uintptr_t)smraw + 1023) & ~(uintptr_t)1023);
    const uint32_t sbase = smem_u32(smp);

    const int tid = threadIdx.x;
    const int lane = tid & 31;
    const int wid = tid >> 5;
    const int warp_m = wid & 1;
    const int warp_n = wid >> 1;
    const int bm = blockIdx.x, bn = blockIdx.y;

    const size_t aoff = (size_t)(bm * 128) * KDIM;
    const size_t boff = (size_t)(bn * 128) * KDIM;
    const __nv_bfloat16* srcs[4] = {Ah, Al, Bh, Bl};
    const size_t roff[4] = {aoff, aoff, boff, boff};

    float acc[4][4][4];
#pragma unroll
    for (int i = 0; i < 4; i++)
#pragma unroll
        for (int j = 0; j < 4; j++)
#pragma unroll
            for (int c = 0; c < 4; c++) acc[i][j][c] = 0.f;

    // cp.async: 2048 16B-chunks per stage, 8 per thread
    auto issue = [&](int ic, int st) {
        uint32_t base = sbase + (uint32_t)st * STAGEB;
#pragma unroll
        for (int t = 0; t < 8; t++) {
            int idx = tid + t * 256;          // 0..2047
            int v = idx >> 9;                 // variant
            int r = (idx >> 2) & 127;         // row
            int c = idx & 3;                  // 16B chunk in row
            CP_ASYNC16(base + (uint32_t)(v * VBYTES + r * 80 + c * 16),
                       srcs[v] + roff[v] + (size_t)r * KDIM + ic * 32 + c * 8);
        }
    };

    const uint32_t a_lane_off =
        (uint32_t)((lane & 15) * 80 + ((lane >> 4) << 3) * 2);
    const uint32_t b_lane_off =
        (uint32_t)((((lane & 16) >> 1) + (lane & 7)) * 80 + (lane & 8) * 2);
    const int m0 = warp_m * 64;
    const int n0 = warp_n * 32;

    auto compute = [&](uint32_t sst) {
#pragma unroll
        for (int ks = 0; ks < 2; ks++) {
            const uint32_t k0b = ks * 32;
            uint32_t ah[4][4], al[4][4], bh[4][2], bl[4][2];
#pragma unroll
            for (int mi = 0; mi < 4; mi++) {
                ldm_x4(ah[mi][0], ah[mi][1], ah[mi][2], ah[mi][3],
                       sst + (uint32_t)((m0 + mi * 16) * 80) + a_lane_off + k0b);
                ldm_x4(al[mi][0], al[mi][1], al[mi][2], al[mi][3],
                       sst + VBYTES + (uint32_t)((m0 + mi * 16) * 80) + a_lane_off + k0b);
            }
#pragma unroll
            for (int p = 0; p < 2; p++) {
                uint32_t r0, r1, r2, r3;
                ldm_x4(r0, r1, r2, r3,
                       sst + 2 * VBYTES + (uint32_t)((n0 + p * 16) * 80) + b_lane_off + k0b);
                bh[p * 2][0] = r0; bh[p * 2][1] = r1;
                bh[p * 2 + 1][0] = r2; bh[p * 2 + 1][1] = r3;
                ldm_x4(r0, r1, r2, r3,
                       sst + 3 * VBYTES + (uint32_t)((n0 + p * 16) * 80) + b_lane_off + k0b);
                bl[p * 2][0] = r0; bl[p * 2][1] = r1;
                bl[p * 2 + 1][0] = r2; bl[p * 2 + 1][1] = r3;
            }
#pragma unroll
            for (int mi = 0; mi < 4; mi++)
#pragma unroll
                for (int ni = 0; ni < 4; ni++) {
                    mma_bf16(acc[mi][ni], ah[mi], bh[ni]);
                    mma_bf16(acc[mi][ni], al[mi], bh[ni]);
                    mma_bf16(acc[mi][ni], ah[mi], bl[ni]);
                }
        }
    };

    // prologue: 3 chunks in flight
    issue(0, 0); CP_COMMIT();
    issue(1, 1); CP_COMMIT();
    issue(2, 2); CP_COMMIT();

    for (int ic = 0; ic < 128; ic++) {
        if (ic <= 125)      CP_WAIT2();
        else if (ic == 126) CP_WAIT1();
        else                CP_WAIT0();
        __syncthreads();   // chunk ic visible to all; stage (ic+3)&3 free to refill
        if (ic + 3 < 128) { issue(ic + 3, (ic + 3) & 3); CP_COMMIT(); }
        compute(sbase + (uint32_t)(ic & 3) * STAGEB);
    }
    __syncthreads();

    // ---- epilogue ----
    float* ep = (float*)smp;                 // [128][136]
    const int g = lane >> 2, tg = lane & 3;
#pragma unroll
    for (int mi = 0; mi < 4; mi++)
#pragma unroll
        for (int ni = 0; ni < 4; ni++) {
            int row = m0 + mi * 16 + g;
            int col = n0 + ni * 8 + tg * 2;
            ep[row * 136 + col]       = acc[mi][ni][0];
            ep[row * 136 + col + 1]   = acc[mi][ni][1];
            ep[(row + 8) * 136 + col]     = acc[mi][ni][2];
            ep[(row + 8) * 136 + col + 1] = acc[mi][ni][3];
        }
    __syncthreads();

    for (int t = tid; t < 128 * 16; t += 256) {
        int row = t >> 4, j = t & 15;
        float4 v1 = *(const float4*)&ep[row * 136 + j * 4];
        float4 v2 = *(const float4*)&ep[row * 136 + 64 + j * 4];
        if (MODE == 0) {
            float* p1 = &v1.x; float* p2 = &v2.x;
#pragma unroll
            for (int e = 0; e < 4; e++) {
                p1[e] = fminf(fmaxf(p1[e], -8.0f), 8.0f);
                p2[e] = fminf(fmaxf(p2[e], -8.0f), 8.0f);
            }
            int m = bm * 128 + row;
            int bb = m >> 11, l = m & (SEQ - 1);
            if (bn < N_HEADS + KV_HEADS) {   // RoPE for q and k heads
#pragma unroll
                for (int e = 0; e < 4; e++) {
                    int d = j * 4 + e;
                    float c = g_cos[l * 64 + d];
                    float s = g_sin[l * 64 + d];
                    float x1 = p1[e], x2 = p2[e];
                    p1[e] = x1 * c - x2 * s;
                    p2[e] = x2 * c + x1 * s;
                }
            }
            float sc = 1.0f;
            __nv_bfloat16 *dhi, *dlo;
            size_t off;
            if (bn < N_HEADS) {
                sc = 0.08838834764831845f;   // fold 1/sqrt(128) into q
                off = ((size_t)(bb * N_HEADS + bn) * SEQ + l) * HEAD_DIM;
                dhi = g_qh; dlo = g_ql;
            } else if (bn < N_HEADS + KV_HEADS) {
                off = ((size_t)(bb * KV_HEADS + (bn - N_HEADS)) * SEQ + l) * HEAD_DIM;
                dhi = g_kh; dlo = g_kl;
            } else {
                off = ((size_t)(bb * KV_HEADS + (bn - N_HEADS - KV_HEADS)) * SEQ + l) * HEAD_DIM;
                dhi = g_vh; dlo = g_vl;
            }
            __nv_bfloat16 hb[8], lb[8];
            float vv[8] = {p1[0]*sc, p1[1]*sc, p1[2]*sc, p1[3]*sc,
                           p2[0]*sc, p2[1]*sc, p2[2]*sc, p2[3]*sc};
#pragma unroll
            for (int e = 0; e < 8; e++) {
                hb[e] = __float2bfloat16(vv[e]);
                lb[e] = __float2bfloat16(vv[e] - __bfloat162float(hb[e]));
            }
            *(uint2*)(dhi + off + j * 4)      = *(uint2*)hb;
            *(uint2*)(dlo + off + j * 4)      = *(uint2*)lb;
            *(uint2*)(dhi + off + 64 + j * 4) = *(uint2*)(hb + 4);
            *(uint2*)(dlo + off + 64 + j * 4) = *(uint2*)(lb + 4);
        } else {
            float* dst = outp + (size_t)(bm * 128 + row) * D_MODEL + bn * 128;
            *(float4*)(dst + j * 4) = v1;
            *(float4*)(dst + 64 + j * 4) = v2;
        }
    }
}

// ---------------- tensor-core flash attention ------------------------------
#define AT_STRIDE 136
#define AT_ROWB   (AT_STRIDE * 2)
#define AT_KV_VB  (64  * AT_ROWB)
#define AT_Q_VB   (128 * AT_ROWB)
#define AT_SMEM   (2 * AT_Q_VB + 8 * AT_KV_VB)

__global__ void __launch_bounds__(256, 1) attn_mma_kernel() {
    extern __shared__ char smp[];
    const uint32_t sb  = smem_u32(smp);
    const uint32_t qhB = sb, qlB = sb + AT_Q_VB;
    const uint32_t kvB = sb + 2 * AT_Q_VB;

    const int tid = threadIdx.x, lane = tid & 31, w = tid >> 5;
    const int g = lane >> 2, tg = lane & 3;
    const int qt = 15 - (int)blockIdx.x;
    const int bh = blockIdx.y;
    const int b = bh >> 5, h = bh & 31, kh = h >> 2;

    const __nv_bfloat16* Qhp = g_qh + ((size_t)(b * N_HEADS + h) * SEQ + qt * 128) * HEAD_DIM;
    const __nv_bfloat16* Qlp = g_ql + ((size_t)(b * N_HEADS + h) * SEQ + qt * 128) * HEAD_DIM;
    const __nv_bfloat16* Khp = g_kh + (size_t)(b * KV_HEADS + kh) * SEQ * HEAD_DIM;
    const __nv_bfloat16* Klp = g_kl + (size_t)(b * KV_HEADS + kh) * SEQ * HEAD_DIM;
    const __nv_bfloat16* Vhp = g_vh + (size_t)(b * KV_HEADS + kh) * SEQ * HEAD_DIM;
    const __nv_bfloat16* Vlp = g_vl + (size_t)(b * KV_HEADS + kh) * SEQ * HEAD_DIM;

    const int nkt = 2 * qt + 2;

    auto issue = [&](int kt, int st) {
        uint32_t base = kvB + (uint32_t)st * (4 * AT_KV_VB);
        const __nv_bfloat16* srcs[4] = {Khp, Klp, Vhp, Vlp};
#pragma unroll
        for (int v = 0; v < 4; v++) {
            const __nv_bfloat16* src = srcs[v] + (size_t)kt * 64 * HEAD_DIM;
#pragma unroll
            for (int t = 0; t < 4; t++) {
                int c = tid + t * 256;
                int row = c >> 4, cc = c & 15;
                CP_ASYNC16(base + (uint32_t)v * AT_KV_VB + row * AT_ROWB + cc * 16,
                           src + (size_t)row * HEAD_DIM + cc * 8);
            }
        }
    };

    issue(0, 0);
    CP_COMMIT();

    for (int i = tid; i < 128 * 16; i += 256) {
        int row = i >> 4, c = i & 15;
        *(uint4*)(smp + row * AT_ROWB + c * 16) =
            *(const uint4*)(Qhp + (size_t)row * HEAD_DIM + c * 8);
        *(uint4*)(smp + AT_Q_VB + row * AT_ROWB + c * 16) =
            *(const uint4*)(Qlp + (size_t)row * HEAD_DIM + c * 8);
    }
    __syncthreads();

    float o[16][4];
#pragma unroll
    for (int j = 0; j < 16; j++)
#pragma unroll
        for (int c = 0; c < 4; c++) o[j][c] = 0.f;
    float mi0 = -1e30f, mi1 = -1e30f, li0 = 0.f, li1 = 0.f;

    const uint32_t a_off = (uint32_t)((lane & 15) * AT_ROWB + ((lane >> 4) << 4));
    const uint32_t b_off = (uint32_t)((((lane & 16) >> 1) + (lane & 7)) * AT_ROWB + (lane & 8) * 2);
    const uint32_t v_off = (uint32_t)((lane & 15) * AT_ROWB + ((lane >> 4) << 4));
    const uint32_t qrowb = (uint32_t)(w * 16) * AT_ROWB;

    for (int kt = 0; kt < nkt; kt++) {
        const uint32_t kb_ = kvB + (uint32_t)(kt & 1) * (4 * AT_KV_VB);
        if (kt + 1 < nkt) { issue(kt + 1, (kt + 1) & 1); CP_COMMIT(); CP_WAIT1(); }
        else              { CP_WAIT0(); }
        __syncthreads();

        float s[8][4];
#pragma unroll
        for (int j = 0; j < 8; j++)
#pragma unroll
            for (int c = 0; c < 4; c++) s[j][c] = 0.f;

#pragma unroll
        for (int kc = 0; kc < 8; kc++) {
            uint32_t aq[4], al4[4], kf[8][2];
            ldm_x4(aq[0], aq[1], aq[2], aq[3],  qhB + qrowb + kc * 32 + a_off);
            ldm_x4(al4[0], al4[1], al4[2], al4[3], qlB + qrowb + kc * 32 + a_off);
#pragma unroll
            for (int g8 = 0; g8 < 4; g8++)
                ldm_x4(kf[g8*2][0], kf[g8*2][1], kf[g8*2+1][0], kf[g8*2+1][1],
                       kb_ + (uint32_t)(g8 * 16) * AT_ROWB + kc * 32 + b_off);
#pragma unroll
            for (int j = 0; j < 8; j++) { mma_bf16(s[j], aq, kf[j]); mma_bf16(s[j], al4, kf[j]); }
#pragma unroll
            for (int g8 = 0; g8 < 4; g8++)
                ldm_x4(kf[g8*2][0], kf[g8*2][1], kf[g8*2+1][0], kf[g8*2+1][1],
                       kb_ + AT_KV_VB + (uint32_t)(g8 * 16) * AT_ROWB + kc * 32 + b_off);
#pragma unroll
            for (int j = 0; j < 8; j++) mma_bf16(s[j], aq, kf[j]);
        }

        if (kt * 64 + 63 > qt * 128 + w * 16) {
            int qr = qt * 128 + w * 16 + g;
#pragma unroll
            for (int j = 0; j < 8; j++) {
                int key = kt * 64 + j * 8 + tg * 2;
                if (key     > qr)     s[j][0] = -1e30f;
                if (key + 1 > qr)     s[j][1] = -1e30f;
                if (key     > qr + 8) s[j][2] = -1e30f;
                if (key + 1 > qr + 8) s[j][3] = -1e30f;
            }
        }

        float rm0 = s[0][0], rm1 = s[0][2];
#pragma unroll
        for (int j = 0; j < 8; j++) {
            rm0 = fmaxf(rm0, fmaxf(s[j][0], s[j][1]));
            rm1 = fmaxf(rm1, fmaxf(s[j][2], s[j][3]));
        }
        rm0 = fmaxf(rm0, __shfl_xor_sync(0xffffffffu, rm0, 1));
        rm0 = fmaxf(rm0, __shfl_xor_sync(0xffffffffu, rm0, 2));
        rm1 = fmaxf(rm1, __shfl_xor_sync(0xffffffffu, rm1, 1));
        rm1 = fmaxf(rm1, __shfl_xor_sync(0xffffffffu, rm1, 2));
        float mn0 = fmaxf(mi0, rm0), mn1 = fmaxf(mi1, rm1);
        float c0 = fast_exp(mi0 - mn0), c1 = fast_exp(mi1 - mn1);
        mi0 = mn0; mi1 = mn1;
        float sum0 = 0.f, sum1 = 0.f;
#pragma unroll
        for (int j = 0; j < 8; j++) {
            s[j][0] = fast_exp(s[j][0] - mn0); sum0 += s[j][0];
            s[j][1] = fast_exp(s[j][1] - mn0); sum0 += s[j][1];
            s[j][2] = fast_exp(s[j][2] - mn1); sum1 += s[j][2];
            s[j][3] = fast_exp(s[j][3] - mn1); sum1 += s[j][3];
        }
        sum0 += __shfl_xor_sync(0xffffffffu, sum0, 1);
        sum0 += __shfl_xor_sync(0xffffffffu, sum0, 2);
        sum1 += __shfl_xor_sync(0xffffffffu, sum1, 1);
        sum1 += __shfl_xor_sync(0xffffffffu, sum1, 2);
        li0 = li0 * c0 + sum0; li1 = li1 * c1 + sum1;
#pragma unroll
        for (int j = 0; j < 16; j++) {
            o[j][0] *= c0; o[j][1] *= c0; o[j][2] *= c1; o[j][3] *= c1;
        }

        uint32_t ph[4][4], pl[4][4];
#pragma unroll
        for (int kc = 0; kc < 4; kc++) {
            split_pack2(s[2*kc][0],   s[2*kc][1],   ph[kc][0], pl[kc][0]);
            split_pack2(s[2*kc][2],   s[2*kc][3],   ph[kc][1], pl[kc][1]);
            split_pack2(s[2*kc+1][0], s[2*kc+1][1], ph[kc][2], pl[kc][2]);
            split_pack2(s[2*kc+1][2], s[2*kc+1][3], ph[kc][3], pl[kc][3]);
        }

#pragma unroll
        for (int g8 = 0; g8 < 8; g8++) {
#pragma unroll
            for (int kc = 0; kc < 4; kc++) {
                uint32_t r0, r1, r2, r3;
                ldm_x4_t(r0, r1, r2, r3,
                         kb_ + 2 * AT_KV_VB + (uint32_t)(kc * 16) * AT_ROWB + g8 * 32 + v_off);
                uint32_t b0[2] = {r0, r1}, b1[2] = {r2, r3};
                mma_bf16(o[2*g8],   ph[kc], b0);
                mma_bf16(o[2*g8+1], ph[kc], b1);
                mma_bf16(o[2*g8],   pl[kc], b0);
                mma_bf16(o[2*g8+1], pl[kc], b1);
            }
#pragma unroll
            for (int kc = 0; kc < 4; kc++) {
                uint32_t r0, r1, r2, r3;
                ldm_x4_t(r0, r1, r2, r3,
                         kb_ + 3 * AT_KV_VB + (uint32_t)(kc * 16) * AT_ROWB + g8 * 32 + v_off);
                uint32_t b0[2] = {r0, r1}, b1[2] = {r2, r3};
                mma_bf16(o[2*g8],   ph[kc], b0);
                mma_bf16(o[2*g8+1], ph[kc], b1);
            }
        }
        __syncthreads();
    }

    float inv0 = 1.0f / li0, inv1 = 1.0f / li1;
    int row0 = qt * 128 + w * 16 + g;
    size_t base  = ((size_t)b * SEQ + row0) * D_MODEL + h * HEAD_DIM;
    size_t base8 = base + (size_t)8 * D_MODEL;
#pragma unroll
    for (int j = 0; j < 16; j++) {
        int col = j * 8 + tg * 2;
        uint32_t hi, lo;
        split_pack2(o[j][0] * inv0, o[j][1] * inv0, hi, lo);
        *(uint32_t*)(g_attnh + base + col) = hi;
        *(uint32_t*)(g_attnl + base + col) = lo;
        split_pack2(o[j][2] * inv1, o[j][3] * inv1, hi, lo);
        *(uint32_t*)(g_attnh + base8 + col) = hi;
        *(uint32_t*)(g_attnl + base8 + col) = lo;
    }
}

// ---------------- launch ---------------------------------------------------
extern "C" void kernel_launch(void* const* d_in, const int* in_sizes, int n_in,
                              void* d_out, int out_size) {
    const float* x    = (const float*)d_in[0];
    const float* Wqkv = (const float*)d_in[1];
    const float* Wout = (const float*)d_in[2];
    float* out = (float*)d_out;

    __nv_bfloat16 *xh, *xl, *wqh, *wql, *woh, *wol, *ah, *al;
    cudaGetSymbolAddress((void**)&xh,  g_xh);
    cudaGetSymbolAddress((void**)&xl,  g_xl);
    cudaGetSymbolAddress((void**)&wqh, g_wqkvh);
    cudaGetSymbolAddress((void**)&wql, g_wqkvl);
    cudaGetSymbolAddress((void**)&woh, g_wouth);
    cudaGetSymbolAddress((void**)&wol, g_woutl);
    cudaGetSymbolAddress((void**)&ah,  g_attnh);
    cudaGetSymbolAddress((void**)&al,  g_attnl);

    rope_table_kernel<<<(SEQ * 64 + 255) / 256, 256>>>();

    {   // fp32 -> bf16 hi/lo splits
        int n4x = M_TOTAL * D_MODEL / 4;
        split_kernel<<<(n4x + 255) / 256, 256>>>(x, xh, xl, n4x);
        int n4q = QKV_N * D_MODEL / 4;
        split_kernel<<<(n4q + 255) / 256, 256>>>(Wqkv, wqh, wql, n4q);
        int n4o = D_MODEL * D_MODEL / 4;
        split_kernel<<<(n4o + 255) / 256, 256>>>(Wout, woh, wol, n4o);
    }

    cudaFuncSetAttribute(mma_gemm<0>, cudaFuncAttributeMaxDynamicSharedMemorySize,
                         GEMM_SMEM_BYTES);
    cudaFuncSetAttribute(mma_gemm<1>, cudaFuncAttributeMaxDynamicSharedMemorySize,
                         GEMM_SMEM_BYTES);
    cudaFuncSetAttribute(attn_mma_kernel, cudaFuncAttributeMaxDynamicSharedMemorySize,
                         AT_SMEM);

    // QKV projection: fused clip+RoPE+scale+split-scatter
    mma_gemm<0><<<dim3(M_TOTAL / 128, QKV_N / 128), 256, GEMM_SMEM_BYTES>>>(
        xh, xl, wqh, wql, nullptr);

    // tensor-core flash attention
    attn_mma_kernel<<<dim3(SEQ / 128, BATCH * N_HEADS), 256, AT_SMEM>>>();

    // out projection
    mma_gemm<1><<<dim3(M_TOTAL / 128, D_MODEL / 128), 256, GEMM_SMEM_BYTES>>>(
        ah, al, woh, wol, out);
}

// round 6
// speedup vs baseline: 2.8049x; 1.0006x over previous
#include <cuda_runtime.h>
#include <cuda_bf16.h>
#include <math.h>
#include <stdint.h>

#define N_HEADS   32
#define KV_HEADS  8
#define HEAD_DIM  128
#define D_MODEL   4096
#define BATCH     2
#define SEQ       2048
#define M_TOTAL   (BATCH * SEQ)                          /* 4096 */
#define QKV_N     ((KV_HEADS * 2 + N_HEADS) * HEAD_DIM)  /* 6144 */
#define KDIM      4096

// ---------------- scratch (static device globals; no allocation) ----------
__device__ float g_cos[SEQ * 64];
__device__ float g_sin[SEQ * 64];

__device__ __align__(256) __nv_bfloat16 g_xh[(size_t)M_TOTAL * D_MODEL];
__device__ __align__(256) __nv_bfloat16 g_xl[(size_t)M_TOTAL * D_MODEL];
__device__ __align__(256) __nv_bfloat16 g_wqkvh[(size_t)QKV_N * D_MODEL];
__device__ __align__(256) __nv_bfloat16 g_wqkvl[(size_t)QKV_N * D_MODEL];
__device__ __align__(256) __nv_bfloat16 g_wouth[(size_t)D_MODEL * D_MODEL];
__device__ __align__(256) __nv_bfloat16 g_woutl[(size_t)D_MODEL * D_MODEL];
__device__ __align__(256) __nv_bfloat16 g_attnh[(size_t)M_TOTAL * D_MODEL];
__device__ __align__(256) __nv_bfloat16 g_attnl[(size_t)M_TOTAL * D_MODEL];

// q/k/v as bf16 hi/lo splits (q pre-scaled by 1/sqrt(HEAD_DIM))
__device__ __align__(256) __nv_bfloat16 g_qh[(size_t)BATCH * N_HEADS * SEQ * HEAD_DIM];
__device__ __align__(256) __nv_bfloat16 g_ql[(size_t)BATCH * N_HEADS * SEQ * HEAD_DIM];
__device__ __align__(256) __nv_bfloat16 g_kh[(size_t)BATCH * KV_HEADS * SEQ * HEAD_DIM];
__device__ __align__(256) __nv_bfloat16 g_kl[(size_t)BATCH * KV_HEADS * SEQ * HEAD_DIM];
__device__ __align__(256) __nv_bfloat16 g_vh[(size_t)BATCH * KV_HEADS * SEQ * HEAD_DIM];
__device__ __align__(256) __nv_bfloat16 g_vl[(size_t)BATCH * KV_HEADS * SEQ * HEAD_DIM];

// ====================== helpers (compute_103-safe) =========================
__device__ __forceinline__ uint32_t smem_u32(const void* p) {
    uint32_t a;
    asm("{ .reg .u64 t; cvta.to.shared.u64 t, %1; cvt.u32.u64 %0, t; }"
        : "=r"(a) : "l"(p));
    return a;
}

__device__ __forceinline__ void ldm_x4(uint32_t& r0, uint32_t& r1,
                                       uint32_t& r2, uint32_t& r3, uint32_t addr) {
    asm volatile("ldmatrix.sync.aligned.m8n8.x4.shared.b16 {%0,%1,%2,%3}, [%4];"
                 : "=r"(r0), "=r"(r1), "=r"(r2), "=r"(r3) : "r"(addr));
}
__device__ __forceinline__ void ldm_x4_t(uint32_t& r0, uint32_t& r1,
                                         uint32_t& r2, uint32_t& r3, uint32_t addr) {
    asm volatile("ldmatrix.sync.aligned.m8n8.x4.trans.shared.b16 {%0,%1,%2,%3}, [%4];"
                 : "=r"(r0), "=r"(r1), "=r"(r2), "=r"(r3) : "r"(addr));
}

__device__ __forceinline__ void mma_bf16(float* c, const uint32_t* a,
                                         const uint32_t* b) {
    asm volatile(
        "mma.sync.aligned.m16n8k16.row.col.f32.bf16.bf16.f32 "
        "{%0,%1,%2,%3}, {%4,%5,%6,%7}, {%8,%9}, {%0,%1,%2,%3};"
        : "+f"(c[0]), "+f"(c[1]), "+f"(c[2]), "+f"(c[3])
        : "r"(a[0]), "r"(a[1]), "r"(a[2]), "r"(a[3]), "r"(b[0]), "r"(b[1]));
}

#define CP_ASYNC16(dst, src) \
    asm volatile("cp.async.cg.shared.global [%0], [%1], 16;" \
                 :: "r"(dst), "l"(src) : "memory")
#define CP_COMMIT() asm volatile("cp.async.commit_group;" ::: "memory")
#define CP_WAIT2()  asm volatile("cp.async.wait_group 2;" ::: "memory")
#define CP_WAIT1()  asm volatile("cp.async.wait_group 1;" ::: "memory")
#define CP_WAIT0()  asm volatile("cp.async.wait_group 0;" ::: "memory")

// fast exp for x <= 0, relative error ~2.4e-6 (FMA pipe, no MUFU)
__device__ __forceinline__ float fast_exp(float x) {
    x = fmaxf(x, -80.0f);
    float y = x * 1.4426950408889634f;
    float z = y + 12582912.0f;
    int   ni = __float_as_int(z) - 0x4B400000;
    float f = y - (z - 12582912.0f);
    float p = 1.3333558146e-3f;
    p = fmaf(p, f, 9.6181291077e-3f);
    p = fmaf(p, f, 5.5504108664e-2f);
    p = fmaf(p, f, 2.4022650696e-1f);
    p = fmaf(p, f, 6.9314718056e-1f);
    p = fmaf(p, f, 1.0f);
    return p * __int_as_float((ni + 127) << 23);
}

__device__ __forceinline__ void split_pack2(float x, float y,
                                            uint32_t& hi, uint32_t& lo) {
    __nv_bfloat162 hh = __floats2bfloat162_rn(x, y);
    float2 hf = __bfloat1622float2(hh);
    __nv_bfloat162 ll = __floats2bfloat162_rn(x - hf.x, y - hf.y);
    hi = *(uint32_t*)&hh;
    lo = *(uint32_t*)&ll;
}

// ---------------- RoPE table (fp64 for exact trig) ------------------------
__global__ void rope_table_kernel() {
    int i = blockIdx.x * blockDim.x + threadIdx.x;
    if (i >= SEQ * 64) return;
    int l = i >> 6, d = i & 63;
    double inv = pow(500000.0, -((double)d) / 64.0);
    double ang = (double)l * inv;
    g_cos[i] = (float)cos(ang);
    g_sin[i] = (float)sin(ang);
}

// ---------------- fp32 -> bf16 hi/lo split ---------------------------------
__global__ __launch_bounds__(256) void split_kernel(
        const float* __restrict__ in, __nv_bfloat16* __restrict__ hi,
        __nv_bfloat16* __restrict__ lo, int n4) {
    int i = blockIdx.x * blockDim.x + threadIdx.x;
    if (i >= n4) return;
    float4 v = ((const float4*)in)[i];
    __nv_bfloat16 h[4], l[4];
    float vv[4] = {v.x, v.y, v.z, v.w};
#pragma unroll
    for (int j = 0; j < 4; j++) {
        h[j] = __float2bfloat16(vv[j]);
        l[j] = __float2bfloat16(vv[j] - __bfloat162float(h[j]));
    }
    ((uint2*)hi)[i] = *(uint2*)h;
    ((uint2*)lo)[i] = *(uint2*)l;
}

// ---------------- split-bf16 GEMM via mma.sync + cp.async pipeline --------
// C[128x128] per CTA = A @ B^T; K-chunk 32; 4 smem stages, 3 in flight.
#define ROWB   40                              /* bf16 elems per smem row */
#define VBYTES (128 * ROWB * 2)                /* 10240 per variant */
#define STAGEB (4 * VBYTES)                    /* 40960 per stage   */
#define NSTAGE 4
#define GEMM_SMEM_BYTES (NSTAGE * STAGEB + 1024)

template<int MODE>
__global__ __launch_bounds__(256) void mma_gemm(
        const __nv_bfloat16* __restrict__ Ah, const __nv_bfloat16* __restrict__ Al,
        const __nv_bfloat16* __restrict__ Bh, const __nv_bfloat16* __restrict__ Bl,
        float* __restrict__ outp) {
    extern __shared__ char smraw[];
    char* smp = (char*)(((uintptr_t)smraw + 1023) & ~(uintptr_t)1023);
    const uint32_t sbase = smem_u32(smp);

    const int tid = threadIdx.x;
    const int lane = tid & 31;
    const int wid = tid >> 5;
    const int warp_m = wid & 1;
    const int warp_n = wid >> 1;
    const int bm = blockIdx.x, bn = blockIdx.y;

    const size_t aoff = (size_t)(bm * 128) * KDIM;
    const size_t boff = (size_t)(bn * 128) * KDIM;
    const __nv_bfloat16* srcs[4] = {Ah, Al, Bh, Bl};
    const size_t roff[4] = {aoff, aoff, boff, boff};

    float acc[4][4][4];
#pragma unroll
    for (int i = 0; i < 4; i++)
#pragma unroll
        for (int j = 0; j < 4; j++)
#pragma unroll
            for (int c = 0; c < 4; c++) acc[i][j][c] = 0.f;

    // cp.async: 2048 16B-chunks per stage, 8 per thread
    auto issue = [&](int ic, int st) {
        uint32_t base = sbase + (uint32_t)st * STAGEB;
#pragma unroll
        for (int t = 0; t < 8; t++) {
            int idx = tid + t * 256;          // 0..2047
            int v = idx >> 9;                 // variant
            int r = (idx >> 2) & 127;         // row
            int c = idx & 3;                  // 16B chunk in row
            CP_ASYNC16(base + (uint32_t)(v * VBYTES + r * 80 + c * 16),
                       srcs[v] + roff[v] + (size_t)r * KDIM + ic * 32 + c * 8);
        }
    };

    const uint32_t a_lane_off =
        (uint32_t)((lane & 15) * 80 + ((lane >> 4) << 3) * 2);
    const uint32_t b_lane_off =
        (uint32_t)((((lane & 16) >> 1) + (lane & 7)) * 80 + (lane & 8) * 2);
    const int m0 = warp_m * 64;
    const int n0 = warp_n * 32;

    auto compute = [&](uint32_t sst) {
#pragma unroll
        for (int ks = 0; ks < 2; ks++) {
            const uint32_t k0b = ks * 32;
            uint32_t ah[4][4], al[4][4], bh[4][2], bl[4][2];
#pragma unroll
            for (int mi = 0; mi < 4; mi++) {
                ldm_x4(ah[mi][0], ah[mi][1], ah[mi][2], ah[mi][3],
                       sst + (uint32_t)((m0 + mi * 16) * 80) + a_lane_off + k0b);
                ldm_x4(al[mi][0], al[mi][1], al[mi][2], al[mi][3],
                       sst + VBYTES + (uint32_t)((m0 + mi * 16) * 80) + a_lane_off + k0b);
            }
#pragma unroll
            for (int p = 0; p < 2; p++) {
                uint32_t r0, r1, r2, r3;
                ldm_x4(r0, r1, r2, r3,
                       sst + 2 * VBYTES + (uint32_t)((n0 + p * 16) * 80) + b_lane_off + k0b);
                bh[p * 2][0] = r0; bh[p * 2][1] = r1;
                bh[p * 2 + 1][0] = r2; bh[p * 2 + 1][1] = r3;
                ldm_x4(r0, r1, r2, r3,
                       sst + 3 * VBYTES + (uint32_t)((n0 + p * 16) * 80) + b_lane_off + k0b);
                bl[p * 2][0] = r0; bl[p * 2][1] = r1;
                bl[p * 2 + 1][0] = r2; bl[p * 2 + 1][1] = r3;
            }
#pragma unroll
            for (int mi = 0; mi < 4; mi++)
#pragma unroll
                for (int ni = 0; ni < 4; ni++) {
                    mma_bf16(acc[mi][ni], ah[mi], bh[ni]);
                    mma_bf16(acc[mi][ni], al[mi], bh[ni]);
                    mma_bf16(acc[mi][ni], ah[mi], bl[ni]);
                }
        }
    };

    // prologue: 3 chunks in flight
    issue(0, 0); CP_COMMIT();
    issue(1, 1); CP_COMMIT();
    issue(2, 2); CP_COMMIT();

    for (int ic = 0; ic < 128; ic++) {
        if (ic <= 125)      CP_WAIT2();
        else if (ic == 126) CP_WAIT1();
        else                CP_WAIT0();
        __syncthreads();   // chunk ic visible to all; stage (ic+3)&3 free to refill
        if (ic + 3 < 128) { issue(ic + 3, (ic + 3) & 3); CP_COMMIT(); }
        compute(sbase + (uint32_t)(ic & 3) * STAGEB);
    }
    __syncthreads();

    // ---- epilogue ----
    float* ep = (float*)smp;                 // [128][136]
    const int g = lane >> 2, tg = lane & 3;
#pragma unroll
    for (int mi = 0; mi < 4; mi++)
#pragma unroll
        for (int ni = 0; ni < 4; ni++) {
            int row = m0 + mi * 16 + g;
            int col = n0 + ni * 8 + tg * 2;
            ep[row * 136 + col]       = acc[mi][ni][0];
            ep[row * 136 + col + 1]   = acc[mi][ni][1];
            ep[(row + 8) * 136 + col]     = acc[mi][ni][2];
            ep[(row + 8) * 136 + col + 1] = acc[mi][ni][3];
        }
    __syncthreads();

    for (int t = tid; t < 128 * 16; t += 256) {
        int row = t >> 4, j = t & 15;
        float4 v1 = *(const float4*)&ep[row * 136 + j * 4];
        float4 v2 = *(const float4*)&ep[row * 136 + 64 + j * 4];
        if (MODE == 0) {
            float* p1 = &v1.x; float* p2 = &v2.x;
#pragma unroll
            for (int e = 0; e < 4; e++) {
                p1[e] = fminf(fmaxf(p1[e], -8.0f), 8.0f);
                p2[e] = fminf(fmaxf(p2[e], -8.0f), 8.0f);
            }
            int m = bm * 128 + row;
            int bb = m >> 11, l = m & (SEQ - 1);
            if (bn < N_HEADS + KV_HEADS) {   // RoPE for q and k heads
#pragma unroll
                for (int e = 0; e < 4; e++) {
                    int d = j * 4 + e;
                    float c = g_cos[l * 64 + d];
                    float s = g_sin[l * 64 + d];
                    float x1 = p1[e], x2 = p2[e];
                    p1[e] = x1 * c - x2 * s;
                    p2[e] = x2 * c + x1 * s;
                }
            }
            float sc = 1.0f;
            __nv_bfloat16 *dhi, *dlo;
            size_t off;
            if (bn < N_HEADS) {
                sc = 0.08838834764831845f;   // fold 1/sqrt(128) into q
                off = ((size_t)(bb * N_HEADS + bn) * SEQ + l) * HEAD_DIM;
                dhi = g_qh; dlo = g_ql;
            } else if (bn < N_HEADS + KV_HEADS) {
                off = ((size_t)(bb * KV_HEADS + (bn - N_HEADS)) * SEQ + l) * HEAD_DIM;
                dhi = g_kh; dlo = g_kl;
            } else {
                off = ((size_t)(bb * KV_HEADS + (bn - N_HEADS - KV_HEADS)) * SEQ + l) * HEAD_DIM;
                dhi = g_vh; dlo = g_vl;
            }
            __nv_bfloat16 hb[8], lb[8];
            float vv[8] = {p1[0]*sc, p1[1]*sc, p1[2]*sc, p1[3]*sc,
                           p2[0]*sc, p2[1]*sc, p2[2]*sc, p2[3]*sc};
#pragma unroll
            for (int e = 0; e < 8; e++) {
                hb[e] = __float2bfloat16(vv[e]);
                lb[e] = __float2bfloat16(vv[e] - __bfloat162float(hb[e]));
            }
            *(uint2*)(dhi + off + j * 4)      = *(uint2*)hb;
            *(uint2*)(dlo + off + j * 4)      = *(uint2*)lb;
            *(uint2*)(dhi + off + 64 + j * 4) = *(uint2*)(hb + 4);
            *(uint2*)(dlo + off + 64 + j * 4) = *(uint2*)(lb + 4);
        } else {
            float* dst = outp + (size_t)(bm * 128 + row) * D_MODEL + bn * 128;
            *(float4*)(dst + j * 4) = v1;
            *(float4*)(dst + 64 + j * 4) = v2;
        }
    }
}

// ---------------- tensor-core flash attention ------------------------------
#define AT_STRIDE 136
#define AT_ROWB   (AT_STRIDE * 2)
#define AT_KV_VB  (64  * AT_ROWB)
#define AT_Q_VB   (128 * AT_ROWB)
#define AT_SMEM   (2 * AT_Q_VB + 8 * AT_KV_VB)

__global__ void __launch_bounds__(256, 1) attn_mma_kernel() {
    extern __shared__ char smp[];
    const uint32_t sb  = smem_u32(smp);
    const uint32_t qhB = sb, qlB = sb + AT_Q_VB;
    const uint32_t kvB = sb + 2 * AT_Q_VB;

    const int tid = threadIdx.x, lane = tid & 31, w = tid >> 5;
    const int g = lane >> 2, tg = lane & 3;
    const int qt = 15 - (int)blockIdx.x;
    const int bh = blockIdx.y;
    const int b = bh >> 5, h = bh & 31, kh = h >> 2;

    const __nv_bfloat16* Qhp = g_qh + ((size_t)(b * N_HEADS + h) * SEQ + qt * 128) * HEAD_DIM;
    const __nv_bfloat16* Qlp = g_ql + ((size_t)(b * N_HEADS + h) * SEQ + qt * 128) * HEAD_DIM;
    const __nv_bfloat16* Khp = g_kh + (size_t)(b * KV_HEADS + kh) * SEQ * HEAD_DIM;
    const __nv_bfloat16* Klp = g_kl + (size_t)(b * KV_HEADS + kh) * SEQ * HEAD_DIM;
    const __nv_bfloat16* Vhp = g_vh + (size_t)(b * KV_HEADS + kh) * SEQ * HEAD_DIM;
    const __nv_bfloat16* Vlp = g_vl + (size_t)(b * KV_HEADS + kh) * SEQ * HEAD_DIM;

    const int nkt = 2 * qt + 2;

    auto issue = [&](int kt, int st) {
        uint32_t base = kvB + (uint32_t)st * (4 * AT_KV_VB);
        const __nv_bfloat16* srcs[4] = {Khp, Klp, Vhp, Vlp};
#pragma unroll
        for (int v = 0; v < 4; v++) {
            const __nv_bfloat16* src = srcs[v] + (size_t)kt * 64 * HEAD_DIM;
#pragma unroll
            for (int t = 0; t < 4; t++) {
                int c = tid + t * 256;
                int row = c >> 4, cc = c & 15;
                CP_ASYNC16(base + (uint32_t)v * AT_KV_VB + row * AT_ROWB + cc * 16,
                           src + (size_t)row * HEAD_DIM + cc * 8);
            }
        }
    };

    issue(0, 0);
    CP_COMMIT();

    for (int i = tid; i < 128 * 16; i += 256) {
        int row = i >> 4, c = i & 15;
        *(uint4*)(smp + row * AT_ROWB + c * 16) =
            *(const uint4*)(Qhp + (size_t)row * HEAD_DIM + c * 8);
        *(uint4*)(smp + AT_Q_VB + row * AT_ROWB + c * 16) =
            *(const uint4*)(Qlp + (size_t)row * HEAD_DIM + c * 8);
    }
    __syncthreads();

    float o[16][4];
#pragma unroll
    for (int j = 0; j < 16; j++)
#pragma unroll
        for (int c = 0; c < 4; c++) o[j][c] = 0.f;
    float mi0 = -1e30f, mi1 = -1e30f, li0 = 0.f, li1 = 0.f;

    const uint32_t a_off = (uint32_t)((lane & 15) * AT_ROWB + ((lane >> 4) << 4));
    const uint32_t b_off = (uint32_t)((((lane & 16) >> 1) + (lane & 7)) * AT_ROWB + (lane & 8) * 2);
    const uint32_t v_off = (uint32_t)((lane & 15) * AT_ROWB + ((lane >> 4) << 4));
    const uint32_t qrowb = (uint32_t)(w * 16) * AT_ROWB;

    for (int kt = 0; kt < nkt; kt++) {
        const uint32_t kb_ = kvB + (uint32_t)(kt & 1) * (4 * AT_KV_VB);
        if (kt + 1 < nkt) { issue(kt + 1, (kt + 1) & 1); CP_COMMIT(); CP_WAIT1(); }
        else              { CP_WAIT0(); }
        __syncthreads();

        float s[8][4];
#pragma unroll
        for (int j = 0; j < 8; j++)
#pragma unroll
            for (int c = 0; c < 4; c++) s[j][c] = 0.f;

#pragma unroll
        for (int kc = 0; kc < 8; kc++) {
            uint32_t aq[4], al4[4], kf[8][2];
            ldm_x4(aq[0], aq[1], aq[2], aq[3],  qhB + qrowb + kc * 32 + a_off);
            ldm_x4(al4[0], al4[1], al4[2], al4[3], qlB + qrowb + kc * 32 + a_off);
#pragma unroll
            for (int g8 = 0; g8 < 4; g8++)
                ldm_x4(kf[g8*2][0], kf[g8*2][1], kf[g8*2+1][0], kf[g8*2+1][1],
                       kb_ + (uint32_t)(g8 * 16) * AT_ROWB + kc * 32 + b_off);
#pragma unroll
            for (int j = 0; j < 8; j++) { mma_bf16(s[j], aq, kf[j]); mma_bf16(s[j], al4, kf[j]); }
#pragma unroll
            for (int g8 = 0; g8 < 4; g8++)
                ldm_x4(kf[g8*2][0], kf[g8*2][1], kf[g8*2+1][0], kf[g8*2+1][1],
                       kb_ + AT_KV_VB + (uint32_t)(g8 * 16) * AT_ROWB + kc * 32 + b_off);
#pragma unroll
            for (int j = 0; j < 8; j++) mma_bf16(s[j], aq, kf[j]);
        }

        if (kt * 64 + 63 > qt * 128 + w * 16) {
            int qr = qt * 128 + w * 16 + g;
#pragma unroll
            for (int j = 0; j < 8; j++) {
                int key = kt * 64 + j * 8 + tg * 2;
                if (key     > qr)     s[j][0] = -1e30f;
                if (key + 1 > qr)     s[j][1] = -1e30f;
                if (key     > qr + 8) s[j][2] = -1e30f;
                if (key + 1 > qr + 8) s[j][3] = -1e30f;
            }
        }

        float rm0 = s[0][0], rm1 = s[0][2];
#pragma unroll
        for (int j = 0; j < 8; j++) {
            rm0 = fmaxf(rm0, fmaxf(s[j][0], s[j][1]));
            rm1 = fmaxf(rm1, fmaxf(s[j][2], s[j][3]));
        }
        rm0 = fmaxf(rm0, __shfl_xor_sync(0xffffffffu, rm0, 1));
        rm0 = fmaxf(rm0, __shfl_xor_sync(0xffffffffu, rm0, 2));
        rm1 = fmaxf(rm1, __shfl_xor_sync(0xffffffffu, rm1, 1));
        rm1 = fmaxf(rm1, __shfl_xor_sync(0xffffffffu, rm1, 2));
        float mn0 = fmaxf(mi0, rm0), mn1 = fmaxf(mi1, rm1);
        float c0 = fast_exp(mi0 - mn0), c1 = fast_exp(mi1 - mn1);
        mi0 = mn0; mi1 = mn1;
        float sum0 = 0.f, sum1 = 0.f;
#pragma unroll
        for (int j = 0; j < 8; j++) {
            s[j][0] = fast_exp(s[j][0] - mn0); sum0 += s[j][0];
            s[j][1] = fast_exp(s[j][1] - mn0); sum0 += s[j][1];
            s[j][2] = fast_exp(s[j][2] - mn1); sum1 += s[j][2];
            s[j][3] = fast_exp(s[j][3] - mn1); sum1 += s[j][3];
        }
        sum0 += __shfl_xor_sync(0xffffffffu, sum0, 1);
        sum0 += __shfl_xor_sync(0xffffffffu, sum0, 2);
        sum1 += __shfl_xor_sync(0xffffffffu, sum1, 1);
        sum1 += __shfl_xor_sync(0xffffffffu, sum1, 2);
        li0 = li0 * c0 + sum0; li1 = li1 * c1 + sum1;
#pragma unroll
        for (int j = 0; j < 16; j++) {
            o[j][0] *= c0; o[j][1] *= c0; o[j][2] *= c1; o[j][3] *= c1;
        }

        uint32_t ph[4][4], pl[4][4];
#pragma unroll
        for (int kc = 0; kc < 4; kc++) {
            split_pack2(s[2*kc][0],   s[2*kc][1],   ph[kc][0], pl[kc][0]);
            split_pack2(s[2*kc][2],   s[2*kc][3],   ph[kc][1], pl[kc][1]);
            split_pack2(s[2*kc+1][0], s[2*kc+1][1], ph[kc][2], pl[kc][2]);
            split_pack2(s[2*kc+1][2], s[2*kc+1][3], ph[kc][3], pl[kc][3]);
        }

#pragma unroll
        for (int g8 = 0; g8 < 8; g8++) {
#pragma unroll
            for (int kc = 0; kc < 4; kc++) {
                uint32_t r0, r1, r2, r3;
                ldm_x4_t(r0, r1, r2, r3,
                         kb_ + 2 * AT_KV_VB + (uint32_t)(kc * 16) * AT_ROWB + g8 * 32 + v_off);
                uint32_t b0[2] = {r0, r1}, b1[2] = {r2, r3};
                mma_bf16(o[2*g8],   ph[kc], b0);
                mma_bf16(o[2*g8+1], ph[kc], b1);
                mma_bf16(o[2*g8],   pl[kc], b0);
                mma_bf16(o[2*g8+1], pl[kc], b1);
            }
#pragma unroll
            for (int kc = 0; kc < 4; kc++) {
                uint32_t r0, r1, r2, r3;
                ldm_x4_t(r0, r1, r2, r3,
                         kb_ + 3 * AT_KV_VB + (uint32_t)(kc * 16) * AT_ROWB + g8 * 32 + v_off);
                uint32_t b0[2] = {r0, r1}, b1[2] = {r2, r3};
                mma_bf16(o[2*g8],   ph[kc], b0);
                mma_bf16(o[2*g8+1], ph[kc], b1);
            }
        }
        __syncthreads();
    }

    float inv0 = 1.0f / li0, inv1 = 1.0f / li1;
    int row0 = qt * 128 + w * 16 + g;
    size_t base  = ((size_t)b * SEQ + row0) * D_MODEL + h * HEAD_DIM;
    size_t base8 = base + (size_t)8 * D_MODEL;
#pragma unroll
    for (int j = 0; j < 16; j++) {
        int col = j * 8 + tg * 2;
        uint32_t hi, lo;
        split_pack2(o[j][0] * inv0, o[j][1] * inv0, hi, lo);
        *(uint32_t*)(g_attnh + base + col) = hi;
        *(uint32_t*)(g_attnl + base + col) = lo;
        split_pack2(o[j][2] * inv1, o[j][3] * inv1, hi, lo);
        *(uint32_t*)(g_attnh + base8 + col) = hi;
        *(uint32_t*)(g_attnl + base8 + col) = lo;
    }
}

// ---------------- launch ---------------------------------------------------
extern "C" void kernel_launch(void* const* d_in, const int* in_sizes, int n_in,
                              void* d_out, int out_size) {
    const float* x    = (const float*)d_in[0];
    const float* Wqkv = (const float*)d_in[1];
    const float* Wout = (const float*)d_in[2];
    float* out = (float*)d_out;

    __nv_bfloat16 *xh, *xl, *wqh, *wql, *woh, *wol, *ah, *al;
    cudaGetSymbolAddress((void**)&xh,  g_xh);
    cudaGetSymbolAddress((void**)&xl,  g_xl);
    cudaGetSymbolAddress((void**)&wqh, g_wqkvh);
    cudaGetSymbolAddress((void**)&wql, g_wqkvl);
    cudaGetSymbolAddress((void**)&woh, g_wouth);
    cudaGetSymbolAddress((void**)&wol, g_woutl);
    cudaGetSymbolAddress((void**)&ah,  g_attnh);
    cudaGetSymbolAddress((void**)&al,  g_attnl);

    rope_table_kernel<<<(SEQ * 64 + 255) / 256, 256>>>();

    {   // fp32 -> bf16 hi/lo splits
        int n4x = M_TOTAL * D_MODEL / 4;
        split_kernel<<<(n4x + 255) / 256, 256>>>(x, xh, xl, n4x);
        int n4q = QKV_N * D_MODEL / 4;
        split_kernel<<<(n4q + 255) / 256, 256>>>(Wqkv, wqh, wql, n4q);
        int n4o = D_MODEL * D_MODEL / 4;
        split_kernel<<<(n4o + 255) / 256, 256>>>(Wout, woh, wol, n4o);
    }

    cudaFuncSetAttribute(mma_gemm<0>, cudaFuncAttributeMaxDynamicSharedMemorySize,
                         GEMM_SMEM_BYTES);
    cudaFuncSetAttribute(mma_gemm<1>, cudaFuncAttributeMaxDynamicSharedMemorySize,
                         GEMM_SMEM_BYTES);
    cudaFuncSetAttribute(attn_mma_kernel, cudaFuncAttributeMaxDynamicSharedMemorySize,
                         AT_SMEM);

    // QKV projection: fused clip+RoPE+scale+split-scatter
    mma_gemm<0><<<dim3(M_TOTAL / 128, QKV_N / 128), 256, GEMM_SMEM_BYTES>>>(
        xh, xl, wqh, wql, nullptr);

    // tensor-core flash attention
    attn_mma_kernel<<<dim3(SEQ / 128, BATCH * N_HEADS), 256, AT_SMEM>>>();

    // out projection
    mma_gemm<1><<<dim3(M_TOTAL / 128, D_MODEL / 128), 256, GEMM_SMEM_BYTES>>>(
        ah, al, woh, wol, out);
}

// round 8
// speedup vs baseline: 2.8056x; 1.0003x over previous
#include <cuda_runtime.h>
#include <cuda_bf16.h>
#include <math.h>
#include <stdint.h>

#define N_HEADS   32
#define KV_HEADS  8
#define HEAD_DIM  128
#define D_MODEL   4096
#define BATCH     2
#define SEQ       2048
#define M_TOTAL   (BATCH * SEQ)
#define QKV_N     ((KV_HEADS * 2 + N_HEADS) * HEAD_DIM)
#define KDIM      4096

__device__ float g_cos[SEQ * 64];
__device__ float g_sin[SEQ * 64];

__device__ __align__(256) __nv_bfloat16 g_xh[(size_t)M_TOTAL * D_MODEL];
__device__ __align__(256) __nv_bfloat16 g_xl[(size_t)M_TOTAL * D_MODEL];
__device__ __align__(256) __nv_bfloat16 g_wqkvh[(size_t)QKV_N * D_MODEL];
__device__ __align__(256) __nv_bfloat16 g_wqkvl[(size_t)QKV_N * D_MODEL];
__device__ __align__(256) __nv_bfloat16 g_wouth[(size_t)D_MODEL * D_MODEL];
__device__ __align__(256) __nv_bfloat16 g_woutl[(size_t)D_MODEL * D_MODEL];
__device__ __align__(256) __nv_bfloat16 g_attnh[(size_t)M_TOTAL * D_MODEL];
__device__ __align__(256) __nv_bfloat16 g_attnl[(size_t)M_TOTAL * D_MODEL];

__device__ __align__(256) __nv_bfloat16 g_qh[(size_t)BATCH * N_HEADS * SEQ * HEAD_DIM];
__device__ __align__(256) __nv_bfloat16 g_ql[(size_t)BATCH * N_HEADS * SEQ * HEAD_DIM];
__device__ __align__(256) __nv_bfloat16 g_kh[(size_t)BATCH * KV_HEADS * SEQ * HEAD_DIM];
__device__ __align__(256) __nv_bfloat16 g_kl[(size_t)BATCH * KV_HEADS * SEQ * HEAD_DIM];
__device__ __align__(256) __nv_bfloat16 g_vh[(size_t)BATCH * KV_HEADS * SEQ * HEAD_DIM];
__device__ __align__(256) __nv_bfloat16 g_vl[(size_t)BATCH * KV_HEADS * SEQ * HEAD_DIM];

__device__ __forceinline__ uint32_t smem_u32(const void* p) {
    uint32_t a;
    asm("{ .reg .u64 t; cvta.to.shared.u64 t, %1; cvt.u32.u64 %0, t; }"
        : "=r"(a) : "l"(p));
    return a;
}
__device__ __forceinline__ void ldm_x4(uint32_t& r0, uint32_t& r1,
                                       uint32_t& r2, uint32_t& r3, uint32_t addr) {
    asm volatile("ldmatrix.sync.aligned.m8n8.x4.shared.b16 {%0,%1,%2,%3}, [%4];"
                 : "=r"(r0), "=r"(r1), "=r"(r2), "=r"(r3) : "r"(addr));
}
__device__ __forceinline__ void ldm_x4_t(uint32_t& r0, uint32_t& r1,
                                         uint32_t& r2, uint32_t& r3, uint32_t addr) {
    asm volatile("ldmatrix.sync.aligned.m8n8.x4.trans.shared.b16 {%0,%1,%2,%3}, [%4];"
                 : "=r"(r0), "=r"(r1), "=r"(r2), "=r"(r3) : "r"(addr));
}
__device__ __forceinline__ void mma_bf16(float* c, const uint32_t* a,
                                         const uint32_t* b) {
    asm volatile(
        "mma.sync.aligned.m16n8k16.row.col.f32.bf16.bf16.f32 "
        "{%0,%1,%2,%3}, {%4,%5,%6,%7}, {%8,%9}, {%0,%1,%2,%3};"
        : "+f"(c[0]), "+f"(c[1]), "+f"(c[2]), "+f"(c[3])
        : "r"(a[0]), "r"(a[1]), "r"(a[2]), "r"(a[3]), "r"(b[0]), "r"(b[1]));
}
#define CP_ASYNC16(dst, src) \
    asm volatile("cp.async.cg.shared.global [%0], [%1], 16;" \
                 :: "r"(dst), "l"(src) : "memory")
#define CP_COMMIT() asm volatile("cp.async.commit_group;" ::: "memory")
#define CP_WAIT2()  asm volatile("cp.async.wait_group 2;" ::: "memory")
#define CP_WAIT1()  asm volatile("cp.async.wait_group 1;" ::: "memory")
#define CP_WAIT0()  asm volatile("cp.async.wait_group 0;" ::: "memory")

__device__ __forceinline__ float fast_exp(float x) {
    x = fmaxf(x, -80.0f);
    float y = x * 1.4426950408889634f;
    float z = y + 12582912.0f;
    int   ni = __float_as_int(z) - 0x4B400000;
    float f = y - (z - 12582912.0f);
    float p = 1.3333558146e-3f;
    p = fmaf(p, f, 9.6181291077e-3f);
    p = fmaf(p, f, 5.5504108664e-2f);
    p = fmaf(p, f, 2.4022650696e-1f);
    p = fmaf(p, f, 6.9314718056e-1f);
    p = fmaf(p, f, 1.0f);
    return p * __int_as_float((ni + 127) << 23);
}
__device__ __forceinline__ void split_pack2(float x, float y,
                                            uint32_t& hi, uint32_t& lo) {
    __nv_bfloat162 hh = __floats2bfloat162_rn(x, y);
    float2 hf = __bfloat1622float2(hh);
    __nv_bfloat162 ll = __floats2bfloat162_rn(x - hf.x, y - hf.y);
    hi = *(uint32_t*)&hh;
    lo = *(uint32_t*)&ll;
}

__global__ void rope_table_kernel() {
    int i = blockIdx.x * blockDim.x + threadIdx.x;
    if (i >= SEQ * 64) return;
    int l = i >> 6, d = i & 63;
    double inv = pow(500000.0, -((double)d) / 64.0);
    double ang = (double)l * inv;
    g_cos[i] = (float)cos(ang);
    g_sin[i] = (float)sin(ang);
}

__global__ __launch_bounds__(256) void split_kernel(
        const float* __restrict__ in, __nv_bfloat16* __restrict__ hi,
        __nv_bfloat16* __restrict__ lo, int n4) {
    int i = blockIdx.x * blockDim.x + threadIdx.x;
    if (i >= n4) return;
    float4 v = ((const float4*)in)[i];
    __nv_bfloat16 h[4], l[4];
    float vv[4] = {v.x, v.y, v.z, v.w};
#pragma unroll
    for (int j = 0; j < 4; j++) {
        h[j] = __float2bfloat16(vv[j]);
        l[j] = __float2bfloat16(vv[j] - __bfloat162float(h[j]));
    }
    ((uint2*)hi)[i] = *(uint2*)h;
    ((uint2*)lo)[i] = *(uint2*)l;
}

// ---------------- split-bf16 GEMM (unchanged from R5) ----------------------
#define ROWB   40
#define VBYTES (128 * ROWB * 2)
#define STAGEB (4 * VBYTES)
#define NSTAGE 4
#define GEMM_SMEM_BYTES (NSTAGE * STAGEB + 1024)

template<int MODE>
__global__ __launch_bounds__(256) void mma_gemm(
        const __nv_bfloat16* __restrict__ Ah, const __nv_bfloat16* __restrict__ Al,
        const __nv_bfloat16* __restrict__ Bh, const __nv_bfloat16* __restrict__ Bl,
        float* __restrict__ outp) {
    extern __shared__ char smraw[];
    char* smp = (char*)(((uintptr_t)smraw + 1023) & ~(uintptr_t)1023);
    const uint32_t sbase = smem_u32(smp);

    const int tid = threadIdx.x;
    const int lane = tid & 31;
    const int wid = tid >> 5;
    const int warp_m = wid & 1;
    const int warp_n = wid >> 1;
    const int bm = blockIdx.x, bn = blockIdx.y;

    const size_t aoff = (size_t)(bm * 128) * KDIM;
    const size_t boff = (size_t)(bn * 128) * KDIM;
    const __nv_bfloat16* srcs[4] = {Ah, Al, Bh, Bl};
    const size_t roff[4] = {aoff, aoff, boff, boff};

    float acc[4][4][4];
#pragma unroll
    for (int i = 0; i < 4; i++)
#pragma unroll
        for (int j = 0; j < 4; j++)
#pragma unroll
            for (int c = 0; c < 4; c++) acc[i][j][c] = 0.f;

    auto issue = [&](int ic, int st) {
        uint32_t base = sbase + (uint32_t)st * STAGEB;
#pragma unroll
        for (int t = 0; t < 8; t++) {
            int idx = tid + t * 256;
            int v = idx >> 9;
            int r = (idx >> 2) & 127;
            int c = idx & 3;
            CP_ASYNC16(base + (uint32_t)(v * VBYTES + r * 80 + c * 16),
                       srcs[v] + roff[v] + (size_t)r * KDIM + ic * 32 + c * 8);
        }
    };

    const uint32_t a_lane_off =
        (uint32_t)((lane & 15) * 80 + ((lane >> 4) << 3) * 2);
    const uint32_t b_lane_off =
        (uint32_t)((((lane & 16) >> 1) + (lane & 7)) * 80 + (lane & 8) * 2);
    const int m0 = warp_m * 64;
    const int n0 = warp_n * 32;

    auto compute = [&](uint32_t sst) {
#pragma unroll
        for (int ks = 0; ks < 2; ks++) {
            const uint32_t k0b = ks * 32;
            uint32_t ah[4][4], al[4][4], bh[4][2], bl[4][2];
#pragma unroll
            for (int mi = 0; mi < 4; mi++) {
                ldm_x4(ah[mi][0], ah[mi][1], ah[mi][2], ah[mi][3],
                       sst + (uint32_t)((m0 + mi * 16) * 80) + a_lane_off + k0b);
                ldm_x4(al[mi][0], al[mi][1], al[mi][2], al[mi][3],
                       sst + VBYTES + (uint32_t)((m0 + mi * 16) * 80) + a_lane_off + k0b);
            }
#pragma unroll
            for (int p = 0; p < 2; p++) {
                uint32_t r0, r1, r2, r3;
                ldm_x4(r0, r1, r2, r3,
                       sst + 2 * VBYTES + (uint32_t)((n0 + p * 16) * 80) + b_lane_off + k0b);
                bh[p * 2][0] = r0; bh[p * 2][1] = r1;
                bh[p * 2 + 1][0] = r2; bh[p * 2 + 1][1] = r3;
                ldm_x4(r0, r1, r2, r3,
                       sst + 3 * VBYTES + (uint32_t)((n0 + p * 16) * 80) + b_lane_off + k0b);
                bl[p * 2][0] = r0; bl[p * 2][1] = r1;
                bl[p * 2 + 1][0] = r2; bl[p * 2 + 1][1] = r3;
            }
#pragma unroll
            for (int mi = 0; mi < 4; mi++)
#pragma unroll
                for (int ni = 0; ni < 4; ni++) {
                    mma_bf16(acc[mi][ni], ah[mi], bh[ni]);
                    mma_bf16(acc[mi][ni], al[mi], bh[ni]);
                    mma_bf16(acc[mi][ni], ah[mi], bl[ni]);
                }
        }
    };

    issue(0, 0); CP_COMMIT();
    issue(1, 1); CP_COMMIT();
    issue(2, 2); CP_COMMIT();

    for (int ic = 0; ic < 128; ic++) {
        if (ic <= 125)      CP_WAIT2();
        else if (ic == 126) CP_WAIT1();
        else                CP_WAIT0();
        __syncthreads();
        if (ic + 3 < 128) { issue(ic + 3, (ic + 3) & 3); CP_COMMIT(); }
        compute(sbase + (uint32_t)(ic & 3) * STAGEB);
    }
    __syncthreads();

    float* ep = (float*)smp;
    const int g = lane >> 2, tg = lane & 3;
#pragma unroll
    for (int mi = 0; mi < 4; mi++)
#pragma unroll
        for (int ni = 0; ni < 4; ni++) {
            int row = m0 + mi * 16 + g;
            int col = n0 + ni * 8 + tg * 2;
            ep[row * 136 + col]       = acc[mi][ni][0];
            ep[row * 136 + col + 1]   = acc[mi][ni][1];
            ep[(row + 8) * 136 + col]     = acc[mi][ni][2];
            ep[(row + 8) * 136 + col + 1] = acc[mi][ni][3];
        }
    __syncthreads();

    for (int t = tid; t < 128 * 16; t += 256) {
        int row = t >> 4, j = t & 15;
        float4 v1 = *(const float4*)&ep[row * 136 + j * 4];
        float4 v2 = *(const float4*)&ep[row * 136 + 64 + j * 4];
        if (MODE == 0) {
            float* p1 = &v1.x; float* p2 = &v2.x;
#pragma unroll
            for (int e = 0; e < 4; e++) {
                p1[e] = fminf(fmaxf(p1[e], -8.0f), 8.0f);
                p2[e] = fminf(fmaxf(p2[e], -8.0f), 8.0f);
            }
            int m = bm * 128 + row;
            int bb = m >> 11, l = m & (SEQ - 1);
            if (bn < N_HEADS + KV_HEADS) {
#pragma unroll
                for (int e = 0; e < 4; e++) {
                    int d = j * 4 + e;
                    float c = g_cos[l * 64 + d];
                    float s = g_sin[l * 64 + d];
                    float x1 = p1[e], x2 = p2[e];
                    p1[e] = x1 * c - x2 * s;
                    p2[e] = x2 * c + x1 * s;
                }
            }
            float sc = 1.0f;
            __nv_bfloat16 *dhi, *dlo;
            size_t off;
            if (bn < N_HEADS) {
                sc = 0.08838834764831845f;
                off = ((size_t)(bb * N_HEADS + bn) * SEQ + l) * HEAD_DIM;
                dhi = g_qh; dlo = g_ql;
            } else if (bn < N_HEADS + KV_HEADS) {
                off = ((size_t)(bb * KV_HEADS + (bn - N_HEADS)) * SEQ + l) * HEAD_DIM;
                dhi = g_kh; dlo = g_kl;
            } else {
                off = ((size_t)(bb * KV_HEADS + (bn - N_HEADS - KV_HEADS)) * SEQ + l) * HEAD_DIM;
                dhi = g_vh; dlo = g_vl;
            }
            __nv_bfloat16 hb[8], lb[8];
            float vv[8] = {p1[0]*sc, p1[1]*sc, p1[2]*sc, p1[3]*sc,
                           p2[0]*sc, p2[1]*sc, p2[2]*sc, p2[3]*sc};
#pragma unroll
            for (int e = 0; e < 8; e++) {
                hb[e] = __float2bfloat16(vv[e]);
                lb[e] = __float2bfloat16(vv[e] - __bfloat162float(hb[e]));
            }
            *(uint2*)(dhi + off + j * 4)      = *(uint2*)hb;
            *(uint2*)(dlo + off + j * 4)      = *(uint2*)lb;
            *(uint2*)(dhi + off + 64 + j * 4) = *(uint2*)(hb + 4);
            *(uint2*)(dlo + off + 64 + j * 4) = *(uint2*)(lb + 4);
        } else {
            float* dst = outp + (size_t)(bm * 128 + row) * D_MODEL + bn * 128;
            *(float4*)(dst + j * 4) = v1;
            *(float4*)(dst + 64 + j * 4) = v2;
        }
    }
}

// ---------------- flash attention v2: Q in regs, 3-stage ring, 1 barrier ---
#define AT_ROWB   272                      /* 136 bf16 per row */
#define AT_KV_VB  (64 * AT_ROWB)           /* 17408 */
#define AT_STG    (4 * AT_KV_VB)           /* 69632 */
#define AT_SMEM   (3 * AT_STG)             /* 208896 */

__global__ void __launch_bounds__(256, 1) attn_mma_kernel() {
    extern __shared__ char smp[];
    const uint32_t kvB = smem_u32(smp);

    const int tid = threadIdx.x, lane = tid & 31, w = tid >> 5;
    const int g = lane >> 2, tg = lane & 3;
    const int qt = 15 - (int)blockIdx.x;
    const int bh = blockIdx.y;
    const int b = bh >> 5, h = bh & 31, kh = h >> 2;

    const __nv_bfloat16* Qhp = g_qh + ((size_t)(b * N_HEADS + h) * SEQ + qt * 128) * HEAD_DIM;
    const __nv_bfloat16* Qlp = g_ql + ((size_t)(b * N_HEADS + h) * SEQ + qt * 128) * HEAD_DIM;
    const __nv_bfloat16* Khp = g_kh + (size_t)(b * KV_HEADS + kh) * SEQ * HEAD_DIM;
    const __nv_bfloat16* Klp = g_kl + (size_t)(b * KV_HEADS + kh) * SEQ * HEAD_DIM;
    const __nv_bfloat16* Vhp = g_vh + (size_t)(b * KV_HEADS + kh) * SEQ * HEAD_DIM;
    const __nv_bfloat16* Vlp = g_vl + (size_t)(b * KV_HEADS + kh) * SEQ * HEAD_DIM;

    const int nkt = 2 * qt + 2;

    auto issue = [&](int kt, int st) {
        uint32_t base = kvB + (uint32_t)st * AT_STG;
        const __nv_bfloat16* srcs[4] = {Khp, Klp, Vhp, Vlp};
#pragma unroll
        for (int v = 0; v < 4; v++) {
            const __nv_bfloat16* src = srcs[v] + (size_t)kt * 64 * HEAD_DIM;
#pragma unroll
            for (int t = 0; t < 4; t++) {
                int c = tid + t * 256;
                int row = c >> 4, cc = c & 15;
                CP_ASYNC16(base + (uint32_t)v * AT_KV_VB + row * AT_ROWB + cc * 16,
                           src + (size_t)row * HEAD_DIM + cc * 8);
            }
        }
    };

    issue(0, 0); CP_COMMIT();
    issue(1, 1); CP_COMMIT();

    // Q fragments -> registers (m16n8k16 A layout), loaded once
    uint32_t aqh[8][4], aql[8][4];
    {
        const int r0 = w * 16 + (lane >> 2);
        const int cb = (lane & 3) * 2;
        const __nv_bfloat16* qa = Qhp + (size_t)r0 * HEAD_DIM;
        const __nv_bfloat16* qb = qa + 8 * HEAD_DIM;
        const __nv_bfloat16* la = Qlp + (size_t)r0 * HEAD_DIM;
        const __nv_bfloat16* lb = la + 8 * HEAD_DIM;
#pragma unroll
        for (int kc = 0; kc < 8; kc++) {
            int c0 = kc * 16 + cb, c1 = c0 + 8;
            aqh[kc][0] = *(const uint32_t*)(qa + c0);
            aqh[kc][1] = *(const uint32_t*)(qb + c0);
            aqh[kc][2] = *(const uint32_t*)(qa + c1);
            aqh[kc][3] = *(const uint32_t*)(qb + c1);
            aql[kc][0] = *(const uint32_t*)(la + c0);
            aql[kc][1] = *(const uint32_t*)(lb + c0);
            aql[kc][2] = *(const uint32_t*)(la + c1);
            aql[kc][3] = *(const uint32_t*)(lb + c1);
        }
    }

    float o[16][4];
#pragma unroll
    for (int j = 0; j < 16; j++)
#pragma unroll
        for (int c = 0; c < 4; c++) o[j][c] = 0.f;
    float mi0 = -1e30f, mi1 = -1e30f, li0 = 0.f, li1 = 0.f;

    const uint32_t b_off = (uint32_t)((((lane & 16) >> 1) + (lane & 7)) * AT_ROWB + (lane & 8) * 2);
    const uint32_t v_off = (uint32_t)((lane & 15) * AT_ROWB + ((lane >> 4) << 4));

    auto computeS = [&](int kt, float s[8][4]) {
        const uint32_t kb_ = kvB + (uint32_t)(kt % 3) * AT_STG;
#pragma unroll
        for (int j = 0; j < 8; j++)
#pragma unroll
            for (int c = 0; c < 4; c++) s[j][c] = 0.f;
#pragma unroll
        for (int kc = 0; kc < 8; kc++) {
            uint32_t kf[8][2];
#pragma unroll
            for (int g8 = 0; g8 < 4; g8++)
                ldm_x4(kf[g8*2][0], kf[g8*2][1], kf[g8*2+1][0], kf[g8*2+1][1],
                       kb_ + (uint32_t)(g8 * 16) * AT_ROWB + kc * 32 + b_off);
#pragma unroll
            for (int j = 0; j < 8; j++) { mma_bf16(s[j], aqh[kc], kf[j]); mma_bf16(s[j], aql[kc], kf[j]); }
#pragma unroll
            for (int g8 = 0; g8 < 4; g8++)
                ldm_x4(kf[g8*2][0], kf[g8*2][1], kf[g8*2+1][0], kf[g8*2+1][1],
                       kb_ + AT_KV_VB + (uint32_t)(g8 * 16) * AT_ROWB + kc * 32 + b_off);
#pragma unroll
            for (int j = 0; j < 8; j++) mma_bf16(s[j], aqh[kc], kf[j]);
        }
        if (kt * 64 + 63 > qt * 128 + w * 16) {
            int qr = qt * 128 + w * 16 + g;
#pragma unroll
            for (int j = 0; j < 8; j++) {
                int key = kt * 64 + j * 8 + tg * 2;
                if (key     > qr)     s[j][0] = -1e30f;
                if (key + 1 > qr)     s[j][1] = -1e30f;
                if (key     > qr + 8) s[j][2] = -1e30f;
                if (key + 1 > qr + 8) s[j][3] = -1e30f;
            }
        }
    };

    float s[8][4], s_nxt[8][4];
    CP_WAIT1();            // tile 0 resident (tile 1 still flying)
    __syncthreads();
    computeS(0, s);

    for (int t = 0; t < nkt; t++) {
        if (t + 1 < nkt) {
            CP_WAIT0();    // tile t+1 resident
            __syncthreads();   // all warps past PV(t-1): stage (t+2)%3 reusable
            if (t + 2 < nkt) { issue(t + 2, (t + 2) % 3); CP_COMMIT(); }
            computeS(t + 1, s_nxt);   // tensor work ahead of softmax(t)
        }

        // ---- softmax(t) ----
        float rm0 = s[0][0], rm1 = s[0][2];
#pragma unroll
        for (int j = 0; j < 8; j++) {
            rm0 = fmaxf(rm0, fmaxf(s[j][0], s[j][1]));
            rm1 = fmaxf(rm1, fmaxf(s[j][2], s[j][3]));
        }
        rm0 = fmaxf(rm0, __shfl_xor_sync(0xffffffffu, rm0, 1));
        rm0 = fmaxf(rm0, __shfl_xor_sync(0xffffffffu, rm0, 2));
        rm1 = fmaxf(rm1, __shfl_xor_sync(0xffffffffu, rm1, 1));
        rm1 = fmaxf(rm1, __shfl_xor_sync(0xffffffffu, rm1, 2));
        float mn0 = fmaxf(mi0, rm0), mn1 = fmaxf(mi1, rm1);
        float c0 = fast_exp(mi0 - mn0), c1 = fast_exp(mi1 - mn1);
        mi0 = mn0; mi1 = mn1;
        float sum0 = 0.f, sum1 = 0.f;
#pragma unroll
        for (int j = 0; j < 8; j++) {
            s[j][0] = fast_exp(s[j][0] - mn0); sum0 += s[j][0];
            s[j][1] = fast_exp(s[j][1] - mn0); sum0 += s[j][1];
            s[j][2] = fast_exp(s[j][2] - mn1); sum1 += s[j][2];
            s[j][3] = fast_exp(s[j][3] - mn1); sum1 += s[j][3];
        }
        sum0 += __shfl_xor_sync(0xffffffffu, sum0, 1);
        sum0 += __shfl_xor_sync(0xffffffffu, sum0, 2);
        sum1 += __shfl_xor_sync(0xffffffffu, sum1, 1);
        sum1 += __shfl_xor_sync(0xffffffffu, sum1, 2);
        li0 = li0 * c0 + sum0; li1 = li1 * c1 + sum1;
#pragma unroll
        for (int j = 0; j < 16; j++) {
            o[j][0] *= c0; o[j][1] *= c0; o[j][2] *= c1; o[j][3] *= c1;
        }

        uint32_t ph[4][4], pl[4][4];
#pragma unroll
        for (int kc = 0; kc < 4; kc++) {
            split_pack2(s[2*kc][0],   s[2*kc][1],   ph[kc][0], pl[kc][0]);
            split_pack2(s[2*kc][2],   s[2*kc][3],   ph[kc][1], pl[kc][1]);
            split_pack2(s[2*kc+1][0], s[2*kc+1][1], ph[kc][2], pl[kc][2]);
            split_pack2(s[2*kc+1][2], s[2*kc+1][3], ph[kc][3], pl[kc][3]);
        }

        // ---- O += P @ V(t) ----
        const uint32_t vb_ = kvB + (uint32_t)(t % 3) * AT_STG + 2 * AT_KV_VB;
#pragma unroll
        for (int g8 = 0; g8 < 8; g8++) {
#pragma unroll
            for (int kc = 0; kc < 4; kc++) {
                uint32_t r0, r1, r2, r3;
                ldm_x4_t(r0, r1, r2, r3,
                         vb_ + (uint32_t)(kc * 16) * AT_ROWB + g8 * 32 + v_off);
                uint32_t b0[2] = {r0, r1}, b1[2] = {r2, r3};
                mma_bf16(o[2*g8],   ph[kc], b0);
                mma_bf16(o[2*g8+1], ph[kc], b1);
                mma_bf16(o[2*g8],   pl[kc], b0);
                mma_bf16(o[2*g8+1], pl[kc], b1);
            }
#pragma unroll
            for (int kc = 0; kc < 4; kc++) {
                uint32_t r0, r1, r2, r3;
                ldm_x4_t(r0, r1, r2, r3,
                         vb_ + AT_KV_VB + (uint32_t)(kc * 16) * AT_ROWB + g8 * 32 + v_off);
                uint32_t b0[2] = {r0, r1}, b1[2] = {r2, r3};
                mma_bf16(o[2*g8],   ph[kc], b0);
                mma_bf16(o[2*g8+1], ph[kc], b1);
            }
        }

        if (t + 1 < nkt) {
#pragma unroll
            for (int j = 0; j < 8; j++)
#pragma unroll
                for (int c = 0; c < 4; c++) s[j][c] = s_nxt[j][c];
        }
    }

    float inv0 = 1.0f / li0, inv1 = 1.0f / li1;
    int row0 = qt * 128 + w * 16 + g;
    size_t base  = ((size_t)b * SEQ + row0) * D_MODEL + h * HEAD_DIM;
    size_t base8 = base + (size_t)8 * D_MODEL;
#pragma unroll
    for (int j = 0; j < 16; j++) {
        int col = j * 8 + tg * 2;
        uint32_t hi, lo;
        split_pack2(o[j][0] * inv0, o[j][1] * inv0, hi, lo);
        *(uint32_t*)(g_attnh + base + col) = hi;
        *(uint32_t*)(g_attnl + base + col) = lo;
        split_pack2(o[j][2] * inv1, o[j][3] * inv1, hi, lo);
        *(uint32_t*)(g_attnh + base8 + col) = hi;
        *(uint32_t*)(g_attnl + base8 + col) = lo;
    }
}

// ---------------- launch ---------------------------------------------------
extern "C" void kernel_launch(void* const* d_in, const int* in_sizes, int n_in,
                              void* d_out, int out_size) {
    const float* x    = (const float*)d_in[0];
    const float* Wqkv = (const float*)d_in[1];
    const float* Wout = (const float*)d_in[2];
    float* out = (float*)d_out;

    __nv_bfloat16 *xh, *xl, *wqh, *wql, *woh, *wol, *ah, *al;
    cudaGetSymbolAddress((void**)&xh,  g_xh);
    cudaGetSymbolAddress((void**)&xl,  g_xl);
    cudaGetSymbolAddress((void**)&wqh, g_wqkvh);
    cudaGetSymbolAddress((void**)&wql, g_wqkvl);
    cudaGetSymbolAddress((void**)&woh, g_wouth);
    cudaGetSymbolAddress((void**)&wol, g_woutl);
    cudaGetSymbolAddress((void**)&ah,  g_attnh);
    cudaGetSymbolAddress((void**)&al,  g_attnl);

    rope_table_kernel<<<(SEQ * 64 + 255) / 256, 256>>>();

    int n4x = M_TOTAL * D_MODEL / 4;
    split_kernel<<<(n4x + 255) / 256, 256>>>(x, xh, xl, n4x);
    int n4q = QKV_N * D_MODEL / 4;
    split_kernel<<<(n4q + 255) / 256, 256>>>(Wqkv, wqh, wql, n4q);
    int n4o = D_MODEL * D_MODEL / 4;
    split_kernel<<<(n4o + 255) / 256, 256>>>(Wout, woh, wol, n4o);

    cudaFuncSetAttribute(mma_gemm<0>, cudaFuncAttributeMaxDynamicSharedMemorySize,
                         GEMM_SMEM_BYTES);
    cudaFuncSetAttribute(mma_gemm<1>, cudaFuncAttributeMaxDynamicSharedMemorySize,
                         GEMM_SMEM_BYTES);
    cudaFuncSetAttribute(attn_mma_kernel, cudaFuncAttributeMaxDynamicSharedMemorySize,
                         AT_SMEM);

    mma_gemm<0><<<dim3(M_TOTAL / 128, QKV_N / 128), 256, GEMM_SMEM_BYTES>>>(
        xh, xl, wqh, wql, nullptr);

    attn_mma_kernel<<<dim3(SEQ / 128, BATCH * N_HEADS), 256, AT_SMEM>>>();

    mma_gemm<1><<<dim3(M_TOTAL / 128, D_MODEL / 128), 256, GEMM_SMEM_BYTES>>>(
        ah, al, woh, wol, out);
}

// round 10
// speedup vs baseline: 3.6523x; 1.3018x over previous
#include <cuda_runtime.h>
#include <cuda_bf16.h>
#include <cuda_fp16.h>
#include <math.h>
#include <stdint.h>

#define N_HEADS   32
#define KV_HEADS  8
#define HEAD_DIM  128
#define D_MODEL   4096
#define BATCH     2
#define SEQ       2048
#define M_TOTAL   (BATCH * SEQ)
#define QKV_N     ((KV_HEADS * 2 + N_HEADS) * HEAD_DIM)
#define KDIM      4096

__device__ float g_cos[SEQ * 64];
__device__ float g_sin[SEQ * 64];

// GEMM operands: A as fp16 hi/lo, B as single fp16
__device__ __align__(256) __half g_xh[(size_t)M_TOTAL * D_MODEL];
__device__ __align__(256) __half g_xl[(size_t)M_TOTAL * D_MODEL];
__device__ __align__(256) __half g_wqkv[(size_t)QKV_N * D_MODEL];
__device__ __align__(256) __half g_wout[(size_t)D_MODEL * D_MODEL];
__device__ __align__(256) __half g_attnh[(size_t)M_TOTAL * D_MODEL];
__device__ __align__(256) __half g_attnl[(size_t)M_TOTAL * D_MODEL];

// attention operands stay bf16 hi/lo (q pre-scaled by 1/sqrt(HEAD_DIM))
__device__ __align__(256) __nv_bfloat16 g_qh[(size_t)BATCH * N_HEADS * SEQ * HEAD_DIM];
__device__ __align__(256) __nv_bfloat16 g_ql[(size_t)BATCH * N_HEADS * SEQ * HEAD_DIM];
__device__ __align__(256) __nv_bfloat16 g_kh[(size_t)BATCH * KV_HEADS * SEQ * HEAD_DIM];
__device__ __align__(256) __nv_bfloat16 g_kl[(size_t)BATCH * KV_HEADS * SEQ * HEAD_DIM];
__device__ __align__(256) __nv_bfloat16 g_vh[(size_t)BATCH * KV_HEADS * SEQ * HEAD_DIM];
__device__ __align__(256) __nv_bfloat16 g_vl[(size_t)BATCH * KV_HEADS * SEQ * HEAD_DIM];

__device__ __forceinline__ uint32_t smem_u32(const void* p) {
    uint32_t a;
    asm("{ .reg .u64 t; cvta.to.shared.u64 t, %1; cvt.u32.u64 %0, t; }"
        : "=r"(a) : "l"(p));
    return a;
}
__device__ __forceinline__ void ldm_x4(uint32_t& r0, uint32_t& r1,
                                       uint32_t& r2, uint32_t& r3, uint32_t addr) {
    asm volatile("ldmatrix.sync.aligned.m8n8.x4.shared.b16 {%0,%1,%2,%3}, [%4];"
                 : "=r"(r0), "=r"(r1), "=r"(r2), "=r"(r3) : "r"(addr));
}
__device__ __forceinline__ void ldm_x4_t(uint32_t& r0, uint32_t& r1,
                                         uint32_t& r2, uint32_t& r3, uint32_t addr) {
    asm volatile("ldmatrix.sync.aligned.m8n8.x4.trans.shared.b16 {%0,%1,%2,%3}, [%4];"
                 : "=r"(r0), "=r"(r1), "=r"(r2), "=r"(r3) : "r"(addr));
}
__device__ __forceinline__ void mma_bf16(float* c, const uint32_t* a,
                                         const uint32_t* b) {
    asm volatile(
        "mma.sync.aligned.m16n8k16.row.col.f32.bf16.bf16.f32 "
        "{%0,%1,%2,%3}, {%4,%5,%6,%7}, {%8,%9}, {%0,%1,%2,%3};"
        : "+f"(c[0]), "+f"(c[1]), "+f"(c[2]), "+f"(c[3])
        : "r"(a[0]), "r"(a[1]), "r"(a[2]), "r"(a[3]), "r"(b[0]), "r"(b[1]));
}
__device__ __forceinline__ void mma_f16(float* c, const uint32_t* a,
                                        const uint32_t* b) {
    asm volatile(
        "mma.sync.aligned.m16n8k16.row.col.f32.f16.f16.f32 "
        "{%0,%1,%2,%3}, {%4,%5,%6,%7}, {%8,%9}, {%0,%1,%2,%3};"
        : "+f"(c[0]), "+f"(c[1]), "+f"(c[2]), "+f"(c[3])
        : "r"(a[0]), "r"(a[1]), "r"(a[2]), "r"(a[3]), "r"(b[0]), "r"(b[1]));
}
#define CP_ASYNC16(dst, src) \
    asm volatile("cp.async.cg.shared.global [%0], [%1], 16;" \
                 :: "r"(dst), "l"(src) : "memory")
#define CP_COMMIT() asm volatile("cp.async.commit_group;" ::: "memory")
#define CP_WAIT2()  asm volatile("cp.async.wait_group 2;" ::: "memory")
#define CP_WAIT1()  asm volatile("cp.async.wait_group 1;" ::: "memory")
#define CP_WAIT0()  asm volatile("cp.async.wait_group 0;" ::: "memory")

__device__ __forceinline__ float fast_exp(float x) {
    x = fmaxf(x, -80.0f);
    float y = x * 1.4426950408889634f;
    float z = y + 12582912.0f;
    int   ni = __float_as_int(z) - 0x4B400000;
    float f = y - (z - 12582912.0f);
    float p = 1.3333558146e-3f;
    p = fmaf(p, f, 9.6181291077e-3f);
    p = fmaf(p, f, 5.5504108664e-2f);
    p = fmaf(p, f, 2.4022650696e-1f);
    p = fmaf(p, f, 6.9314718056e-1f);
    p = fmaf(p, f, 1.0f);
    return p * __int_as_float((ni + 127) << 23);
}
__device__ __forceinline__ void split_pack2(float x, float y,
                                            uint32_t& hi, uint32_t& lo) {
    __nv_bfloat162 hh = __floats2bfloat162_rn(x, y);
    float2 hf = __bfloat1622float2(hh);
    __nv_bfloat162 ll = __floats2bfloat162_rn(x - hf.x, y - hf.y);
    hi = *(uint32_t*)&hh;
    lo = *(uint32_t*)&ll;
}
__device__ __forceinline__ void split_pack2h(float x, float y,
                                             uint32_t& hi, uint32_t& lo) {
    __half2 hh = __floats2half2_rn(x, y);
    float2 hf = __half22float2(hh);
    __half2 ll = __floats2half2_rn(x - hf.x, y - hf.y);
    hi = *(uint32_t*)&hh;
    lo = *(uint32_t*)&ll;
}

__global__ void rope_table_kernel() {
    int i = blockIdx.x * blockDim.x + threadIdx.x;
    if (i >= SEQ * 64) return;
    int l = i >> 6, d = i & 63;
    double inv = pow(500000.0, -((double)d) / 64.0);
    double ang = (double)l * inv;
    g_cos[i] = (float)cos(ang);
    g_sin[i] = (float)sin(ang);
}

// fp32 -> fp16 hi/lo split
__global__ __launch_bounds__(256) void split_h_kernel(
        const float* __restrict__ in, __half* __restrict__ hi,
        __half* __restrict__ lo, int n4) {
    int i = blockIdx.x * blockDim.x + threadIdx.x;
    if (i >= n4) return;
    float4 v = ((const float4*)in)[i];
    __half h[4], l[4];
    float vv[4] = {v.x, v.y, v.z, v.w};
#pragma unroll
    for (int j = 0; j < 4; j++) {
        h[j] = __float2half_rn(vv[j]);
        l[j] = __float2half_rn(vv[j] - __half2float(h[j]));
    }
    ((uint2*)hi)[i] = *(uint2*)h;
    ((uint2*)lo)[i] = *(uint2*)l;
}

// fp32 -> fp16 single
__global__ __launch_bounds__(256) void cvt_h_kernel(
        const float* __restrict__ in, __half* __restrict__ outp, int n4) {
    int i = blockIdx.x * blockDim.x + threadIdx.x;
    if (i >= n4) return;
    float4 v = ((const float4*)in)[i];
    __half h[4] = {__float2half_rn(v.x), __float2half_rn(v.y),
                   __float2half_rn(v.z), __float2half_rn(v.w)};
    ((uint2*)outp)[i] = *(uint2*)h;
}

// ---------------- fp16 2-pass GEMM via mma.sync + cp.async pipeline -------
// D = (Ah + Al) @ B^T ; 3 operand buffers per stage; 4 stages, 3 in flight.
#define VBYTES (128 * 40 * 2)                  /* 10240 per operand  */
#define STAGEB (3 * VBYTES)                    /* 30720 per stage    */
#define GEMM_SMEM_BYTES (4 * STAGEB + 1024)

template<int MODE>
__global__ __launch_bounds__(256) void mma_gemm(
        const __half* __restrict__ Ah, const __half* __restrict__ Al,
        const __half* __restrict__ Bf, float* __restrict__ outp) {
    extern __shared__ char smraw[];
    char* smp = (char*)(((uintptr_t)smraw + 1023) & ~(uintptr_t)1023);
    const uint32_t sbase = smem_u32(smp);

    const int tid = threadIdx.x;
    const int lane = tid & 31;
    const int wid = tid >> 5;
    const int warp_m = wid & 1;
    const int warp_n = wid >> 1;
    const int bm = blockIdx.x, bn = blockIdx.y;

    const size_t aoff = (size_t)(bm * 128) * KDIM;
    const size_t boff = (size_t)(bn * 128) * KDIM;
    const __half* srcs[3] = {Ah, Al, Bf};
    const size_t roff[3] = {aoff, aoff, boff};

    float acc[4][4][4];
#pragma unroll
    for (int i = 0; i < 4; i++)
#pragma unroll
        for (int j = 0; j < 4; j++)
#pragma unroll
            for (int c = 0; c < 4; c++) acc[i][j][c] = 0.f;

    // 1536 16B-chunks per stage, 6 per thread
    auto issue = [&](int ic, int st) {
        uint32_t base = sbase + (uint32_t)st * STAGEB;
#pragma unroll
        for (int t = 0; t < 6; t++) {
            int idx = tid + t * 256;          // 0..1535
            int v = idx >> 9;                 // operand 0..2
            int r = (idx >> 2) & 127;         // row
            int c = idx & 3;                  // 16B chunk in row
            CP_ASYNC16(base + (uint32_t)(v * VBYTES + r * 80 + c * 16),
                       srcs[v] + roff[v] + (size_t)r * KDIM + ic * 32 + c * 8);
        }
    };

    const uint32_t a_lane_off =
        (uint32_t)((lane & 15) * 80 + ((lane >> 4) << 3) * 2);
    const uint32_t b_lane_off =
        (uint32_t)((((lane & 16) >> 1) + (lane & 7)) * 80 + (lane & 8) * 2);
    const int m0 = warp_m * 64;
    const int n0 = warp_n * 32;

    auto compute = [&](uint32_t sst) {
#pragma unroll
        for (int ks = 0; ks < 2; ks++) {
            const uint32_t k0b = ks * 32;
            uint32_t ah[4][4], al[4][4], bf[4][2];
#pragma unroll
            for (int mi = 0; mi < 4; mi++) {
                ldm_x4(ah[mi][0], ah[mi][1], ah[mi][2], ah[mi][3],
                       sst + (uint32_t)((m0 + mi * 16) * 80) + a_lane_off + k0b);
                ldm_x4(al[mi][0], al[mi][1], al[mi][2], al[mi][3],
                       sst + VBYTES + (uint32_t)((m0 + mi * 16) * 80) + a_lane_off + k0b);
            }
#pragma unroll
            for (int p = 0; p < 2; p++) {
                uint32_t r0, r1, r2, r3;
                ldm_x4(r0, r1, r2, r3,
                       sst + 2 * VBYTES + (uint32_t)((n0 + p * 16) * 80) + b_lane_off + k0b);
                bf[p * 2][0] = r0; bf[p * 2][1] = r1;
                bf[p * 2 + 1][0] = r2; bf[p * 2 + 1][1] = r3;
            }
#pragma unroll
            for (int mi = 0; mi < 4; mi++)
#pragma unroll
                for (int ni = 0; ni < 4; ni++) {
                    mma_f16(acc[mi][ni], ah[mi], bf[ni]);
                    mma_f16(acc[mi][ni], al[mi], bf[ni]);
                }
        }
    };

    issue(0, 0); CP_COMMIT();
    issue(1, 1); CP_COMMIT();
    issue(2, 2); CP_COMMIT();

    for (int ic = 0; ic < 128; ic++) {
        if (ic <= 125)      CP_WAIT2();
        else if (ic == 126) CP_WAIT1();
        else                CP_WAIT0();
        __syncthreads();
        if (ic + 3 < 128) { issue(ic + 3, (ic + 3) & 3); CP_COMMIT(); }
        compute(sbase + (uint32_t)(ic & 3) * STAGEB);
    }
    __syncthreads();

    // ---- epilogue: fp32 stage in smem, then transform + store ----
    float* ep = (float*)smp;                 // [128][136]
    const int g = lane >> 2, tg = lane & 3;
#pragma unroll
    for (int mi = 0; mi < 4; mi++)
#pragma unroll
        for (int ni = 0; ni < 4; ni++) {
            int row = m0 + mi * 16 + g;
            int col = n0 + ni * 8 + tg * 2;
            ep[row * 136 + col]       = acc[mi][ni][0];
            ep[row * 136 + col + 1]   = acc[mi][ni][1];
            ep[(row + 8) * 136 + col]     = acc[mi][ni][2];
            ep[(row + 8) * 136 + col + 1] = acc[mi][ni][3];
        }
    __syncthreads();

    for (int t = tid; t < 128 * 16; t += 256) {
        int row = t >> 4, j = t & 15;
        float4 v1 = *(const float4*)&ep[row * 136 + j * 4];
        float4 v2 = *(const float4*)&ep[row * 136 + 64 + j * 4];
        if (MODE == 0) {
            float* p1 = &v1.x; float* p2 = &v2.x;
#pragma unroll
            for (int e = 0; e < 4; e++) {
                p1[e] = fminf(fmaxf(p1[e], -8.0f), 8.0f);
                p2[e] = fminf(fmaxf(p2[e], -8.0f), 8.0f);
            }
            int m = bm * 128 + row;
            int bb = m >> 11, l = m & (SEQ - 1);
            if (bn < N_HEADS + KV_HEADS) {
#pragma unroll
                for (int e = 0; e < 4; e++) {
                    int d = j * 4 + e;
                    float c = g_cos[l * 64 + d];
                    float s = g_sin[l * 64 + d];
                    float x1 = p1[e], x2 = p2[e];
                    p1[e] = x1 * c - x2 * s;
                    p2[e] = x2 * c + x1 * s;
                }
            }
            float sc = 1.0f;
            __nv_bfloat16 *dhi, *dlo;
            size_t off;
            if (bn < N_HEADS) {
                sc = 0.08838834764831845f;
                off = ((size_t)(bb * N_HEADS + bn) * SEQ + l) * HEAD_DIM;
                dhi = g_qh; dlo = g_ql;
            } else if (bn < N_HEADS + KV_HEADS) {
                off = ((size_t)(bb * KV_HEADS + (bn - N_HEADS)) * SEQ + l) * HEAD_DIM;
                dhi = g_kh; dlo = g_kl;
            } else {
                off = ((size_t)(bb * KV_HEADS + (bn - N_HEADS - KV_HEADS)) * SEQ + l) * HEAD_DIM;
                dhi = g_vh; dlo = g_vl;
            }
            __nv_bfloat16 hb[8], lb[8];
            float vv[8] = {p1[0]*sc, p1[1]*sc, p1[2]*sc, p1[3]*sc,
                           p2[0]*sc, p2[1]*sc, p2[2]*sc, p2[3]*sc};
#pragma unroll
            for (int e = 0; e < 8; e++) {
                hb[e] = __float2bfloat16(vv[e]);
                lb[e] = __float2bfloat16(vv[e] - __bfloat162float(hb[e]));
            }
            *(uint2*)(dhi + off + j * 4)      = *(uint2*)hb;
            *(uint2*)(dlo + off + j * 4)      = *(uint2*)lb;
            *(uint2*)(dhi + off + 64 + j * 4) = *(uint2*)(hb + 4);
            *(uint2*)(dlo + off + 64 + j * 4) = *(uint2*)(lb + 4);
        } else {
            float* dst = outp + (size_t)(bm * 128 + row) * D_MODEL + bn * 128;
            *(float4*)(dst + j * 4) = v1;
            *(float4*)(dst + 64 + j * 4) = v2;
        }
    }
}

// ---------------- flash attention (bf16, unchanged math) -------------------
#define AT_ROWB   272
#define AT_KV_VB  (64 * AT_ROWB)
#define AT_STG    (4 * AT_KV_VB)
#define AT_SMEM   (3 * AT_STG)

__global__ void __launch_bounds__(256, 1) attn_mma_kernel() {
    extern __shared__ char smp[];
    const uint32_t kvB = smem_u32(smp);

    const int tid = threadIdx.x, lane = tid & 31, w = tid >> 5;
    const int g = lane >> 2, tg = lane & 3;
    const int qt = 15 - (int)blockIdx.x;
    const int bh = blockIdx.y;
    const int b = bh >> 5, h = bh & 31, kh = h >> 2;

    const __nv_bfloat16* Qhp = g_qh + ((size_t)(b * N_HEADS + h) * SEQ + qt * 128) * HEAD_DIM;
    const __nv_bfloat16* Qlp = g_ql + ((size_t)(b * N_HEADS + h) * SEQ + qt * 128) * HEAD_DIM;
    const __nv_bfloat16* Khp = g_kh + (size_t)(b * KV_HEADS + kh) * SEQ * HEAD_DIM;
    const __nv_bfloat16* Klp = g_kl + (size_t)(b * KV_HEADS + kh) * SEQ * HEAD_DIM;
    const __nv_bfloat16* Vhp = g_vh + (size_t)(b * KV_HEADS + kh) * SEQ * HEAD_DIM;
    const __nv_bfloat16* Vlp = g_vl + (size_t)(b * KV_HEADS + kh) * SEQ * HEAD_DIM;

    const int nkt = 2 * qt + 2;

    auto issue = [&](int kt, int st) {
        uint32_t base = kvB + (uint32_t)st * AT_STG;
        const __nv_bfloat16* srcs[4] = {Khp, Klp, Vhp, Vlp};
#pragma unroll
        for (int v = 0; v < 4; v++) {
            const __nv_bfloat16* src = srcs[v] + (size_t)kt * 64 * HEAD_DIM;
#pragma unroll
            for (int t = 0; t < 4; t++) {
                int c = tid + t * 256;
                int row = c >> 4, cc = c & 15;
                CP_ASYNC16(base + (uint32_t)v * AT_KV_VB + row * AT_ROWB + cc * 16,
                           src + (size_t)row * HEAD_DIM + cc * 8);
            }
        }
    };

    issue(0, 0); CP_COMMIT();
    issue(1, 1); CP_COMMIT();

    uint32_t aqh[8][4], aql[8][4];
    {
        const int r0 = w * 16 + (lane >> 2);
        const int cb = (lane & 3) * 2;
        const __nv_bfloat16* qa = Qhp + (size_t)r0 * HEAD_DIM;
        const __nv_bfloat16* qb = qa + 8 * HEAD_DIM;
        const __nv_bfloat16* la = Qlp + (size_t)r0 * HEAD_DIM;
        const __nv_bfloat16* lb = la + 8 * HEAD_DIM;
#pragma unroll
        for (int kc = 0; kc < 8; kc++) {
            int c0 = kc * 16 + cb, c1 = c0 + 8;
            aqh[kc][0] = *(const uint32_t*)(qa + c0);
            aqh[kc][1] = *(const uint32_t*)(qb + c0);
            aqh[kc][2] = *(const uint32_t*)(qa + c1);
            aqh[kc][3] = *(const uint32_t*)(qb + c1);
            aql[kc][0] = *(const uint32_t*)(la + c0);
            aql[kc][1] = *(const uint32_t*)(lb + c0);
            aql[kc][2] = *(const uint32_t*)(la + c1);
            aql[kc][3] = *(const uint32_t*)(lb + c1);
        }
    }

    float o[16][4];
#pragma unroll
    for (int j = 0; j < 16; j++)
#pragma unroll
        for (int c = 0; c < 4; c++) o[j][c] = 0.f;
    float mi0 = -1e30f, mi1 = -1e30f, li0 = 0.f, li1 = 0.f;

    const uint32_t b_off = (uint32_t)((((lane & 16) >> 1) + (lane & 7)) * AT_ROWB + (lane & 8) * 2);
    const uint32_t v_off = (uint32_t)((lane & 15) * AT_ROWB + ((lane >> 4) << 4));

    auto computeS = [&](int kt, float s[8][4]) {
        const uint32_t kb_ = kvB + (uint32_t)(kt % 3) * AT_STG;
#pragma unroll
        for (int j = 0; j < 8; j++)
#pragma unroll
            for (int c = 0; c < 4; c++) s[j][c] = 0.f;
#pragma unroll
        for (int kc = 0; kc < 8; kc++) {
            uint32_t kf[8][2];
#pragma unroll
            for (int g8 = 0; g8 < 4; g8++)
                ldm_x4(kf[g8*2][0], kf[g8*2][1], kf[g8*2+1][0], kf[g8*2+1][1],
                       kb_ + (uint32_t)(g8 * 16) * AT_ROWB + kc * 32 + b_off);
#pragma unroll
            for (int j = 0; j < 8; j++) { mma_bf16(s[j], aqh[kc], kf[j]); mma_bf16(s[j], aql[kc], kf[j]); }
#pragma unroll
            for (int g8 = 0; g8 < 4; g8++)
                ldm_x4(kf[g8*2][0], kf[g8*2][1], kf[g8*2+1][0], kf[g8*2+1][1],
                       kb_ + AT_KV_VB + (uint32_t)(g8 * 16) * AT_ROWB + kc * 32 + b_off);
#pragma unroll
            for (int j = 0; j < 8; j++) mma_bf16(s[j], aqh[kc], kf[j]);
        }
        if (kt * 64 + 63 > qt * 128 + w * 16) {
            int qr = qt * 128 + w * 16 + g;
#pragma unroll
            for (int j = 0; j < 8; j++) {
                int key = kt * 64 + j * 8 + tg * 2;
                if (key     > qr)     s[j][0] = -1e30f;
                if (key + 1 > qr)     s[j][1] = -1e30f;
                if (key     > qr + 8) s[j][2] = -1e30f;
                if (key + 1 > qr + 8) s[j][3] = -1e30f;
            }
        }
    };

    float s[8][4], s_nxt[8][4];
    CP_WAIT1();
    __syncthreads();
    computeS(0, s);

    for (int t = 0; t < nkt; t++) {
        if (t + 1 < nkt) {
            CP_WAIT0();
            __syncthreads();
            if (t + 2 < nkt) { issue(t + 2, (t + 2) % 3); CP_COMMIT(); }
            computeS(t + 1, s_nxt);
        }

        float rm0 = s[0][0], rm1 = s[0][2];
#pragma unroll
        for (int j = 0; j < 8; j++) {
            rm0 = fmaxf(rm0, fmaxf(s[j][0], s[j][1]));
            rm1 = fmaxf(rm1, fmaxf(s[j][2], s[j][3]));
        }
        rm0 = fmaxf(rm0, __shfl_xor_sync(0xffffffffu, rm0, 1));
        rm0 = fmaxf(rm0, __shfl_xor_sync(0xffffffffu, rm0, 2));
        rm1 = fmaxf(rm1, __shfl_xor_sync(0xffffffffu, rm1, 1));
        rm1 = fmaxf(rm1, __shfl_xor_sync(0xffffffffu, rm1, 2));
        float mn0 = fmaxf(mi0, rm0), mn1 = fmaxf(mi1, rm1);
        float c0 = fast_exp(mi0 - mn0), c1 = fast_exp(mi1 - mn1);
        mi0 = mn0; mi1 = mn1;
        float sum0 = 0.f, sum1 = 0.f;
#pragma unroll
        for (int j = 0; j < 8; j++) {
            s[j][0] = fast_exp(s[j][0] - mn0); sum0 += s[j][0];
            s[j][1] = fast_exp(s[j][1] - mn0); sum0 += s[j][1];
            s[j][2] = fast_exp(s[j][2] - mn1); sum1 += s[j][2];
            s[j][3] = fast_exp(s[j][3] - mn1); sum1 += s[j][3];
        }
        sum0 += __shfl_xor_sync(0xffffffffu, sum0, 1);
        sum0 += __shfl_xor_sync(0xffffffffu, sum0, 2);
        sum1 += __shfl_xor_sync(0xffffffffu, sum1, 1);
        sum1 += __shfl_xor_sync(0xffffffffu, sum1, 2);
        li0 = li0 * c0 + sum0; li1 = li1 * c1 + sum1;
#pragma unroll
        for (int j = 0; j < 16; j++) {
            o[j][0] *= c0; o[j][1] *= c0; o[j][2] *= c1; o[j][3] *= c1;
        }

        uint32_t ph[4][4], pl[4][4];
#pragma unroll
        for (int kc = 0; kc < 4; kc++) {
            split_pack2(s[2*kc][0],   s[2*kc][1],   ph[kc][0], pl[kc][0]);
            split_pack2(s[2*kc][2],   s[2*kc][3],   ph[kc][1], pl[kc][1]);
            split_pack2(s[2*kc+1][0], s[2*kc+1][1], ph[kc][2], pl[kc][2]);
            split_pack2(s[2*kc+1][2], s[2*kc+1][3], ph[kc][3], pl[kc][3]);
        }

        const uint32_t vb_ = kvB + (uint32_t)(t % 3) * AT_STG + 2 * AT_KV_VB;
#pragma unroll
        for (int g8 = 0; g8 < 8; g8++) {
#pragma unroll
            for (int kc = 0; kc < 4; kc++) {
                uint32_t r0, r1, r2, r3;
                ldm_x4_t(r0, r1, r2, r3,
                         vb_ + (uint32_t)(kc * 16) * AT_ROWB + g8 * 32 + v_off);
                uint32_t b0[2] = {r0, r1}, b1[2] = {r2, r3};
                mma_bf16(o[2*g8],   ph[kc], b0);
                mma_bf16(o[2*g8+1], ph[kc], b1);
                mma_bf16(o[2*g8],   pl[kc], b0);
                mma_bf16(o[2*g8+1], pl[kc], b1);
            }
#pragma unroll
            for (int kc = 0; kc < 4; kc++) {
                uint32_t r0, r1, r2, r3;
                ldm_x4_t(r0, r1, r2, r3,
                         vb_ + AT_KV_VB + (uint32_t)(kc * 16) * AT_ROWB + g8 * 32 + v_off);
                uint32_t b0[2] = {r0, r1}, b1[2] = {r2, r3};
                mma_bf16(o[2*g8],   ph[kc], b0);
                mma_bf16(o[2*g8+1], ph[kc], b1);
            }
        }

        if (t + 1 < nkt) {
#pragma unroll
            for (int j = 0; j < 8; j++)
#pragma unroll
                for (int c = 0; c < 4; c++) s[j][c] = s_nxt[j][c];
        }
    }

    // ---- epilogue: O/l -> fp16 hi/lo for the out-proj ----
    float inv0 = 1.0f / li0, inv1 = 1.0f / li1;
    int row0 = qt * 128 + w * 16 + g;
    size_t base  = ((size_t)b * SEQ + row0) * D_MODEL + h * HEAD_DIM;
    size_t base8 = base + (size_t)8 * D_MODEL;
#pragma unroll
    for (int j = 0; j < 16; j++) {
        int col = j * 8 + tg * 2;
        uint32_t hi, lo;
        split_pack2h(o[j][0] * inv0, o[j][1] * inv0, hi, lo);
        *(uint32_t*)(g_attnh + base + col) = hi;
        *(uint32_t*)(g_attnl + base + col) = lo;
        split_pack2h(o[j][2] * inv1, o[j][3] * inv1, hi, lo);
        *(uint32_t*)(g_attnh + base8 + col) = hi;
        *(uint32_t*)(g_attnl + base8 + col) = lo;
    }
}

// ---------------- launch ---------------------------------------------------
extern "C" void kernel_launch(void* const* d_in, const int* in_sizes, int n_in,
                              void* d_out, int out_size) {
    const float* x    = (const float*)d_in[0];
    const float* Wqkv = (const float*)d_in[1];
    const float* Wout = (const float*)d_in[2];
    float* out = (float*)d_out;

    __half *xh, *xl, *wq, *wo, *ah, *al;
    cudaGetSymbolAddress((void**)&xh, g_xh);
    cudaGetSymbolAddress((void**)&xl, g_xl);
    cudaGetSymbolAddress((void**)&wq, g_wqkv);
    cudaGetSymbolAddress((void**)&wo, g_wout);
    cudaGetSymbolAddress((void**)&ah, g_attnh);
    cudaGetSymbolAddress((void**)&al, g_attnl);

    rope_table_kernel<<<(SEQ * 64 + 255) / 256, 256>>>();

    int n4x = M_TOTAL * D_MODEL / 4;
    split_h_kernel<<<(n4x + 255) / 256, 256>>>(x, xh, xl, n4x);
    int n4q = QKV_N * D_MODEL / 4;
    cvt_h_kernel<<<(n4q + 255) / 256, 256>>>(Wqkv, wq, n4q);
    int n4o = D_MODEL * D_MODEL / 4;
    cvt_h_kernel<<<(n4o + 255) / 256, 256>>>(Wout, wo, n4o);

    cudaFuncSetAttribute(mma_gemm<0>, cudaFuncAttributeMaxDynamicSharedMemorySize,
                         GEMM_SMEM_BYTES);
    cudaFuncSetAttribute(mma_gemm<1>, cudaFuncAttributeMaxDynamicSharedMemorySize,
                         GEMM_SMEM_BYTES);
    cudaFuncSetAttribute(attn_mma_kernel, cudaFuncAttributeMaxDynamicSharedMemorySize,
                         AT_SMEM);

    // QKV projection: fused clip+RoPE+scale+split-scatter
    mma_gemm<0><<<dim3(M_TOTAL / 128, QKV_N / 128), 256, GEMM_SMEM_BYTES>>>(
        xh, xl, wq, nullptr);

    // tensor-core flash attention
    attn_mma_kernel<<<dim3(SEQ / 128, BATCH * N_HEADS), 256, AT_SMEM>>>();

    // out projection
    mma_gemm<1><<<dim3(M_TOTAL / 128, D_MODEL / 128), 256, GEMM_SMEM_BYTES>>>(
        ah, al, wo, out);
}

// round 11
// speedup vs baseline: 4.5793x; 1.2538x over previous
#include <cuda_runtime.h>
#include <cuda_bf16.h>
#include <cuda_fp16.h>
#include <math.h>
#include <stdint.h>

#define N_HEADS   32
#define KV_HEADS  8
#define HEAD_DIM  128
#define D_MODEL   4096
#define BATCH     2
#define SEQ       2048
#define M_TOTAL   (BATCH * SEQ)
#define QKV_N     ((KV_HEADS * 2 + N_HEADS) * HEAD_DIM)
#define KDIM      4096

__device__ float g_cos[SEQ * 64];
__device__ float g_sin[SEQ * 64];

// GEMM operands: A as fp16 hi/lo, B as single fp16
__device__ __align__(256) __half g_xh[(size_t)M_TOTAL * D_MODEL];
__device__ __align__(256) __half g_xl[(size_t)M_TOTAL * D_MODEL];
__device__ __align__(256) __half g_wqkv[(size_t)QKV_N * D_MODEL];
__device__ __align__(256) __half g_wout[(size_t)D_MODEL * D_MODEL];
__device__ __align__(256) __half g_attnh[(size_t)M_TOTAL * D_MODEL];
__device__ __align__(256) __half g_attnl[(size_t)M_TOTAL * D_MODEL];

// attention operands (fp16): q hi/lo (pre-scaled), k/v single
__device__ __align__(256) __half g_qh[(size_t)BATCH * N_HEADS * SEQ * HEAD_DIM];
__device__ __align__(256) __half g_ql[(size_t)BATCH * N_HEADS * SEQ * HEAD_DIM];
__device__ __align__(256) __half g_kf[(size_t)BATCH * KV_HEADS * SEQ * HEAD_DIM];
__device__ __align__(256) __half g_vf[(size_t)BATCH * KV_HEADS * SEQ * HEAD_DIM];

__device__ __forceinline__ uint32_t smem_u32(const void* p) {
    uint32_t a;
    asm("{ .reg .u64 t; cvta.to.shared.u64 t, %1; cvt.u32.u64 %0, t; }"
        : "=r"(a) : "l"(p));
    return a;
}
__device__ __forceinline__ void ldm_x4(uint32_t& r0, uint32_t& r1,
                                       uint32_t& r2, uint32_t& r3, uint32_t addr) {
    asm volatile("ldmatrix.sync.aligned.m8n8.x4.shared.b16 {%0,%1,%2,%3}, [%4];"
                 : "=r"(r0), "=r"(r1), "=r"(r2), "=r"(r3) : "r"(addr));
}
__device__ __forceinline__ void ldm_x4_t(uint32_t& r0, uint32_t& r1,
                                         uint32_t& r2, uint32_t& r3, uint32_t addr) {
    asm volatile("ldmatrix.sync.aligned.m8n8.x4.trans.shared.b16 {%0,%1,%2,%3}, [%4];"
                 : "=r"(r0), "=r"(r1), "=r"(r2), "=r"(r3) : "r"(addr));
}
__device__ __forceinline__ void mma_f16(float* c, const uint32_t* a,
                                        const uint32_t* b) {
    asm volatile(
        "mma.sync.aligned.m16n8k16.row.col.f32.f16.f16.f32 "
        "{%0,%1,%2,%3}, {%4,%5,%6,%7}, {%8,%9}, {%0,%1,%2,%3};"
        : "+f"(c[0]), "+f"(c[1]), "+f"(c[2]), "+f"(c[3])
        : "r"(a[0]), "r"(a[1]), "r"(a[2]), "r"(a[3]), "r"(b[0]), "r"(b[1]));
}
#define CP_ASYNC16(dst, src) \
    asm volatile("cp.async.cg.shared.global [%0], [%1], 16;" \
                 :: "r"(dst), "l"(src) : "memory")
#define CP_COMMIT() asm volatile("cp.async.commit_group;" ::: "memory")
#define CP_WAIT1()  asm volatile("cp.async.wait_group 1;" ::: "memory")
#define CP_WAIT0()  asm volatile("cp.async.wait_group 0;" ::: "memory")

__device__ __forceinline__ float fast_exp(float x) {
    x = fmaxf(x, -80.0f);
    float y = x * 1.4426950408889634f;
    float z = y + 12582912.0f;
    int   ni = __float_as_int(z) - 0x4B400000;
    float f = y - (z - 12582912.0f);
    float p = 1.3333558146e-3f;
    p = fmaf(p, f, 9.6181291077e-3f);
    p = fmaf(p, f, 5.5504108664e-2f);
    p = fmaf(p, f, 2.4022650696e-1f);
    p = fmaf(p, f, 6.9314718056e-1f);
    p = fmaf(p, f, 1.0f);
    return p * __int_as_float((ni + 127) << 23);
}
__device__ __forceinline__ void split_pack2h(float x, float y,
                                             uint32_t& hi, uint32_t& lo) {
    __half2 hh = __floats2half2_rn(x, y);
    float2 hf = __half22float2(hh);
    __half2 ll = __floats2half2_rn(x - hf.x, y - hf.y);
    hi = *(uint32_t*)&hh;
    lo = *(uint32_t*)&ll;
}

__global__ void rope_table_kernel() {
    int i = blockIdx.x * blockDim.x + threadIdx.x;
    if (i >= SEQ * 64) return;
    int l = i >> 6, d = i & 63;
    double inv = pow(500000.0, -((double)d) / 64.0);
    double ang = (double)l * inv;
    g_cos[i] = (float)cos(ang);
    g_sin[i] = (float)sin(ang);
}

__global__ __launch_bounds__(256) void split_h_kernel(
        const float* __restrict__ in, __half* __restrict__ hi,
        __half* __restrict__ lo, int n4) {
    int i = blockIdx.x * blockDim.x + threadIdx.x;
    if (i >= n4) return;
    float4 v = ((const float4*)in)[i];
    __half h[4], l[4];
    float vv[4] = {v.x, v.y, v.z, v.w};
#pragma unroll
    for (int j = 0; j < 4; j++) {
        h[j] = __float2half_rn(vv[j]);
        l[j] = __float2half_rn(vv[j] - __half2float(h[j]));
    }
    ((uint2*)hi)[i] = *(uint2*)h;
    ((uint2*)lo)[i] = *(uint2*)l;
}

__global__ __launch_bounds__(256) void cvt_h_kernel(
        const float* __restrict__ in, __half* __restrict__ outp, int n4) {
    int i = blockIdx.x * blockDim.x + threadIdx.x;
    if (i >= n4) return;
    float4 v = ((const float4*)in)[i];
    __half h[4] = {__float2half_rn(v.x), __float2half_rn(v.y),
                   __float2half_rn(v.z), __float2half_rn(v.w)};
    ((uint2*)outp)[i] = *(uint2*)h;
}

// ---------------- fp16 2-pass GEMM: 3 stages, 2 CTAs/SM --------------------
#define VBYTES (128 * 40 * 2)                  /* 10240 per operand  */
#define STAGEB (3 * VBYTES)                    /* 30720 per stage    */
#define GEMM_SMEM_BYTES (3 * STAGEB + 1024)    /* 93184              */

template<int MODE>
__global__ __launch_bounds__(256, 2) void mma_gemm(
        const __half* __restrict__ Ah, const __half* __restrict__ Al,
        const __half* __restrict__ Bf, float* __restrict__ outp) {
    extern __shared__ char smraw[];
    char* smp = (char*)(((uintptr_t)smraw + 1023) & ~(uintptr_t)1023);
    const uint32_t sbase = smem_u32(smp);

    const int tid = threadIdx.x;
    const int lane = tid & 31;
    const int wid = tid >> 5;
    const int warp_m = wid & 1;
    const int warp_n = wid >> 1;
    const int bm = blockIdx.x, bn = blockIdx.y;

    const size_t aoff = (size_t)(bm * 128) * KDIM;
    const size_t boff = (size_t)(bn * 128) * KDIM;
    const __half* srcs[3] = {Ah, Al, Bf};
    const size_t roff[3] = {aoff, aoff, boff};

    float acc[4][4][4];
#pragma unroll
    for (int i = 0; i < 4; i++)
#pragma unroll
        for (int j = 0; j < 4; j++)
#pragma unroll
            for (int c = 0; c < 4; c++) acc[i][j][c] = 0.f;

    auto issue = [&](int ic, int st) {
        uint32_t base = sbase + (uint32_t)st * STAGEB;
#pragma unroll
        for (int t = 0; t < 6; t++) {
            int idx = tid + t * 256;          // 0..1535
            int v = idx >> 9;
            int r = (idx >> 2) & 127;
            int c = idx & 3;
            CP_ASYNC16(base + (uint32_t)(v * VBYTES + r * 80 + c * 16),
                       srcs[v] + roff[v] + (size_t)r * KDIM + ic * 32 + c * 8);
        }
    };

    const uint32_t a_lane_off =
        (uint32_t)((lane & 15) * 80 + ((lane >> 4) << 3) * 2);
    const uint32_t b_lane_off =
        (uint32_t)((((lane & 16) >> 1) + (lane & 7)) * 80 + (lane & 8) * 2);
    const int m0 = warp_m * 64;
    const int n0 = warp_n * 32;

    // low-register compute: B fragments first, A per-mi
    auto compute = [&](uint32_t sst) {
#pragma unroll
        for (int ks = 0; ks < 2; ks++) {
            const uint32_t k0b = ks * 32;
            uint32_t bf[4][2];
#pragma unroll
            for (int p = 0; p < 2; p++) {
                uint32_t r0, r1, r2, r3;
                ldm_x4(r0, r1, r2, r3,
                       sst + 2 * VBYTES + (uint32_t)((n0 + p * 16) * 80) + b_lane_off + k0b);
                bf[p * 2][0] = r0; bf[p * 2][1] = r1;
                bf[p * 2 + 1][0] = r2; bf[p * 2 + 1][1] = r3;
            }
#pragma unroll
            for (int mi = 0; mi < 4; mi++) {
                uint32_t ah[4], al[4];
                ldm_x4(ah[0], ah[1], ah[2], ah[3],
                       sst + (uint32_t)((m0 + mi * 16) * 80) + a_lane_off + k0b);
                ldm_x4(al[0], al[1], al[2], al[3],
                       sst + VBYTES + (uint32_t)((m0 + mi * 16) * 80) + a_lane_off + k0b);
#pragma unroll
                for (int ni = 0; ni < 4; ni++) {
                    mma_f16(acc[mi][ni], ah, bf[ni]);
                    mma_f16(acc[mi][ni], al, bf[ni]);
                }
            }
        }
    };

    issue(0, 0); CP_COMMIT();
    issue(1, 1); CP_COMMIT();

    for (int ic = 0; ic < 128; ic++) {
        if (ic <= 126) CP_WAIT1();
        else           CP_WAIT0();
        __syncthreads();
        if (ic + 2 < 128) { issue(ic + 2, (ic + 2) % 3); CP_COMMIT(); }
        compute(sbase + (uint32_t)(ic % 3) * STAGEB);
    }
    __syncthreads();

    // ---- epilogue ----
    float* ep = (float*)smp;                 // [128][136] = 69632 B
    const int g = lane >> 2, tg = lane & 3;
#pragma unroll
    for (int mi = 0; mi < 4; mi++)
#pragma unroll
        for (int ni = 0; ni < 4; ni++) {
            int row = m0 + mi * 16 + g;
            int col = n0 + ni * 8 + tg * 2;
            ep[row * 136 + col]       = acc[mi][ni][0];
            ep[row * 136 + col + 1]   = acc[mi][ni][1];
            ep[(row + 8) * 136 + col]     = acc[mi][ni][2];
            ep[(row + 8) * 136 + col + 1] = acc[mi][ni][3];
        }
    __syncthreads();

    for (int t = tid; t < 128 * 16; t += 256) {
        int row = t >> 4, j = t & 15;
        float4 v1 = *(const float4*)&ep[row * 136 + j * 4];
        float4 v2 = *(const float4*)&ep[row * 136 + 64 + j * 4];
        if (MODE == 0) {
            float* p1 = &v1.x; float* p2 = &v2.x;
#pragma unroll
            for (int e = 0; e < 4; e++) {
                p1[e] = fminf(fmaxf(p1[e], -8.0f), 8.0f);
                p2[e] = fminf(fmaxf(p2[e], -8.0f), 8.0f);
            }
            int m = bm * 128 + row;
            int bb = m >> 11, l = m & (SEQ - 1);
            if (bn < N_HEADS + KV_HEADS) {   // RoPE for q and k heads
#pragma unroll
                for (int e = 0; e < 4; e++) {
                    int d = j * 4 + e;
                    float c = g_cos[l * 64 + d];
                    float s = g_sin[l * 64 + d];
                    float x1 = p1[e], x2 = p2[e];
                    p1[e] = x1 * c - x2 * s;
                    p2[e] = x2 * c + x1 * s;
                }
            }
            if (bn < N_HEADS) {
                // q: scale + fp16 hi/lo split
                const float sc = 0.08838834764831845f;
                size_t off = ((size_t)(bb * N_HEADS + bn) * SEQ + l) * HEAD_DIM;
                __half hb[8], lb[8];
                float vv[8] = {p1[0]*sc, p1[1]*sc, p1[2]*sc, p1[3]*sc,
                               p2[0]*sc, p2[1]*sc, p2[2]*sc, p2[3]*sc};
#pragma unroll
                for (int e = 0; e < 8; e++) {
                    hb[e] = __float2half_rn(vv[e]);
                    lb[e] = __float2half_rn(vv[e] - __half2float(hb[e]));
                }
                *(uint2*)(g_qh + off + j * 4)      = *(uint2*)hb;
                *(uint2*)(g_ql + off + j * 4)      = *(uint2*)lb;
                *(uint2*)(g_qh + off + 64 + j * 4) = *(uint2*)(hb + 4);
                *(uint2*)(g_ql + off + 64 + j * 4) = *(uint2*)(lb + 4);
            } else {
                // k / v: single fp16
                int kv = bn - N_HEADS;
                __half* dst = (kv < KV_HEADS) ? g_kf : g_vf;
                int hh = (kv < KV_HEADS) ? kv : kv - KV_HEADS;
                size_t off = ((size_t)(bb * KV_HEADS + hh) * SEQ + l) * HEAD_DIM;
                __half hb[8] = {__float2half_rn(p1[0]), __float2half_rn(p1[1]),
                                __float2half_rn(p1[2]), __float2half_rn(p1[3]),
                                __float2half_rn(p2[0]), __float2half_rn(p2[1]),
                                __float2half_rn(p2[2]), __float2half_rn(p2[3])};
                *(uint2*)(dst + off + j * 4)      = *(uint2*)hb;
                *(uint2*)(dst + off + 64 + j * 4) = *(uint2*)(hb + 4);
            }
        } else {
            float* dst = outp + (size_t)(bm * 128 + row) * D_MODEL + bn * 128;
            *(float4*)(dst + j * 4) = v1;
            *(float4*)(dst + 64 + j * 4) = v2;
        }
    }
}

// ---------------- flash attention (fp16 2-pass) ----------------------------
#define AT_ROWB   272
#define AT_KV_VB  (64 * AT_ROWB)               /* 17408 */
#define AT_STG    (2 * AT_KV_VB)               /* K + V = 34816 */
#define AT_SMEM   (3 * AT_STG)                 /* 104448 */

__global__ void __launch_bounds__(256, 1) attn_mma_kernel() {
    extern __shared__ char smp[];
    const uint32_t kvB = smem_u32(smp);

    const int tid = threadIdx.x, lane = tid & 31, w = tid >> 5;
    const int g = lane >> 2, tg = lane & 3;
    const int qt = 15 - (int)blockIdx.x;
    const int bh = blockIdx.y;
    const int b = bh >> 5, h = bh & 31, kh = h >> 2;

    const __half* Qhp = g_qh + ((size_t)(b * N_HEADS + h) * SEQ + qt * 128) * HEAD_DIM;
    const __half* Qlp = g_ql + ((size_t)(b * N_HEADS + h) * SEQ + qt * 128) * HEAD_DIM;
    const __half* Kfp = g_kf + (size_t)(b * KV_HEADS + kh) * SEQ * HEAD_DIM;
    const __half* Vfp = g_vf + (size_t)(b * KV_HEADS + kh) * SEQ * HEAD_DIM;

    const int nkt = 2 * qt + 2;

    auto issue = [&](int kt, int st) {
        uint32_t base = kvB + (uint32_t)st * AT_STG;
        const __half* srcs[2] = {Kfp, Vfp};
#pragma unroll
        for (int v = 0; v < 2; v++) {
            const __half* src = srcs[v] + (size_t)kt * 64 * HEAD_DIM;
#pragma unroll
            for (int t = 0; t < 4; t++) {
                int c = tid + t * 256;
                int row = c >> 4, cc = c & 15;
                CP_ASYNC16(base + (uint32_t)v * AT_KV_VB + row * AT_ROWB + cc * 16,
                           src + (size_t)row * HEAD_DIM + cc * 8);
            }
        }
    };

    issue(0, 0); CP_COMMIT();
    issue(1, 1); CP_COMMIT();

    // Q fragments -> registers (m16n8k16 A layout), loaded once
    uint32_t aqh[8][4], aql[8][4];
    {
        const int r0 = w * 16 + (lane >> 2);
        const int cb = (lane & 3) * 2;
        const __half* qa = Qhp + (size_t)r0 * HEAD_DIM;
        const __half* qb = qa + 8 * HEAD_DIM;
        const __half* la = Qlp + (size_t)r0 * HEAD_DIM;
        const __half* lb = la + 8 * HEAD_DIM;
#pragma unroll
        for (int kc = 0; kc < 8; kc++) {
            int c0 = kc * 16 + cb, c1 = c0 + 8;
            aqh[kc][0] = *(const uint32_t*)(qa + c0);
            aqh[kc][1] = *(const uint32_t*)(qb + c0);
            aqh[kc][2] = *(const uint32_t*)(qa + c1);
            aqh[kc][3] = *(const uint32_t*)(qb + c1);
            aql[kc][0] = *(const uint32_t*)(la + c0);
            aql[kc][1] = *(const uint32_t*)(lb + c0);
            aql[kc][2] = *(const uint32_t*)(la + c1);
            aql[kc][3] = *(const uint32_t*)(lb + c1);
        }
    }

    float o[16][4];
#pragma unroll
    for (int j = 0; j < 16; j++)
#pragma unroll
        for (int c = 0; c < 4; c++) o[j][c] = 0.f;
    float mi0 = -1e30f, mi1 = -1e30f, li0 = 0.f, li1 = 0.f;

    const uint32_t b_off = (uint32_t)((((lane & 16) >> 1) + (lane & 7)) * AT_ROWB + (lane & 8) * 2);
    const uint32_t v_off = (uint32_t)((lane & 15) * AT_ROWB + ((lane >> 4) << 4));

    auto computeS = [&](int kt, float s[8][4]) {
        const uint32_t kb_ = kvB + (uint32_t)(kt % 3) * AT_STG;
#pragma unroll
        for (int j = 0; j < 8; j++)
#pragma unroll
            for (int c = 0; c < 4; c++) s[j][c] = 0.f;
#pragma unroll
        for (int kc = 0; kc < 8; kc++) {
            uint32_t kf[8][2];
#pragma unroll
            for (int g8 = 0; g8 < 4; g8++)
                ldm_x4(kf[g8*2][0], kf[g8*2][1], kf[g8*2+1][0], kf[g8*2+1][1],
                       kb_ + (uint32_t)(g8 * 16) * AT_ROWB + kc * 32 + b_off);
#pragma unroll
            for (int j = 0; j < 8; j++) {
                mma_f16(s[j], aqh[kc], kf[j]);
                mma_f16(s[j], aql[kc], kf[j]);
            }
        }
        if (kt * 64 + 63 > qt * 128 + w * 16) {
            int qr = qt * 128 + w * 16 + g;
#pragma unroll
            for (int j = 0; j < 8; j++) {
                int key = kt * 64 + j * 8 + tg * 2;
                if (key     > qr)     s[j][0] = -1e30f;
                if (key + 1 > qr)     s[j][1] = -1e30f;
                if (key     > qr + 8) s[j][2] = -1e30f;
                if (key + 1 > qr + 8) s[j][3] = -1e30f;
            }
        }
    };

    float s[8][4], s_nxt[8][4];
    CP_WAIT1();
    __syncthreads();
    computeS(0, s);

    for (int t = 0; t < nkt; t++) {
        if (t + 1 < nkt) {
            CP_WAIT0();
            __syncthreads();
            if (t + 2 < nkt) { issue(t + 2, (t + 2) % 3); CP_COMMIT(); }
            computeS(t + 1, s_nxt);
        }

        // ---- softmax(t) ----
        float rm0 = s[0][0], rm1 = s[0][2];
#pragma unroll
        for (int j = 0; j < 8; j++) {
            rm0 = fmaxf(rm0, fmaxf(s[j][0], s[j][1]));
            rm1 = fmaxf(rm1, fmaxf(s[j][2], s[j][3]));
        }
        rm0 = fmaxf(rm0, __shfl_xor_sync(0xffffffffu, rm0, 1));
        rm0 = fmaxf(rm0, __shfl_xor_sync(0xffffffffu, rm0, 2));
        rm1 = fmaxf(rm1, __shfl_xor_sync(0xffffffffu, rm1, 1));
        rm1 = fmaxf(rm1, __shfl_xor_sync(0xffffffffu, rm1, 2));
        float mn0 = fmaxf(mi0, rm0), mn1 = fmaxf(mi1, rm1);
        float c0 = fast_exp(mi0 - mn0), c1 = fast_exp(mi1 - mn1);
        mi0 = mn0; mi1 = mn1;
        float sum0 = 0.f, sum1 = 0.f;
#pragma unroll
        for (int j = 0; j < 8; j++) {
            s[j][0] = fast_exp(s[j][0] - mn0); sum0 += s[j][0];
            s[j][1] = fast_exp(s[j][1] - mn0); sum0 += s[j][1];
            s[j][2] = fast_exp(s[j][2] - mn1); sum1 += s[j][2];
            s[j][3] = fast_exp(s[j][3] - mn1); sum1 += s[j][3];
        }
        sum0 += __shfl_xor_sync(0xffffffffu, sum0, 1);
        sum0 += __shfl_xor_sync(0xffffffffu, sum0, 2);
        sum1 += __shfl_xor_sync(0xffffffffu, sum1, 1);
        sum1 += __shfl_xor_sync(0xffffffffu, sum1, 2);
        li0 = li0 * c0 + sum0; li1 = li1 * c1 + sum1;
#pragma unroll
        for (int j = 0; j < 16; j++) {
            o[j][0] *= c0; o[j][1] *= c0; o[j][2] *= c1; o[j][3] *= c1;
        }

        // ---- pack P fp16 hi/lo (C layout == A layout) ----
        uint32_t ph[4][4], pl[4][4];
#pragma unroll
        for (int kc = 0; kc < 4; kc++) {
            split_pack2h(s[2*kc][0],   s[2*kc][1],   ph[kc][0], pl[kc][0]);
            split_pack2h(s[2*kc][2],   s[2*kc][3],   ph[kc][1], pl[kc][1]);
            split_pack2h(s[2*kc+1][0], s[2*kc+1][1], ph[kc][2], pl[kc][2]);
            split_pack2h(s[2*kc+1][2], s[2*kc+1][3], ph[kc][3], pl[kc][3]);
        }

        // ---- O += (Ph + Pl) @ V(t) ----
        const uint32_t vb_ = kvB + (uint32_t)(t % 3) * AT_STG + AT_KV_VB;
#pragma unroll
        for (int g8 = 0; g8 < 8; g8++) {
#pragma unroll
            for (int kc = 0; kc < 4; kc++) {
                uint32_t r0, r1, r2, r3;
                ldm_x4_t(r0, r1, r2, r3,
                         vb_ + (uint32_t)(kc * 16) * AT_ROWB + g8 * 32 + v_off);
                uint32_t b0[2] = {r0, r1}, b1[2] = {r2, r3};
                mma_f16(o[2*g8],   ph[kc], b0);
                mma_f16(o[2*g8+1], ph[kc], b1);
                mma_f16(o[2*g8],   pl[kc], b0);
                mma_f16(o[2*g8+1], pl[kc], b1);
            }
        }

        if (t + 1 < nkt) {
#pragma unroll
            for (int j = 0; j < 8; j++)
#pragma unroll
                for (int c = 0; c < 4; c++) s[j][c] = s_nxt[j][c];
        }
    }

    // ---- epilogue: O/l -> fp16 hi/lo for the out-proj ----
    float inv0 = 1.0f / li0, inv1 = 1.0f / li1;
    int row0 = qt * 128 + w * 16 + g;
    size_t base  = ((size_t)b * SEQ + row0) * D_MODEL + h * HEAD_DIM;
    size_t base8 = base + (size_t)8 * D_MODEL;
#pragma unroll
    for (int j = 0; j < 16; j++) {
        int col = j * 8 + tg * 2;
        uint32_t hi, lo;
        split_pack2h(o[j][0] * inv0, o[j][1] * inv0, hi, lo);
        *(uint32_t*)(g_attnh + base + col) = hi;
        *(uint32_t*)(g_attnl + base + col) = lo;
        split_pack2h(o[j][2] * inv1, o[j][3] * inv1, hi, lo);
        *(uint32_t*)(g_attnh + base8 + col) = hi;
        *(uint32_t*)(g_attnl + base8 + col) = lo;
    }
}

// ---------------- launch ---------------------------------------------------
extern "C" void kernel_launch(void* const* d_in, const int* in_sizes, int n_in,
                              void* d_out, int out_size) {
    const float* x    = (const float*)d_in[0];
    const float* Wqkv = (const float*)d_in[1];
    const float* Wout = (const float*)d_in[2];
    float* out = (float*)d_out;

    __half *xh, *xl, *wq, *wo, *ah, *al;
    cudaGetSymbolAddress((void**)&xh, g_xh);
    cudaGetSymbolAddress((void**)&xl, g_xl);
    cudaGetSymbolAddress((void**)&wq, g_wqkv);
    cudaGetSymbolAddress((void**)&wo, g_wout);
    cudaGetSymbolAddress((void**)&ah, g_attnh);
    cudaGetSymbolAddress((void**)&al, g_attnl);

    rope_table_kernel<<<(SEQ * 64 + 255) / 256, 256>>>();

    int n4x = M_TOTAL * D_MODEL / 4;
    split_h_kernel<<<(n4x + 255) / 256, 256>>>(x, xh, xl, n4x);
    int n4q = QKV_N * D_MODEL / 4;
    cvt_h_kernel<<<(n4q + 255) / 256, 256>>>(Wqkv, wq, n4q);
    int n4o = D_MODEL * D_MODEL / 4;
    cvt_h_kernel<<<(n4o + 255) / 256, 256>>>(Wout, wo, n4o);

    cudaFuncSetAttribute(mma_gemm<0>, cudaFuncAttributeMaxDynamicSharedMemorySize,
                         GEMM_SMEM_BYTES);
    cudaFuncSetAttribute(mma_gemm<1>, cudaFuncAttributeMaxDynamicSharedMemorySize,
                         GEMM_SMEM_BYTES);
    cudaFuncSetAttribute(attn_mma_kernel, cudaFuncAttributeMaxDynamicSharedMemorySize,
                         AT_SMEM);

    // QKV projection: fused clip+RoPE+scale+split-scatter
    mma_gemm<0><<<dim3(M_TOTAL / 128, QKV_N / 128), 256, GEMM_SMEM_BYTES>>>(
        xh, xl, wq, nullptr);

    // tensor-core flash attention (fp16 2-pass)
    attn_mma_kernel<<<dim3(SEQ / 128, BATCH * N_HEADS), 256, AT_SMEM>>>();

    // out projection
    mma_gemm<1><<<dim3(M_TOTAL / 128, D_MODEL / 128), 256, GEMM_SMEM_BYTES>>>(
        ah, al, wo, out);
}

// round 15
// speedup vs baseline: 7.1226x; 1.5554x over previous
#include <cuda_runtime.h>
#include <cuda_bf16.h>
#include <cuda_fp16.h>
#include <math.h>
#include <stdint.h>

#define N_HEADS   32
#define KV_HEADS  8
#define HEAD_DIM  128
#define D_MODEL   4096
#define BATCH     2
#define SEQ       2048
#define M_TOTAL   (BATCH * SEQ)
#define QKV_N     ((KV_HEADS * 2 + N_HEADS) * HEAD_DIM)
#define KDIM      4096

__device__ float g_cos[SEQ * 64];
__device__ float g_sin[SEQ * 64];

// GEMM operands: single fp16 A and B
__device__ __align__(256) __half g_x16[(size_t)M_TOTAL * D_MODEL];
__device__ __align__(256) __half g_wqkv[(size_t)QKV_N * D_MODEL];
__device__ __align__(256) __half g_wout[(size_t)D_MODEL * D_MODEL];
__device__ __align__(256) __half g_attn16[(size_t)M_TOTAL * D_MODEL];

// attention operands (fp16): q hi/lo (pre-scaled), k/v single
__device__ __align__(256) __half g_qh[(size_t)BATCH * N_HEADS * SEQ * HEAD_DIM];
__device__ __align__(256) __half g_ql[(size_t)BATCH * N_HEADS * SEQ * HEAD_DIM];
__device__ __align__(256) __half g_kf[(size_t)BATCH * KV_HEADS * SEQ * HEAD_DIM];
__device__ __align__(256) __half g_vf[(size_t)BATCH * KV_HEADS * SEQ * HEAD_DIM];

__device__ __forceinline__ uint32_t smem_u32(const void* p) {
    uint32_t a;
    asm("{ .reg .u64 t; cvta.to.shared.u64 t, %1; cvt.u32.u64 %0, t; }"
        : "=r"(a) : "l"(p));
    return a;
}
__device__ __forceinline__ void ldm_x4(uint32_t& r0, uint32_t& r1,
                                       uint32_t& r2, uint32_t& r3, uint32_t addr) {
    asm volatile("ldmatrix.sync.aligned.m8n8.x4.shared.b16 {%0,%1,%2,%3}, [%4];"
                 : "=r"(r0), "=r"(r1), "=r"(r2), "=r"(r3) : "r"(addr));
}
__device__ __forceinline__ void ldm_x4_t(uint32_t& r0, uint32_t& r1,
                                         uint32_t& r2, uint32_t& r3, uint32_t addr) {
    asm volatile("ldmatrix.sync.aligned.m8n8.x4.trans.shared.b16 {%0,%1,%2,%3}, [%4];"
                 : "=r"(r0), "=r"(r1), "=r"(r2), "=r"(r3) : "r"(addr));
}
__device__ __forceinline__ void mma_f16(float* c, const uint32_t* a,
                                        const uint32_t* b) {
    asm volatile(
        "mma.sync.aligned.m16n8k16.row.col.f32.f16.f16.f32 "
        "{%0,%1,%2,%3}, {%4,%5,%6,%7}, {%8,%9}, {%0,%1,%2,%3};"
        : "+f"(c[0]), "+f"(c[1]), "+f"(c[2]), "+f"(c[3])
        : "r"(a[0]), "r"(a[1]), "r"(a[2]), "r"(a[3]), "r"(b[0]), "r"(b[1]));
}
#define CP_ASYNC16(dst, src) \
    asm volatile("cp.async.cg.shared.global [%0], [%1], 16;" \
                 :: "r"(dst), "l"(src) : "memory")
#define CP_COMMIT() asm volatile("cp.async.commit_group;" ::: "memory")
#define CP_WAIT1()  asm volatile("cp.async.wait_group 1;" ::: "memory")
#define CP_WAIT0()  asm volatile("cp.async.wait_group 0;" ::: "memory")

__device__ __forceinline__ float fast_exp(float x) {
    x = fmaxf(x, -80.0f);
    float y = x * 1.4426950408889634f;
    float z = y + 12582912.0f;
    int   ni = __float_as_int(z) - 0x4B400000;
    float f = y - (z - 12582912.0f);
    float p = 1.3333558146e-3f;
    p = fmaf(p, f, 9.6181291077e-3f);
    p = fmaf(p, f, 5.5504108664e-2f);
    p = fmaf(p, f, 2.4022650696e-1f);
    p = fmaf(p, f, 6.9314718056e-1f);
    p = fmaf(p, f, 1.0f);
    return p * __int_as_float((ni + 127) << 23);
}
__device__ __forceinline__ void split_pack2h(float x, float y,
                                             uint32_t& hi, uint32_t& lo) {
    __half2 hh = __floats2half2_rn(x, y);
    float2 hf = __half22float2(hh);
    __half2 ll = __floats2half2_rn(x - hf.x, y - hf.y);
    hi = *(uint32_t*)&hh;
    lo = *(uint32_t*)&ll;
}

__global__ void rope_table_kernel() {
    int i = blockIdx.x * blockDim.x + threadIdx.x;
    if (i >= SEQ * 64) return;
    int l = i >> 6, d = i & 63;
    double inv = pow(500000.0, -((double)d) / 64.0);
    double ang = (double)l * inv;
    g_cos[i] = (float)cos(ang);
    g_sin[i] = (float)sin(ang);
}

__global__ __launch_bounds__(256) void cvt_h_kernel(
        const float* __restrict__ in, __half* __restrict__ outp, int n4) {
    int i = blockIdx.x * blockDim.x + threadIdx.x;
    if (i >= n4) return;
    float4 v = ((const float4*)in)[i];
    __half h[4] = {__float2half_rn(v.x), __float2half_rn(v.y),
                   __float2half_rn(v.z), __float2half_rn(v.w)};
    ((uint2*)outp)[i] = *(uint2*)h;
}

// ---------------- fp16 1-pass GEMM: 3 stages, 2 CTAs/SM --------------------
#define VBYTES (128 * 40 * 2)                  /* 10240 per operand  */
#define STAGEB (2 * VBYTES)                    /* 20480 per stage    */
#define GEMM_SMEM_BYTES 70656                  /* max(3*STAGEB, epi 69632)+pad */

template<int MODE>
__global__ __launch_bounds__(256, 2) void mma_gemm(
        const __half* __restrict__ Af, const __half* __restrict__ Bf,
        float* __restrict__ outp) {
    extern __shared__ char smraw[];
    char* smp = (char*)(((uintptr_t)smraw + 1023) & ~(uintptr_t)1023);
    const uint32_t sbase = smem_u32(smp);

    const int tid = threadIdx.x;
    const int lane = tid & 31;
    const int wid = tid >> 5;
    const int warp_m = wid & 1;
    const int warp_n = wid >> 1;
    const int bm = blockIdx.x, bn = blockIdx.y;

    const size_t aoff = (size_t)(bm * 128) * KDIM;
    const size_t boff = (size_t)(bn * 128) * KDIM;
    const __half* srcs[2] = {Af, Bf};
    const size_t roff[2] = {aoff, boff};

    float acc[4][4][4];
#pragma unroll
    for (int i = 0; i < 4; i++)
#pragma unroll
        for (int j = 0; j < 4; j++)
#pragma unroll
            for (int c = 0; c < 4; c++) acc[i][j][c] = 0.f;

    // 1024 16B-chunks per stage, 4 per thread
    auto issue = [&](int ic, int st) {
        uint32_t base = sbase + (uint32_t)st * STAGEB;
#pragma unroll
        for (int t = 0; t < 4; t++) {
            int idx = tid + t * 256;          // 0..1023
            int v = idx >> 9;                 // operand 0..1
            int r = (idx >> 2) & 127;
            int c = idx & 3;
            CP_ASYNC16(base + (uint32_t)(v * VBYTES + r * 80 + c * 16),
                       srcs[v] + roff[v] + (size_t)r * KDIM + ic * 32 + c * 8);
        }
    };

    const uint32_t a_lane_off =
        (uint32_t)((lane & 15) * 80 + ((lane >> 4) << 3) * 2);
    const uint32_t b_lane_off =
        (uint32_t)((((lane & 16) >> 1) + (lane & 7)) * 80 + (lane & 8) * 2);
    const int m0 = warp_m * 64;
    const int n0 = warp_n * 32;

    auto compute = [&](uint32_t sst) {
#pragma unroll
        for (int ks = 0; ks < 2; ks++) {
            const uint32_t k0b = ks * 32;
            uint32_t bf[4][2];
#pragma unroll
            for (int p = 0; p < 2; p++) {
                uint32_t r0, r1, r2, r3;
                ldm_x4(r0, r1, r2, r3,
                       sst + VBYTES + (uint32_t)((n0 + p * 16) * 80) + b_lane_off + k0b);
                bf[p * 2][0] = r0; bf[p * 2][1] = r1;
                bf[p * 2 + 1][0] = r2; bf[p * 2 + 1][1] = r3;
            }
#pragma unroll
            for (int mi = 0; mi < 4; mi++) {
                uint32_t af[4];
                ldm_x4(af[0], af[1], af[2], af[3],
                       sst + (uint32_t)((m0 + mi * 16) * 80) + a_lane_off + k0b);
#pragma unroll
                for (int ni = 0; ni < 4; ni++)
                    mma_f16(acc[mi][ni], af, bf[ni]);
            }
        }
    };

    issue(0, 0); CP_COMMIT();
    issue(1, 1); CP_COMMIT();

    for (int ic = 0; ic < 128; ic++) {
        if (ic <= 126) CP_WAIT1();
        else           CP_WAIT0();
        __syncthreads();
        if (ic + 2 < 128) { issue(ic + 2, (ic + 2) % 3); CP_COMMIT(); }
        compute(sbase + (uint32_t)(ic % 3) * STAGEB);
    }
    __syncthreads();

    // ---- epilogue ----
    float* ep = (float*)smp;                 // [128][136] = 69632 B
    const int g = lane >> 2, tg = lane & 3;
#pragma unroll
    for (int mi = 0; mi < 4; mi++)
#pragma unroll
        for (int ni = 0; ni < 4; ni++) {
            int row = m0 + mi * 16 + g;
            int col = n0 + ni * 8 + tg * 2;
            ep[row * 136 + col]       = acc[mi][ni][0];
            ep[row * 136 + col + 1]   = acc[mi][ni][1];
            ep[(row + 8) * 136 + col]     = acc[mi][ni][2];
            ep[(row + 8) * 136 + col + 1] = acc[mi][ni][3];
        }
    __syncthreads();

    for (int t = tid; t < 128 * 16; t += 256) {
        int row = t >> 4, j = t & 15;
        float4 v1 = *(const float4*)&ep[row * 136 + j * 4];
        float4 v2 = *(const float4*)&ep[row * 136 + 64 + j * 4];
        if (MODE == 0) {
            float* p1 = &v1.x; float* p2 = &v2.x;
#pragma unroll
            for (int e = 0; e < 4; e++) {
                p1[e] = fminf(fmaxf(p1[e], -8.0f), 8.0f);
                p2[e] = fminf(fmaxf(p2[e], -8.0f), 8.0f);
            }
            int m = bm * 128 + row;
            int bb = m >> 11, l = m & (SEQ - 1);
            if (bn < N_HEADS + KV_HEADS) {   // RoPE for q and k heads
#pragma unroll
                for (int e = 0; e < 4; e++) {
                    int d = j * 4 + e;
                    float c = g_cos[l * 64 + d];
                    float s = g_sin[l * 64 + d];
                    float x1 = p1[e], x2 = p2[e];
                    p1[e] = x1 * c - x2 * s;
                    p2[e] = x2 * c + x1 * s;
                }
            }
            if (bn < N_HEADS) {
                // q: scale + fp16 hi/lo split
                const float sc = 0.08838834764831845f;
                size_t off = ((size_t)(bb * N_HEADS + bn) * SEQ + l) * HEAD_DIM;
                __half hb[8], lb[8];
                float vv[8] = {p1[0]*sc, p1[1]*sc, p1[2]*sc, p1[3]*sc,
                               p2[0]*sc, p2[1]*sc, p2[2]*sc, p2[3]*sc};
#pragma unroll
                for (int e = 0; e < 8; e++) {
                    hb[e] = __float2half_rn(vv[e]);
                    lb[e] = __float2half_rn(vv[e] - __half2float(hb[e]));
                }
                *(uint2*)(g_qh + off + j * 4)      = *(uint2*)hb;
                *(uint2*)(g_ql + off + j * 4)      = *(uint2*)lb;
                *(uint2*)(g_qh + off + 64 + j * 4) = *(uint2*)(hb + 4);
                *(uint2*)(g_ql + off + 64 + j * 4) = *(uint2*)(lb + 4);
            } else {
                // k / v: single fp16
                int kv = bn - N_HEADS;
                __half* dst = (kv < KV_HEADS) ? g_kf : g_vf;
                int hh = (kv < KV_HEADS) ? kv : kv - KV_HEADS;
                size_t off = ((size_t)(bb * KV_HEADS + hh) * SEQ + l) * HEAD_DIM;
                __half hb[8] = {__float2half_rn(p1[0]), __float2half_rn(p1[1]),
                                __float2half_rn(p1[2]), __float2half_rn(p1[3]),
                                __float2half_rn(p2[0]), __float2half_rn(p2[1]),
                                __float2half_rn(p2[2]), __float2half_rn(p2[3])};
                *(uint2*)(dst + off + j * 4)      = *(uint2*)hb;
                *(uint2*)(dst + off + 64 + j * 4) = *(uint2*)(hb + 4);
            }
        } else {
            float* dst = outp + (size_t)(bm * 128 + row) * D_MODEL + bn * 128;
            *(float4*)(dst + j * 4) = v1;
            *(float4*)(dst + 64 + j * 4) = v2;
        }
    }
}

// ---------------- flash attention (fp16 2-pass, unchanged) -----------------
#define AT_ROWB   272
#define AT_KV_VB  (64 * AT_ROWB)               /* 17408 */
#define AT_STG    (2 * AT_KV_VB)               /* K + V = 34816 */
#define AT_SMEM   (3 * AT_STG)                 /* 104448 */

__global__ void __launch_bounds__(256, 1) attn_mma_kernel() {
    extern __shared__ char smp[];
    const uint32_t kvB = smem_u32(smp);

    const int tid = threadIdx.x, lane = tid & 31, w = tid >> 5;
    const int g = lane >> 2, tg = lane & 3;
    const int qt = 15 - (int)blockIdx.x;
    const int bh = blockIdx.y;
    const int b = bh >> 5, h = bh & 31, kh = h >> 2;

    const __half* Qhp = g_qh + ((size_t)(b * N_HEADS + h) * SEQ + qt * 128) * HEAD_DIM;
    const __half* Qlp = g_ql + ((size_t)(b * N_HEADS + h) * SEQ + qt * 128) * HEAD_DIM;
    const __half* Kfp = g_kf + (size_t)(b * KV_HEADS + kh) * SEQ * HEAD_DIM;
    const __half* Vfp = g_vf + (size_t)(b * KV_HEADS + kh) * SEQ * HEAD_DIM;

    const int nkt = 2 * qt + 2;

    auto issue = [&](int kt, int st) {
        uint32_t base = kvB + (uint32_t)st * AT_STG;
        const __half* srcs[2] = {Kfp, Vfp};
#pragma unroll
        for (int v = 0; v < 2; v++) {
            const __half* src = srcs[v] + (size_t)kt * 64 * HEAD_DIM;
#pragma unroll
            for (int t = 0; t < 4; t++) {
                int c = tid + t * 256;
                int row = c >> 4, cc = c & 15;
                CP_ASYNC16(base + (uint32_t)v * AT_KV_VB + row * AT_ROWB + cc * 16,
                           src + (size_t)row * HEAD_DIM + cc * 8);
            }
        }
    };

    issue(0, 0); CP_COMMIT();
    issue(1, 1); CP_COMMIT();

    // Q fragments -> registers (m16n8k16 A layout), loaded once
    uint32_t aqh[8][4], aql[8][4];
    {
        const int r0 = w * 16 + (lane >> 2);
        const int cb = (lane & 3) * 2;
        const __half* qa = Qhp + (size_t)r0 * HEAD_DIM;
        const __half* qb = qa + 8 * HEAD_DIM;
        const __half* la = Qlp + (size_t)r0 * HEAD_DIM;
        const __half* lb = la + 8 * HEAD_DIM;
#pragma unroll
        for (int kc = 0; kc < 8; kc++) {
            int c0 = kc * 16 + cb, c1 = c0 + 8;
            aqh[kc][0] = *(const uint32_t*)(qa + c0);
            aqh[kc][1] = *(const uint32_t*)(qb + c0);
            aqh[kc][2] = *(const uint32_t*)(qa + c1);
            aqh[kc][3] = *(const uint32_t*)(qb + c1);
            aql[kc][0] = *(const uint32_t*)(la + c0);
            aql[kc][1] = *(const uint32_t*)(lb + c0);
            aql[kc][2] = *(const uint32_t*)(la + c1);
            aql[kc][3] = *(const uint32_t*)(lb + c1);
        }
    }

    float o[16][4];
#pragma unroll
    for (int j = 0; j < 16; j++)
#pragma unroll
        for (int c = 0; c < 4; c++) o[j][c] = 0.f;
    float mi0 = -1e30f, mi1 = -1e30f, li0 = 0.f, li1 = 0.f;

    const uint32_t b_off = (uint32_t)((((lane & 16) >> 1) + (lane & 7)) * AT_ROWB + (lane & 8) * 2);
    const uint32_t v_off = (uint32_t)((lane & 15) * AT_ROWB + ((lane >> 4) << 4));

    auto computeS = [&](int kt, float s[8][4]) {
        const uint32_t kb_ = kvB + (uint32_t)(kt % 3) * AT_STG;
#pragma unroll
        for (int j = 0; j < 8; j++)
#pragma unroll
            for (int c = 0; c < 4; c++) s[j][c] = 0.f;
#pragma unroll
        for (int kc = 0; kc < 8; kc++) {
            uint32_t kf[8][2];
#pragma unroll
            for (int g8 = 0; g8 < 4; g8++)
                ldm_x4(kf[g8*2][0], kf[g8*2][1], kf[g8*2+1][0], kf[g8*2+1][1],
                       kb_ + (uint32_t)(g8 * 16) * AT_ROWB + kc * 32 + b_off);
#pragma unroll
            for (int j = 0; j < 8; j++) {
                mma_f16(s[j], aqh[kc], kf[j]);
                mma_f16(s[j], aql[kc], kf[j]);
            }
        }
        if (kt * 64 + 63 > qt * 128 + w * 16) {
            int qr = qt * 128 + w * 16 + g;
#pragma unroll
            for (int j = 0; j < 8; j++) {
                int key = kt * 64 + j * 8 + tg * 2;
                if (key     > qr)     s[j][0] = -1e30f;
                if (key + 1 > qr)     s[j][1] = -1e30f;
                if (key     > qr + 8) s[j][2] = -1e30f;
                if (key + 1 > qr + 8) s[j][3] = -1e30f;
            }
        }
    };

    float s[8][4], s_nxt[8][4];
    CP_WAIT1();
    __syncthreads();
    computeS(0, s);

    for (int t = 0; t < nkt; t++) {
        if (t + 1 < nkt) {
            CP_WAIT0();
            __syncthreads();
            if (t + 2 < nkt) { issue(t + 2, (t + 2) % 3); CP_COMMIT(); }
            computeS(t + 1, s_nxt);
        }

        // ---- softmax(t) ----
        float rm0 = s[0][0], rm1 = s[0][2];
#pragma unroll
        for (int j = 0; j < 8; j++) {
            rm0 = fmaxf(rm0, fmaxf(s[j][0], s[j][1]));
            rm1 = fmaxf(rm1, fmaxf(s[j][2], s[j][3]));
        }
        rm0 = fmaxf(rm0, __shfl_xor_sync(0xffffffffu, rm0, 1));
        rm0 = fmaxf(rm0, __shfl_xor_sync(0xffffffffu, rm0, 2));
        rm1 = fmaxf(rm1, __shfl_xor_sync(0xffffffffu, rm1, 1));
        rm1 = fmaxf(rm1, __shfl_xor_sync(0xffffffffu, rm1, 2));
        float mn0 = fmaxf(mi0, rm0), mn1 = fmaxf(mi1, rm1);
        float c0 = fast_exp(mi0 - mn0), c1 = fast_exp(mi1 - mn1);
        mi0 = mn0; mi1 = mn1;
        float sum0 = 0.f, sum1 = 0.f;
#pragma unroll
        for (int j = 0; j < 8; j++) {
            s[j][0] = fast_exp(s[j][0] - mn0); sum0 += s[j][0];
            s[j][1] = fast_exp(s[j][1] - mn0); sum0 += s[j][1];
            s[j][2] = fast_exp(s[j][2] - mn1); sum1 += s[j][2];
            s[j][3] = fast_exp(s[j][3] - mn1); sum1 += s[j][3];
        }
        sum0 += __shfl_xor_sync(0xffffffffu, sum0, 1);
        sum0 += __shfl_xor_sync(0xffffffffu, sum0, 2);
        sum1 += __shfl_xor_sync(0xffffffffu, sum1, 1);
        sum1 += __shfl_xor_sync(0xffffffffu, sum1, 2);
        li0 = li0 * c0 + sum0; li1 = li1 * c1 + sum1;
#pragma unroll
        for (int j = 0; j < 16; j++) {
            o[j][0] *= c0; o[j][1] *= c0; o[j][2] *= c1; o[j][3] *= c1;
        }

        // ---- pack P fp16 hi/lo ----
        uint32_t ph[4][4], pl[4][4];
#pragma unroll
        for (int kc = 0; kc < 4; kc++) {
            split_pack2h(s[2*kc][0],   s[2*kc][1],   ph[kc][0], pl[kc][0]);
            split_pack2h(s[2*kc][2],   s[2*kc][3],   ph[kc][1], pl[kc][1]);
            split_pack2h(s[2*kc+1][0], s[2*kc+1][1], ph[kc][2], pl[kc][2]);
            split_pack2h(s[2*kc+1][2], s[2*kc+1][3], ph[kc][3], pl[kc][3]);
        }

        // ---- O += (Ph + Pl) @ V(t) ----
        const uint32_t vb_ = kvB + (uint32_t)(t % 3) * AT_STG + AT_KV_VB;
#pragma unroll
        for (int g8 = 0; g8 < 8; g8++) {
#pragma unroll
            for (int kc = 0; kc < 4; kc++) {
                uint32_t r0, r1, r2, r3;
                ldm_x4_t(r0, r1, r2, r3,
                         vb_ + (uint32_t)(kc * 16) * AT_ROWB + g8 * 32 + v_off);
                uint32_t b0[2] = {r0, r1}, b1[2] = {r2, r3};
                mma_f16(o[2*g8],   ph[kc], b0);
                mma_f16(o[2*g8+1], ph[kc], b1);
                mma_f16(o[2*g8],   pl[kc], b0);
                mma_f16(o[2*g8+1], pl[kc], b1);
            }
        }

        if (t + 1 < nkt) {
#pragma unroll
            for (int j = 0; j < 8; j++)
#pragma unroll
                for (int c = 0; c < 4; c++) s[j][c] = s_nxt[j][c];
        }
    }

    // ---- epilogue: O/l -> single fp16 for the 1-pass out-proj ----
    float inv0 = 1.0f / li0, inv1 = 1.0f / li1;
    int row0 = qt * 128 + w * 16 + g;
    size_t base  = ((size_t)b * SEQ + row0) * D_MODEL + h * HEAD_DIM;
    size_t base8 = base + (size_t)8 * D_MODEL;
#pragma unroll
    for (int j = 0; j < 16; j++) {
        int col = j * 8 + tg * 2;
        __half2 h0 = __floats2half2_rn(o[j][0] * inv0, o[j][1] * inv0);
        __half2 h1 = __floats2half2_rn(o[j][2] * inv1, o[j][3] * inv1);
        *(uint32_t*)(g_attn16 + base + col)  = *(uint32_t*)&h0;
        *(uint32_t*)(g_attn16 + base8 + col) = *(uint32_t*)&h1;
    }
}

// ---------------- launch ---------------------------------------------------
extern "C" void kernel_launch(void* const* d_in, const int* in_sizes, int n_in,
                              void* d_out, int out_size) {
    const float* x    = (const float*)d_in[0];
    const float* Wqkv = (const float*)d_in[1];
    const float* Wout = (const float*)d_in[2];
    float* out = (float*)d_out;

    __half *x16, *wq, *wo, *a16;
    cudaGetSymbolAddress((void**)&x16, g_x16);
    cudaGetSymbolAddress((void**)&wq,  g_wqkv);
    cudaGetSymbolAddress((void**)&wo,  g_wout);
    cudaGetSymbolAddress((void**)&a16, g_attn16);

    rope_table_kernel<<<(SEQ * 64 + 255) / 256, 256>>>();

    int n4x = M_TOTAL * D_MODEL / 4;
    cvt_h_kernel<<<(n4x + 255) / 256, 256>>>(x, x16, n4x);
    int n4q = QKV_N * D_MODEL / 4;
    cvt_h_kernel<<<(n4q + 255) / 256, 256>>>(Wqkv, wq, n4q);
    int n4o = D_MODEL * D_MODEL / 4;
    cvt_h_kernel<<<(n4o + 255) / 256, 256>>>(Wout, wo, n4o);

    cudaFuncSetAttribute(mma_gemm<0>, cudaFuncAttributeMaxDynamicSharedMemorySize,
                         GEMM_SMEM_BYTES);
    cudaFuncSetAttribute(mma_gemm<1>, cudaFuncAttributeMaxDynamicSharedMemorySize,
                         GEMM_SMEM_BYTES);
    cudaFuncSetAttribute(attn_mma_kernel, cudaFuncAttributeMaxDynamicSharedMemorySize,
                         AT_SMEM);

    // QKV projection (1-pass fp16): fused clip+RoPE+scale+split-scatter
    mma_gemm<0><<<dim3(M_TOTAL / 128, QKV_N / 128), 256, GEMM_SMEM_BYTES>>>(
        x16, wq, nullptr);

    // tensor-core flash attention (fp16 2-pass)
    attn_mma_kernel<<<dim3(SEQ / 128, BATCH * N_HEADS), 256, AT_SMEM>>>();

    // out projection (1-pass fp16)
    mma_gemm<1><<<dim3(M_TOTAL / 128, D_MODEL / 128), 256, GEMM_SMEM_BYTES>>>(
        a16, wo, out);
}

// round 17
// speedup vs baseline: 7.8468x; 1.1017x over previous
#include <cuda_runtime.h>
#include <cuda_bf16.h>
#include <cuda_fp16.h>
#include <math.h>
#include <stdint.h>

#define N_HEADS   32
#define KV_HEADS  8
#define HEAD_DIM  128
#define D_MODEL   4096
#define BATCH     2
#define SEQ       2048
#define M_TOTAL   (BATCH * SEQ)
#define QKV_N     ((KV_HEADS * 2 + N_HEADS) * HEAD_DIM)
#define KDIM      4096

__device__ float g_cos[SEQ * 64];
__device__ float g_sin[SEQ * 64];

// GEMM operands: single fp16 A and B
__device__ __align__(256) __half g_x16[(size_t)M_TOTAL * D_MODEL];
__device__ __align__(256) __half g_wqkv[(size_t)QKV_N * D_MODEL];
__device__ __align__(256) __half g_wout[(size_t)D_MODEL * D_MODEL];
__device__ __align__(256) __half g_attn16[(size_t)M_TOTAL * D_MODEL];

// attention operands: all single fp16 (q pre-scaled by 1/sqrt(HEAD_DIM))
__device__ __align__(256) __half g_q16[(size_t)BATCH * N_HEADS * SEQ * HEAD_DIM];
__device__ __align__(256) __half g_kf[(size_t)BATCH * KV_HEADS * SEQ * HEAD_DIM];
__device__ __align__(256) __half g_vf[(size_t)BATCH * KV_HEADS * SEQ * HEAD_DIM];

__device__ __forceinline__ uint32_t smem_u32(const void* p) {
    uint32_t a;
    asm("{ .reg .u64 t; cvta.to.shared.u64 t, %1; cvt.u32.u64 %0, t; }"
        : "=r"(a) : "l"(p));
    return a;
}
__device__ __forceinline__ void ldm_x4(uint32_t& r0, uint32_t& r1,
                                       uint32_t& r2, uint32_t& r3, uint32_t addr) {
    asm volatile("ldmatrix.sync.aligned.m8n8.x4.shared.b16 {%0,%1,%2,%3}, [%4];"
                 : "=r"(r0), "=r"(r1), "=r"(r2), "=r"(r3) : "r"(addr));
}
__device__ __forceinline__ void ldm_x4_t(uint32_t& r0, uint32_t& r1,
                                         uint32_t& r2, uint32_t& r3, uint32_t addr) {
    asm volatile("ldmatrix.sync.aligned.m8n8.x4.trans.shared.b16 {%0,%1,%2,%3}, [%4];"
                 : "=r"(r0), "=r"(r1), "=r"(r2), "=r"(r3) : "r"(addr));
}
__device__ __forceinline__ void mma_f16(float* c, const uint32_t* a,
                                        const uint32_t* b) {
    asm volatile(
        "mma.sync.aligned.m16n8k16.row.col.f32.f16.f16.f32 "
        "{%0,%1,%2,%3}, {%4,%5,%6,%7}, {%8,%9}, {%0,%1,%2,%3};"
        : "+f"(c[0]), "+f"(c[1]), "+f"(c[2]), "+f"(c[3])
        : "r"(a[0]), "r"(a[1]), "r"(a[2]), "r"(a[3]), "r"(b[0]), "r"(b[1]));
}
#define CP_ASYNC16(dst, src) \
    asm volatile("cp.async.cg.shared.global [%0], [%1], 16;" \
                 :: "r"(dst), "l"(src) : "memory")
#define CP_COMMIT() asm volatile("cp.async.commit_group;" ::: "memory")
#define CP_WAIT1()  asm volatile("cp.async.wait_group 1;" ::: "memory")
#define CP_WAIT0()  asm volatile("cp.async.wait_group 0;" ::: "memory")

__device__ __forceinline__ float fast_exp(float x) {
    x = fmaxf(x, -80.0f);
    float y = x * 1.4426950408889634f;
    float z = y + 12582912.0f;
    int   ni = __float_as_int(z) - 0x4B400000;
    float f = y - (z - 12582912.0f);
    float p = 1.3333558146e-3f;
    p = fmaf(p, f, 9.6181291077e-3f);
    p = fmaf(p, f, 5.5504108664e-2f);
    p = fmaf(p, f, 2.4022650696e-1f);
    p = fmaf(p, f, 6.9314718056e-1f);
    p = fmaf(p, f, 1.0f);
    return p * __int_as_float((ni + 127) << 23);
}

__global__ void rope_table_kernel() {
    int i = blockIdx.x * blockDim.x + threadIdx.x;
    if (i >= SEQ * 64) return;
    int l = i >> 6, d = i & 63;
    double inv = pow(500000.0, -((double)d) / 64.0);
    double ang = (double)l * inv;
    g_cos[i] = (float)cos(ang);
    g_sin[i] = (float)sin(ang);
}

__global__ __launch_bounds__(256) void cvt_h_kernel(
        const float* __restrict__ in, __half* __restrict__ outp, int n4) {
    int i = blockIdx.x * blockDim.x + threadIdx.x;
    if (i >= n4) return;
    float4 v = ((const float4*)in)[i];
    __half h[4] = {__float2half_rn(v.x), __float2half_rn(v.y),
                   __float2half_rn(v.z), __float2half_rn(v.w)};
    ((uint2*)outp)[i] = *(uint2*)h;
}

// ---------------- fp16 1-pass GEMM: 3 stages, 2 CTAs/SM --------------------
#define VBYTES (128 * 40 * 2)                  /* 10240 per operand  */
#define STAGEB (2 * VBYTES)                    /* 20480 per stage    */
#define GEMM_SMEM_BYTES 70656                  /* max(3*STAGEB, epi 69632)+pad */

template<int MODE>
__global__ __launch_bounds__(256, 2) void mma_gemm(
        const __half* __restrict__ Af, const __half* __restrict__ Bf,
        float* __restrict__ outp) {
    extern __shared__ char smraw[];
    char* smp = (char*)(((uintptr_t)smraw + 1023) & ~(uintptr_t)1023);
    const uint32_t sbase = smem_u32(smp);

    const int tid = threadIdx.x;
    const int lane = tid & 31;
    const int wid = tid >> 5;
    const int warp_m = wid & 1;
    const int warp_n = wid >> 1;
    const int bm = blockIdx.x, bn = blockIdx.y;

    const size_t aoff = (size_t)(bm * 128) * KDIM;
    const size_t boff = (size_t)(bn * 128) * KDIM;
    const __half* srcs[2] = {Af, Bf};
    const size_t roff[2] = {aoff, boff};

    float acc[4][4][4];
#pragma unroll
    for (int i = 0; i < 4; i++)
#pragma unroll
        for (int j = 0; j < 4; j++)
#pragma unroll
            for (int c = 0; c < 4; c++) acc[i][j][c] = 0.f;

    auto issue = [&](int ic, int st) {
        uint32_t base = sbase + (uint32_t)st * STAGEB;
#pragma unroll
        for (int t = 0; t < 4; t++) {
            int idx = tid + t * 256;
            int v = idx >> 9;
            int r = (idx >> 2) & 127;
            int c = idx & 3;
            CP_ASYNC16(base + (uint32_t)(v * VBYTES + r * 80 + c * 16),
                       srcs[v] + roff[v] + (size_t)r * KDIM + ic * 32 + c * 8);
        }
    };

    const uint32_t a_lane_off =
        (uint32_t)((lane & 15) * 80 + ((lane >> 4) << 3) * 2);
    const uint32_t b_lane_off =
        (uint32_t)((((lane & 16) >> 1) + (lane & 7)) * 80 + (lane & 8) * 2);
    const int m0 = warp_m * 64;
    const int n0 = warp_n * 32;

    auto compute = [&](uint32_t sst) {
#pragma unroll
        for (int ks = 0; ks < 2; ks++) {
            const uint32_t k0b = ks * 32;
            uint32_t bf[4][2];
#pragma unroll
            for (int p = 0; p < 2; p++) {
                uint32_t r0, r1, r2, r3;
                ldm_x4(r0, r1, r2, r3,
                       sst + VBYTES + (uint32_t)((n0 + p * 16) * 80) + b_lane_off + k0b);
                bf[p * 2][0] = r0; bf[p * 2][1] = r1;
                bf[p * 2 + 1][0] = r2; bf[p * 2 + 1][1] = r3;
            }
#pragma unroll
            for (int mi = 0; mi < 4; mi++) {
                uint32_t af[4];
                ldm_x4(af[0], af[1], af[2], af[3],
                       sst + (uint32_t)((m0 + mi * 16) * 80) + a_lane_off + k0b);
#pragma unroll
                for (int ni = 0; ni < 4; ni++)
                    mma_f16(acc[mi][ni], af, bf[ni]);
            }
        }
    };

    issue(0, 0); CP_COMMIT();
    issue(1, 1); CP_COMMIT();

    for (int ic = 0; ic < 128; ic++) {
        if (ic <= 126) CP_WAIT1();
        else           CP_WAIT0();
        __syncthreads();
        if (ic + 2 < 128) { issue(ic + 2, (ic + 2) % 3); CP_COMMIT(); }
        compute(sbase + (uint32_t)(ic % 3) * STAGEB);
    }
    __syncthreads();

    // ---- epilogue ----
    float* ep = (float*)smp;                 // [128][136]
    const int g = lane >> 2, tg = lane & 3;
#pragma unroll
    for (int mi = 0; mi < 4; mi++)
#pragma unroll
        for (int ni = 0; ni < 4; ni++) {
            int row = m0 + mi * 16 + g;
            int col = n0 + ni * 8 + tg * 2;
            ep[row * 136 + col]       = acc[mi][ni][0];
            ep[row * 136 + col + 1]   = acc[mi][ni][1];
            ep[(row + 8) * 136 + col]     = acc[mi][ni][2];
            ep[(row + 8) * 136 + col + 1] = acc[mi][ni][3];
        }
    __syncthreads();

    for (int t = tid; t < 128 * 16; t += 256) {
        int row = t >> 4, j = t & 15;
        float4 v1 = *(const float4*)&ep[row * 136 + j * 4];
        float4 v2 = *(const float4*)&ep[row * 136 + 64 + j * 4];
        if (MODE == 0) {
            float* p1 = &v1.x; float* p2 = &v2.x;
#pragma unroll
            for (int e = 0; e < 4; e++) {
                p1[e] = fminf(fmaxf(p1[e], -8.0f), 8.0f);
                p2[e] = fminf(fmaxf(p2[e], -8.0f), 8.0f);
            }
            int m = bm * 128 + row;
            int bb = m >> 11, l = m & (SEQ - 1);
            if (bn < N_HEADS + KV_HEADS) {   // RoPE for q and k heads
#pragma unroll
                for (int e = 0; e < 4; e++) {
                    int d = j * 4 + e;
                    float c = g_cos[l * 64 + d];
                    float s = g_sin[l * 64 + d];
                    float x1 = p1[e], x2 = p2[e];
                    p1[e] = x1 * c - x2 * s;
                    p2[e] = x2 * c + x1 * s;
                }
            }
            float sc = 1.0f;
            __half* dst;
            size_t off;
            if (bn < N_HEADS) {
                sc = 0.08838834764831845f;   // fold 1/sqrt(128) into q
                dst = g_q16;
                off = ((size_t)(bb * N_HEADS + bn) * SEQ + l) * HEAD_DIM;
            } else {
                int kv = bn - N_HEADS;
                dst = (kv < KV_HEADS) ? g_kf : g_vf;
                int hh = (kv < KV_HEADS) ? kv : kv - KV_HEADS;
                off = ((size_t)(bb * KV_HEADS + hh) * SEQ + l) * HEAD_DIM;
            }
            __half hb[8] = {__float2half_rn(p1[0]*sc), __float2half_rn(p1[1]*sc),
                            __float2half_rn(p1[2]*sc), __float2half_rn(p1[3]*sc),
                            __float2half_rn(p2[0]*sc), __float2half_rn(p2[1]*sc),
                            __float2half_rn(p2[2]*sc), __float2half_rn(p2[3]*sc)};
            *(uint2*)(dst + off + j * 4)      = *(uint2*)hb;
            *(uint2*)(dst + off + 64 + j * 4) = *(uint2*)(hb + 4);
        } else {
            float* dst = outp + (size_t)(bm * 128 + row) * D_MODEL + bn * 128;
            *(float4*)(dst + j * 4) = v1;
            *(float4*)(dst + 64 + j * 4) = v2;
        }
    }
}

// ---------------- flash attention (fp16 1-pass S and PV) -------------------
#define AT_ROWB   272
#define AT_KV_VB  (64 * AT_ROWB)               /* 17408 */
#define AT_STG    (2 * AT_KV_VB)               /* K + V = 34816 */
#define AT_SMEM   (3 * AT_STG)                 /* 104448 */

__global__ void __launch_bounds__(256, 1) attn_mma_kernel() {
    extern __shared__ char smp[];
    const uint32_t kvB = smem_u32(smp);

    const int tid = threadIdx.x, lane = tid & 31, w = tid >> 5;
    const int g = lane >> 2, tg = lane & 3;
    const int qt = 15 - (int)blockIdx.x;
    const int bh = blockIdx.y;
    const int b = bh >> 5, h = bh & 31, kh = h >> 2;

    const __half* Qp  = g_q16 + ((size_t)(b * N_HEADS + h) * SEQ + qt * 128) * HEAD_DIM;
    const __half* Kfp = g_kf + (size_t)(b * KV_HEADS + kh) * SEQ * HEAD_DIM;
    const __half* Vfp = g_vf + (size_t)(b * KV_HEADS + kh) * SEQ * HEAD_DIM;

    const int nkt = 2 * qt + 2;

    auto issue = [&](int kt, int st) {
        uint32_t base = kvB + (uint32_t)st * AT_STG;
        const __half* srcs[2] = {Kfp, Vfp};
#pragma unroll
        for (int v = 0; v < 2; v++) {
            const __half* src = srcs[v] + (size_t)kt * 64 * HEAD_DIM;
#pragma unroll
            for (int t = 0; t < 4; t++) {
                int c = tid + t * 256;
                int row = c >> 4, cc = c & 15;
                CP_ASYNC16(base + (uint32_t)v * AT_KV_VB + row * AT_ROWB + cc * 16,
                           src + (size_t)row * HEAD_DIM + cc * 8);
            }
        }
    };

    issue(0, 0); CP_COMMIT();
    issue(1, 1); CP_COMMIT();

    // Q fragments -> registers (m16n8k16 A layout), loaded once, single fp16
    uint32_t aq[8][4];
    {
        const int r0 = w * 16 + (lane >> 2);
        const int cb = (lane & 3) * 2;
        const __half* qa = Qp + (size_t)r0 * HEAD_DIM;
        const __half* qb = qa + 8 * HEAD_DIM;
#pragma unroll
        for (int kc = 0; kc < 8; kc++) {
            int c0 = kc * 16 + cb, c1 = c0 + 8;
            aq[kc][0] = *(const uint32_t*)(qa + c0);
            aq[kc][1] = *(const uint32_t*)(qb + c0);
            aq[kc][2] = *(const uint32_t*)(qa + c1);
            aq[kc][3] = *(const uint32_t*)(qb + c1);
        }
    }

    float o[16][4];
#pragma unroll
    for (int j = 0; j < 16; j++)
#pragma unroll
        for (int c = 0; c < 4; c++) o[j][c] = 0.f;
    float mi0 = -1e30f, mi1 = -1e30f, li0 = 0.f, li1 = 0.f;

    const uint32_t b_off = (uint32_t)((((lane & 16) >> 1) + (lane & 7)) * AT_ROWB + (lane & 8) * 2);
    const uint32_t v_off = (uint32_t)((lane & 15) * AT_ROWB + ((lane >> 4) << 4));

    auto computeS = [&](int kt, float s[8][4]) {
        const uint32_t kb_ = kvB + (uint32_t)(kt % 3) * AT_STG;
#pragma unroll
        for (int j = 0; j < 8; j++)
#pragma unroll
            for (int c = 0; c < 4; c++) s[j][c] = 0.f;
#pragma unroll
        for (int kc = 0; kc < 8; kc++) {
            uint32_t kf[8][2];
#pragma unroll
            for (int g8 = 0; g8 < 4; g8++)
                ldm_x4(kf[g8*2][0], kf[g8*2][1], kf[g8*2+1][0], kf[g8*2+1][1],
                       kb_ + (uint32_t)(g8 * 16) * AT_ROWB + kc * 32 + b_off);
#pragma unroll
            for (int j = 0; j < 8; j++)
                mma_f16(s[j], aq[kc], kf[j]);
        }
        if (kt * 64 + 63 > qt * 128 + w * 16) {
            int qr = qt * 128 + w * 16 + g;
#pragma unroll
            for (int j = 0; j < 8; j++) {
                int key = kt * 64 + j * 8 + tg * 2;
                if (key     > qr)     s[j][0] = -1e30f;
                if (key + 1 > qr)     s[j][1] = -1e30f;
                if (key     > qr + 8) s[j][2] = -1e30f;
                if (key + 1 > qr + 8) s[j][3] = -1e30f;
            }
        }
    };

    float s[8][4], s_nxt[8][4];
    CP_WAIT1();
    __syncthreads();
    computeS(0, s);

    for (int t = 0; t < nkt; t++) {
        if (t + 1 < nkt) {
            CP_WAIT0();
            __syncthreads();
            if (t + 2 < nkt) { issue(t + 2, (t + 2) % 3); CP_COMMIT(); }
            computeS(t + 1, s_nxt);
        }

        // ---- softmax(t) ----
        float rm0 = s[0][0], rm1 = s[0][2];
#pragma unroll
        for (int j = 0; j < 8; j++) {
            rm0 = fmaxf(rm0, fmaxf(s[j][0], s[j][1]));
            rm1 = fmaxf(rm1, fmaxf(s[j][2], s[j][3]));
        }
        rm0 = fmaxf(rm0, __shfl_xor_sync(0xffffffffu, rm0, 1));
        rm0 = fmaxf(rm0, __shfl_xor_sync(0xffffffffu, rm0, 2));
        rm1 = fmaxf(rm1, __shfl_xor_sync(0xffffffffu, rm1, 1));
        rm1 = fmaxf(rm1, __shfl_xor_sync(0xffffffffu, rm1, 2));
        float mn0 = fmaxf(mi0, rm0), mn1 = fmaxf(mi1, rm1);
        float c0 = fast_exp(mi0 - mn0), c1 = fast_exp(mi1 - mn1);
        mi0 = mn0; mi1 = mn1;
        float sum0 = 0.f, sum1 = 0.f;
#pragma unroll
        for (int j = 0; j < 8; j++) {
            s[j][0] = fast_exp(s[j][0] - mn0); sum0 += s[j][0];
            s[j][1] = fast_exp(s[j][1] - mn0); sum0 += s[j][1];
            s[j][2] = fast_exp(s[j][2] - mn1); sum1 += s[j][2];
            s[j][3] = fast_exp(s[j][3] - mn1); sum1 += s[j][3];
        }
        sum0 += __shfl_xor_sync(0xffffffffu, sum0, 1);
        sum0 += __shfl_xor_sync(0xffffffffu, sum0, 2);
        sum1 += __shfl_xor_sync(0xffffffffu, sum1, 1);
        sum1 += __shfl_xor_sync(0xffffffffu, sum1, 2);
        li0 = li0 * c0 + sum0; li1 = li1 * c1 + sum1;
#pragma unroll
        for (int j = 0; j < 16; j++) {
            o[j][0] *= c0; o[j][1] *= c0; o[j][2] *= c1; o[j][3] *= c1;
        }

        // ---- pack P single fp16 (C layout == A layout) ----
        uint32_t ph[4][4];
#pragma unroll
        for (int kc = 0; kc < 4; kc++) {
            __half2 h0 = __floats2half2_rn(s[2*kc][0],   s[2*kc][1]);
            __half2 h1 = __floats2half2_rn(s[2*kc][2],   s[2*kc][3]);
            __half2 h2 = __floats2half2_rn(s[2*kc+1][0], s[2*kc+1][1]);
            __half2 h3 = __floats2half2_rn(s[2*kc+1][2], s[2*kc+1][3]);
            ph[kc][0] = *(uint32_t*)&h0;
            ph[kc][1] = *(uint32_t*)&h1;
            ph[kc][2] = *(uint32_t*)&h2;
            ph[kc][3] = *(uint32_t*)&h3;
        }

        // ---- O += P @ V(t) ----
        const uint32_t vb_ = kvB + (uint32_t)(t % 3) * AT_STG + AT_KV_VB;
#pragma unroll
        for (int g8 = 0; g8 < 8; g8++) {
#pragma unroll
            for (int kc = 0; kc < 4; kc++) {
                uint32_t r0, r1, r2, r3;
                ldm_x4_t(r0, r1, r2, r3,
                         vb_ + (uint32_t)(kc * 16) * AT_ROWB + g8 * 32 + v_off);
                uint32_t b0[2] = {r0, r1}, b1[2] = {r2, r3};
                mma_f16(o[2*g8],   ph[kc], b0);
                mma_f16(o[2*g8+1], ph[kc], b1);
            }
        }

        if (t + 1 < nkt) {
#pragma unroll
            for (int j = 0; j < 8; j++)
#pragma unroll
                for (int c = 0; c < 4; c++) s[j][c] = s_nxt[j][c];
        }
    }

    // ---- epilogue: O/l -> single fp16 for the 1-pass out-proj ----
    float inv0 = 1.0f / li0, inv1 = 1.0f / li1;
    int row0 = qt * 128 + w * 16 + g;
    size_t base  = ((size_t)b * SEQ + row0) * D_MODEL + h * HEAD_DIM;
    size_t base8 = base + (size_t)8 * D_MODEL;
#pragma unroll
    for (int j = 0; j < 16; j++) {
        int col = j * 8 + tg * 2;
        __half2 h0 = __floats2half2_rn(o[j][0] * inv0, o[j][1] * inv0);
        __half2 h1 = __floats2half2_rn(o[j][2] * inv1, o[j][3] * inv1);
        *(uint32_t*)(g_attn16 + base + col)  = *(uint32_t*)&h0;
        *(uint32_t*)(g_attn16 + base8 + col) = *(uint32_t*)&h1;
    }
}

// ---------------- launch ---------------------------------------------------
extern "C" void kernel_launch(void* const* d_in, const int* in_sizes, int n_in,
                              void* d_out, int out_size) {
    const float* x    = (const float*)d_in[0];
    const float* Wqkv = (const float*)d_in[1];
    const float* Wout = (const float*)d_in[2];
    float* out = (float*)d_out;

    __half *x16, *wq, *wo, *a16;
    cudaGetSymbolAddress((void**)&x16, g_x16);
    cudaGetSymbolAddress((void**)&wq,  g_wqkv);
    cudaGetSymbolAddress((void**)&wo,  g_wout);
    cudaGetSymbolAddress((void**)&a16, g_attn16);

    rope_table_kernel<<<(SEQ * 64 + 255) / 256, 256>>>();

    int n4x = M_TOTAL * D_MODEL / 4;
    cvt_h_kernel<<<(n4x + 255) / 256, 256>>>(x, x16, n4x);
    int n4q = QKV_N * D_MODEL / 4;
    cvt_h_kernel<<<(n4q + 255) / 256, 256>>>(Wqkv, wq, n4q);
    int n4o = D_MODEL * D_MODEL / 4;
    cvt_h_kernel<<<(n4o + 255) / 256, 256>>>(Wout, wo, n4o);

    cudaFuncSetAttribute(mma_gemm<0>, cudaFuncAttributeMaxDynamicSharedMemorySize,
                         GEMM_SMEM_BYTES);
    cudaFuncSetAttribute(mma_gemm<1>, cudaFuncAttributeMaxDynamicSharedMemorySize,
                         GEMM_SMEM_BYTES);
    cudaFuncSetAttribute(attn_mma_kernel, cudaFuncAttributeMaxDynamicSharedMemorySize,
                         AT_SMEM);

    // QKV projection (1-pass fp16): fused clip+RoPE+scale+scatter
    mma_gemm<0><<<dim3(M_TOTAL / 128, QKV_N / 128), 256, GEMM_SMEM_BYTES>>>(
        x16, wq, nullptr);

    // tensor-core flash attention (fp16 1-pass S and PV)
    attn_mma_kernel<<<dim3(SEQ / 128, BATCH * N_HEADS), 256, AT_SMEM>>>();

    // out projection (1-pass fp16)
    mma_gemm<1><<<dim3(M_TOTAL / 128, D_MODEL / 128), 256, GEMM_SMEM_BYTES>>>(
        a16, wo, out);
}